// round 9
// baseline (speedup 1.0000x reference)
#include <cuda_runtime.h>
#include <math.h>
#include <stdint.h>

// ---------------- problem constants ----------------
constexpr int BB   = 8;
constexpr int CC   = 512;
constexpr int SS   = 1024;
constexpr int NHH  = 8;
constexpr int DHH  = 64;
constexpr int NCC  = 77;
constexpr int DCC  = 768;
constexpr int MM   = BB * SS;  // 8192
constexpr int MKV  = BB * NCC; // 616

// ---------------- scratch ----------------
__device__ __align__(256) float g_t   [ (long)MM * CC ];
__device__ __align__(256) float g_tn  [ (long)MM * CC ];
__device__ __align__(256) float g_q   [ (long)MM * CC ];
__device__ __align__(256) float g_k   [ (long)MM * CC ];
__device__ __align__(256) float g_v   [ (long)MM * CC ];
__device__ __align__(256) float g_ao  [ (long)MM * CC ];
__device__ __align__(256) float g_gg  [ (long)MM * 2048 ];   // GEGLU output
__device__ __align__(256) float g_stats [ 2 * BB * 32 ];     // groupnorm stats
__device__ __align__(256) float g_lnst  [ 2 * MM ];          // layernorm stats

// ---------------- reductions ----------------
__inline__ __device__ float warpSum(float v){
    #pragma unroll
    for (int o = 16; o > 0; o >>= 1) v += __shfl_xor_sync(0xffffffffu, v, o);
    return v;
}

// ---------------- cp.async helpers ----------------
__device__ __forceinline__ uint32_t smem_u32(const void* p){
    return (uint32_t)__cvta_generic_to_shared(p);
}
__device__ __forceinline__ void cp16(void* dst, const void* src, int bytes){
    asm volatile("cp.async.cg.shared.global [%0], [%1], 16, %2;\n"
                 :: "r"(smem_u32(dst)), "l"(src), "r"(bytes));
}
__device__ __forceinline__ void cp_commit(){ asm volatile("cp.async.commit_group;\n"); }
template<int N> __device__ __forceinline__ void cp_wait(){
    asm volatile("cp.async.wait_group %0;\n" :: "n"(N));
}

// ---------------- mma tf32 ----------------
__inline__ __device__ void mma_tf32(float* c, const uint32_t* a, const uint32_t* b){
    asm volatile(
        "mma.sync.aligned.m16n8k8.row.col.f32.tf32.tf32.f32 "
        "{%0,%1,%2,%3}, {%4,%5,%6,%7}, {%8,%9}, {%0,%1,%2,%3};"
        : "+f"(c[0]), "+f"(c[1]), "+f"(c[2]), "+f"(c[3])
        : "r"(a[0]), "r"(a[1]), "r"(a[2]), "r"(a[3]), "r"(b[0]), "r"(b[1]));
}
__inline__ __device__ void mma_tf32f(float* c, const float* a, float b0, float b1){
    uint32_t au[4] = {__float_as_uint(a[0]), __float_as_uint(a[1]),
                      __float_as_uint(a[2]), __float_as_uint(a[3])};
    uint32_t bu[2] = {__float_as_uint(b0), __float_as_uint(b1)};
    mma_tf32(c, au, bu);
}

__inline__ __device__ float gelu_exact(float x){
    return 0.5f * x * (1.f + erff(x * 0.70710678118654752f));
}

// ---------------- groupnorm stats ----------------
__global__ void gn_stats_k(const float* __restrict__ x, float* __restrict__ stats){
    long base = (long)blockIdx.x * 16384;
    float s = 0.f, q = 0.f;
    for (int i = threadIdx.x; i < 16384; i += blockDim.x){
        float v = x[base + i];
        s += v; q += v * v;
    }
    __shared__ float shs[8], shq[8];
    s = warpSum(s); q = warpSum(q);
    int w = threadIdx.x >> 5, l = threadIdx.x & 31;
    if (l == 0){ shs[w] = s; shq[w] = q; }
    __syncthreads();
    if (threadIdx.x < 32){
        s = (l < 8) ? shs[l] : 0.f;
        q = (l < 8) ? shq[l] : 0.f;
        s = warpSum(s); q = warpSum(q);
        if (l == 0){
            float mean = s * (1.f / 16384.f);
            float var  = q * (1.f / 16384.f) - mean * mean;
            stats[2 * blockIdx.x]     = mean;
            stats[2 * blockIdx.x + 1] = rsqrtf(var + 1e-6f);
        }
    }
}

// ---------------- layernorm stats (per-row mean/rstd), warp per row ----------------
__global__ void ln_stats_k(const float* __restrict__ in, float* __restrict__ st){
    int row = blockIdx.x * 8 + (threadIdx.x >> 5);
    int lane = threadIdx.x & 31;
    const float4* x4 = (const float4*)(in + (long)row * CC);
    float s = 0.f, q = 0.f;
    #pragma unroll
    for (int t = 0; t < 4; t++){
        float4 v = x4[lane + t * 32];
        s += v.x + v.y + v.z + v.w;
        q += v.x*v.x + v.y*v.y + v.z*v.z + v.w*v.w;
    }
    s = warpSum(s); q = warpSum(q);
    if (lane == 0){
        float mean = s * (1.f / 512.f);
        st[2 * row]     = mean;
        st[2 * row + 1] = rsqrtf(q * (1.f / 512.f) - mean * mean + 1e-5f);
    }
}

// ---------------- groupnorm apply + transpose ----------------
__global__ void gn_apply_t_k(const float* __restrict__ x, const float* __restrict__ stats,
                             const float* __restrict__ gs, const float* __restrict__ gb,
                             float* __restrict__ out){
    __shared__ float tile[32][33];
    int b = blockIdx.z, c0 = blockIdx.y * 32, p0 = blockIdx.x * 32;
    int tx = threadIdx.x, ty = threadIdx.y;
    #pragma unroll
    for (int r = 0; r < 4; r++){
        int c = c0 + ty + r * 8;
        float v = x[((long)b * CC + c) * SS + p0 + tx];
        int grp = b * 32 + (c >> 4);
        v = (v - stats[2 * grp]) * stats[2 * grp + 1] * gs[c] + gb[c];
        tile[ty + r * 8][tx] = v;
    }
    __syncthreads();
    #pragma unroll
    for (int r = 0; r < 4; r++){
        int p = p0 + ty + r * 8;
        out[((long)b * SS + p) * CC + c0 + tx] = tile[tx][ty + r * 8];
    }
}

// ---------------- final transpose + x_in residual ----------------
__global__ void out_add_t_k(const float* __restrict__ z, const float* __restrict__ x,
                            float* __restrict__ out){
    __shared__ float tile[32][33];
    int b = blockIdx.z, c0 = blockIdx.y * 32, p0 = blockIdx.x * 32;
    int tx = threadIdx.x, ty = threadIdx.y;
    #pragma unroll
    for (int r = 0; r < 4; r++){
        int p = p0 + ty + r * 8;
        tile[ty + r * 8][tx] = z[((long)b * SS + p) * CC + c0 + tx];
    }
    __syncthreads();
    #pragma unroll
    for (int r = 0; r < 4; r++){
        int c = c0 + ty + r * 8;
        long o = ((long)b * CC + c) * SS + p0 + tx;
        out[o] = tile[tx][ty + r * 8] + x[o];
    }
}

// =====================================================================
// Flash attention (tf32 mma.sync, online softmax).
// PREUSE: stage P in the (consumed-after-t0) Q smem slice — valid only
// when TKV <= LQ (self: 64 <= 68). Cross keeps a dedicated P region.
// __launch_bounds__(256,2): with PREUSE smem=104KB -> 2 blocks/SM.
// =====================================================================
template<int TKV, int KVLEN, int NTILES, int NSTAGE, bool PREUSE>
__global__ void __launch_bounds__(256, 2)
flash_k(const float* __restrict__ Q, const float* __restrict__ K,
        const float* __restrict__ V, float* __restrict__ O,
        long kv_bstride){
    constexpr int NT = TKV / 8;
    constexpr int LQ = 68, LK = 68, LV = 72;
    constexpr int LP = PREUSE ? LQ : (TKV + 4);
    static_assert(!PREUSE || TKV <= LQ, "P overflow");
    extern __shared__ float sm[];
    float* Qs = sm;
    float* Ks = sm + 128 * LQ;
    float* Vs = Ks + NSTAGE * TKV * LK;
    float* Pall = PREUSE ? Qs : (Vs + NSTAGE * TKV * LV);

    int tid = threadIdx.x;
    int w = tid >> 5, lane = tid & 31;
    int g = lane >> 2, tg = lane & 3;
    int qt = blockIdx.x;
    int b = blockIdx.y / NHH, h = blockIdx.y % NHH;

    const float* Qb = Q + ((long)(b * SS + qt * 128)) * CC + h * DHH;
    const float* Kb = K + (long)b * kv_bstride + h * DHH;
    const float* Vb = V + (long)b * kv_bstride + h * DHH;

    auto loadQ = [&](){
        #pragma unroll
        for (int i = 0; i < 8; i++){
            int c = tid + i * 256;
            int row = c >> 4, d4 = (c & 15) << 2;
            cp16(Qs + row * LQ + d4, Qb + (long)row * CC + d4, 16);
        }
    };
    auto loadKV = [&](int s, int t){
        constexpr int CH = TKV * 16;
        #pragma unroll
        for (int i = 0; i < CH / 256; i++){
            int c = tid + i * 256;
            int row = c >> 4, d4 = (c & 15) << 2;
            int r = t * TKV + row;
            int by = (r < KVLEN) ? 16 : 0;
            const float* ksrc = by ? (Kb + (long)r * CC + d4) : Kb;
            const float* vsrc = by ? (Vb + (long)r * CC + d4) : Vb;
            cp16(Ks + s * TKV * LK + row * LK + d4, ksrc, by);
            cp16(Vs + s * TKV * LV + row * LV + d4, vsrc, by);
        }
    };

    loadQ(); loadKV(0, 0); cp_commit();
    if (NTILES > 1){ loadKV(1, 1); cp_commit(); }

    float qa[8][4];
    float oacc[8][4];
    #pragma unroll
    for (int j = 0; j < 8; j++)
        #pragma unroll
        for (int r = 0; r < 4; r++) oacc[j][r] = 0.f;
    float m0 = -1e30f, m1 = -1e30f, l0 = 0.f, l1 = 0.f;
    float* Ps = Pall + w * 16 * LP;

    for (int t = 0; t < NTILES; t++){
        if (t + 1 < NTILES) cp_wait<1>(); else cp_wait<0>();
        __syncthreads();
        if (t == 0){
            const float* qsw = Qs + w * 16 * LQ;
            #pragma unroll
            for (int kk = 0; kk < 8; kk++){
                qa[kk][0] = qsw[(g    ) * LQ + kk * 8 + tg    ];
                qa[kk][1] = qsw[(g + 8) * LQ + kk * 8 + tg    ];
                qa[kk][2] = qsw[(g    ) * LQ + kk * 8 + tg + 4];
                qa[kk][3] = qsw[(g + 8) * LQ + kk * 8 + tg + 4];
            }
            __syncwarp();
        }
        const float* Kt = Ks + (t % NSTAGE) * TKV * LK;
        const float* Vt = Vs + (t % NSTAGE) * TKV * LV;

        float sacc[NT][4];
        #pragma unroll
        for (int j = 0; j < NT; j++)
            #pragma unroll
            for (int r = 0; r < 4; r++) sacc[j][r] = 0.f;
        #pragma unroll
        for (int j = 0; j < NT; j++){
            const float* krow = Kt + (j * 8 + g) * LK;
            #pragma unroll
            for (int kk = 0; kk < 8; kk++)
                mma_tf32f(sacc[j], qa[kk], krow[kk * 8 + tg], krow[kk * 8 + tg + 4]);
        }
        if (KVLEN < NTILES * TKV && t == NTILES - 1){
            #pragma unroll
            for (int j = 0; j < NT; j++){
                int col = t * TKV + j * 8 + 2 * tg;
                if (col     >= KVLEN){ sacc[j][0] = -1e30f; sacc[j][2] = -1e30f; }
                if (col + 1 >= KVLEN){ sacc[j][1] = -1e30f; sacc[j][3] = -1e30f; }
            }
        }
        float rm0 = -1e30f, rm1 = -1e30f;
        #pragma unroll
        for (int j = 0; j < NT; j++){
            rm0 = fmaxf(rm0, fmaxf(sacc[j][0], sacc[j][1]));
            rm1 = fmaxf(rm1, fmaxf(sacc[j][2], sacc[j][3]));
        }
        rm0 = fmaxf(rm0, __shfl_xor_sync(0xffffffffu, rm0, 1));
        rm0 = fmaxf(rm0, __shfl_xor_sync(0xffffffffu, rm0, 2));
        rm1 = fmaxf(rm1, __shfl_xor_sync(0xffffffffu, rm1, 1));
        rm1 = fmaxf(rm1, __shfl_xor_sync(0xffffffffu, rm1, 2));
        float mn0 = fmaxf(m0, rm0), mn1 = fmaxf(m1, rm1);
        float a0 = __expf(m0 - mn0), a1 = __expf(m1 - mn1);
        float rs0 = 0.f, rs1 = 0.f;
        #pragma unroll
        for (int j = 0; j < NT; j++){
            sacc[j][0] = __expf(sacc[j][0] - mn0);
            sacc[j][1] = __expf(sacc[j][1] - mn0);
            sacc[j][2] = __expf(sacc[j][2] - mn1);
            sacc[j][3] = __expf(sacc[j][3] - mn1);
            rs0 += sacc[j][0] + sacc[j][1];
            rs1 += sacc[j][2] + sacc[j][3];
        }
        rs0 += __shfl_xor_sync(0xffffffffu, rs0, 1);
        rs0 += __shfl_xor_sync(0xffffffffu, rs0, 2);
        rs1 += __shfl_xor_sync(0xffffffffu, rs1, 1);
        rs1 += __shfl_xor_sync(0xffffffffu, rs1, 2);
        l0 = l0 * a0 + rs0;  l1 = l1 * a1 + rs1;
        m0 = mn0;  m1 = mn1;
        #pragma unroll
        for (int jn = 0; jn < 8; jn++){
            oacc[jn][0] *= a0; oacc[jn][1] *= a0;
            oacc[jn][2] *= a1; oacc[jn][3] *= a1;
        }
        #pragma unroll
        for (int j = 0; j < NT; j++){
            Ps[(g    ) * LP + j * 8 + 2 * tg    ] = sacc[j][0];
            Ps[(g    ) * LP + j * 8 + 2 * tg + 1] = sacc[j][1];
            Ps[(g + 8) * LP + j * 8 + 2 * tg    ] = sacc[j][2];
            Ps[(g + 8) * LP + j * 8 + 2 * tg + 1] = sacc[j][3];
        }
        __syncwarp();
        #pragma unroll
        for (int kk = 0; kk < NT; kk++){
            float pa[4];
            pa[0] = Ps[(g    ) * LP + kk * 8 + tg    ];
            pa[1] = Ps[(g + 8) * LP + kk * 8 + tg    ];
            pa[2] = Ps[(g    ) * LP + kk * 8 + tg + 4];
            pa[3] = Ps[(g + 8) * LP + kk * 8 + tg + 4];
            #pragma unroll
            for (int jn = 0; jn < 8; jn++){
                float vb0 = Vt[(kk * 8 + tg    ) * LV + jn * 8 + g];
                float vb1 = Vt[(kk * 8 + tg + 4) * LV + jn * 8 + g];
                mma_tf32f(oacc[jn], pa, vb0, vb1);
            }
        }
        __syncthreads();
        if (t + 2 < NTILES) loadKV(t % 2, t + 2);
        cp_commit();
    }

    float inv0 = 1.f / l0, inv1 = 1.f / l1;
    float* Ob = O + ((long)(b * SS + qt * 128 + w * 16)) * CC + h * DHH;
    #pragma unroll
    for (int jn = 0; jn < 8; jn++){
        int col = jn * 8 + 2 * tg;
        Ob[(long)(g    ) * CC + col    ] = oacc[jn][0] * inv0;
        Ob[(long)(g    ) * CC + col + 1] = oacc[jn][1] * inv0;
        Ob[(long)(g + 8) * CC + col    ] = oacc[jn][2] * inv1;
        Ob[(long)(g + 8) * CC + col + 1] = oacc[jn][3] * inv1;
    }
}

// =====================================================================
// NN tf32 GEMM (R7 core, passing): BM=128, BN=128, 4 warps of 64x64,
// BK=32, 3-stage cp.async, 2 blocks/SM.
// Multi-z: blockIdx.z selects B/C pointer (fused QKV, fused cross-KV).
// LNA: A-load applies layernorm on the fly (LDG -> normalize -> STS);
// only B participates in cp.async groups (wait<1> still gates B(t)).
// GEGLU: B column remap + u*gelu(gate) epilogue (R7, passing).
// =====================================================================
constexpr int GK_LA = 36;
constexpr int GK_LB = 136;
constexpr int GK_AW = 128 * GK_LA;
constexpr int GK_BW = 32 * GK_LB;
constexpr int GK_SMEM = 3 * (GK_AW + GK_BW) * 4;   // 107,520 B

template<bool GEGLU, bool LNA>
__global__ void mma_gemm_k(const float* __restrict__ A,
                           const float* __restrict__ B0, const float* __restrict__ B1,
                           const float* __restrict__ B2,
                           float* __restrict__ C0, float* __restrict__ C1,
                           float* __restrict__ C2,
                           const float* __restrict__ bias, const float* __restrict__ res,
                           const float* __restrict__ lnst, const float* __restrict__ lnsc,
                           const float* __restrict__ lnbi,
                           int M, int N, int K, int lda, int ldb, int ldc){
    constexpr int BK = 32, STAGES = 3;
    extern __shared__ float sm[];
    float* As = sm;
    float* Bs = sm + STAGES * GK_AW;

    int z = blockIdx.z;
    const float* Bm = (z == 0) ? B0 : (z == 1) ? B1 : B2;
    float*       C  = (z == 0) ? C0 : (z == 1) ? C1 : C2;

    int tid  = threadIdx.x;
    int warp = tid >> 5, lane = tid & 31;
    int g  = lane >> 2;
    int tg = lane & 3;
    int wm = (warp & 1) * 64;
    int wn = (warp >> 1) * 64;
    int row0 = blockIdx.y * 128;
    int col0 = GEGLU ? 0 : blockIdx.x * 128;
    int c0h  = blockIdx.x * 64;

    float acc[4][8][4];
    #pragma unroll
    for (int i = 0; i < 4; i++)
        #pragma unroll
        for (int j = 0; j < 8; j++)
            #pragma unroll
            for (int r = 0; r < 4; r++) acc[i][j][r] = 0.f;

    auto loadA = [&](int s, int kt){
        float* base = As + s * GK_AW;
        #pragma unroll
        for (int it = 0; it < 8; it++){
            int c = tid + it * 128;
            int m  = c >> 3;
            int kc = (c & 7) << 2;
            int gm = row0 + m, gk = kt + kc;
            if (LNA){
                float4 v = {0.f, 0.f, 0.f, 0.f};
                if (gm < M){
                    v = *(const float4*)(A + (long)gm * lda + gk);
                    float mu = lnst[2 * gm], rs = lnst[2 * gm + 1];
                    float4 sc4 = *(const float4*)(lnsc + gk);
                    float4 bi4 = *(const float4*)(lnbi + gk);
                    v.x = (v.x - mu) * rs * sc4.x + bi4.x;
                    v.y = (v.y - mu) * rs * sc4.y + bi4.y;
                    v.z = (v.z - mu) * rs * sc4.z + bi4.z;
                    v.w = (v.w - mu) * rs * sc4.w + bi4.w;
                }
                *(float4*)(base + m * GK_LA + kc) = v;
            } else {
                int bytes = (gm < M && gk < K) ? 16 : 0;
                const float* src = bytes ? (A + (long)gm * lda + gk) : A;
                cp16(base + m * GK_LA + kc, src, bytes);
            }
        }
    };
    auto loadB = [&](int s, int kt){
        float* base = Bs + s * GK_BW;
        #pragma unroll
        for (int it = 0; it < 8; it++){
            int c = tid + it * 128;
            int kr = c >> 5;
            int nc = (c & 31) << 2;
            int gk = kt + kr;
            int gn;
            if (GEGLU) gn = c0h + (nc & 63) + ((nc >= 64) ? 2048 : 0);
            else       gn = col0 + nc;
            int bytes = (gk < K && gn < N) ? 16 : 0;
            const float* src = bytes ? (Bm + (long)gk * ldb + gn) : Bm;
            cp16(base + kr * GK_LB + nc, src, bytes);
        }
    };
    auto compute = [&](int s){
        const float* Ab = As + s * GK_AW;
        const float* Bb = Bs + s * GK_BW;
        #pragma unroll
        for (int ks = 0; ks < BK; ks += 8){
            uint32_t bf[8][2];
            #pragma unroll
            for (int j = 0; j < 8; j++){
                bf[j][0] = __float_as_uint(Bb[(ks + tg    ) * GK_LB + wn + j * 8 + g]);
                bf[j][1] = __float_as_uint(Bb[(ks + tg + 4) * GK_LB + wn + j * 8 + g]);
            }
            #pragma unroll
            for (int i = 0; i < 4; i++){
                int mr = wm + i * 16 + g;
                uint32_t af[4];
                af[0] = __float_as_uint(Ab[(mr    ) * GK_LA + ks + tg]);
                af[1] = __float_as_uint(Ab[(mr + 8) * GK_LA + ks + tg]);
                af[2] = __float_as_uint(Ab[(mr    ) * GK_LA + ks + tg + 4]);
                af[3] = __float_as_uint(Ab[(mr + 8) * GK_LA + ks + tg + 4]);
                #pragma unroll
                for (int j = 0; j < 8; j++)
                    mma_tf32(acc[i][j], af, bf[j]);
            }
        }
    };

    int nk = (K + BK - 1) / BK;
    #pragma unroll
    for (int s = 0; s < STAGES - 1; s++){
        if (s < nk){ loadA(s, s * BK); loadB(s, s * BK); }
        cp_commit();
    }
    for (int t = 0; t < nk; t++){
        cp_wait<STAGES - 2>();
        __syncthreads();
        int tn = t + STAGES - 1;
        if (tn < nk){ loadA(tn % STAGES, tn * BK); loadB(tn % STAGES, tn * BK); }
        cp_commit();
        compute(t % STAGES);
    }

    if (!GEGLU){
        #pragma unroll
        for (int i = 0; i < 4; i++){
            int r0 = row0 + wm + i * 16 + g;
            int r1 = r0 + 8;
            #pragma unroll
            for (int j = 0; j < 8; j++){
                int c0 = col0 + wn + j * 8 + 2 * tg;
                float* a4 = acc[i][j];
                float b0 = 0.f, b1v = 0.f;
                if (bias){ b0 = bias[c0]; b1v = bias[c0 + 1]; }
                if (r0 < M){
                    float2 v = {a4[0] + b0, a4[1] + b1v};
                    if (res){
                        float2 rr = *(const float2*)&res[(long)r0 * ldc + c0];
                        v.x += rr.x; v.y += rr.y;
                    }
                    *(float2*)&C[(long)r0 * ldc + c0] = v;
                }
                if (r1 < M){
                    float2 v = {a4[2] + b0, a4[3] + b1v};
                    if (res){
                        float2 rr = *(const float2*)&res[(long)r1 * ldc + c0];
                        v.x += rr.x; v.y += rr.y;
                    }
                    *(float2*)&C[(long)r1 * ldc + c0] = v;
                }
            }
        }
    } else {
        constexpr int LE = 68;
        float* ex = sm;
        __syncthreads();
        if (wn == 64){
            #pragma unroll
            for (int i = 0; i < 4; i++){
                int lr0 = wm + i * 16 + g, lr1 = lr0 + 8;
                #pragma unroll
                for (int j = 0; j < 8; j++){
                    int gc = j * 8 + 2 * tg;
                    float bg0 = bias[c0h + gc + 2048];
                    float bg1 = bias[c0h + gc + 1 + 2048];
                    ex[lr0 * LE + gc    ] = gelu_exact(acc[i][j][0] + bg0);
                    ex[lr0 * LE + gc + 1] = gelu_exact(acc[i][j][1] + bg1);
                    ex[lr1 * LE + gc    ] = gelu_exact(acc[i][j][2] + bg0);
                    ex[lr1 * LE + gc + 1] = gelu_exact(acc[i][j][3] + bg1);
                }
            }
        }
        __syncthreads();
        if (wn == 0){
            #pragma unroll
            for (int i = 0; i < 4; i++){
                int lr0 = wm + i * 16 + g, lr1 = lr0 + 8;
                long gr0 = row0 + lr0, gr1 = row0 + lr1;
                #pragma unroll
                for (int j = 0; j < 8; j++){
                    int lc = j * 8 + 2 * tg;
                    float bu0 = bias[c0h + lc], bu1 = bias[c0h + lc + 1];
                    float2 v0 = {(acc[i][j][0] + bu0) * ex[lr0 * LE + lc],
                                 (acc[i][j][1] + bu1) * ex[lr0 * LE + lc + 1]};
                    float2 v1 = {(acc[i][j][2] + bu0) * ex[lr1 * LE + lc],
                                 (acc[i][j][3] + bu1) * ex[lr1 * LE + lc + 1]};
                    *(float2*)&C[gr0 * ldc + c0h + lc] = v0;
                    *(float2*)&C[gr1 * ldc + c0h + lc] = v1;
                }
            }
        }
    }
}

// ---------------- launch helpers ----------------
static void gemm_plain(const float* A, const float* W, const float* bias, const float* res,
                       float* C, int M, int N, int K, int lda, int ldb, int ldc){
    cudaFuncSetAttribute(mma_gemm_k<false,false>,
                         cudaFuncAttributeMaxDynamicSharedMemorySize, GK_SMEM);
    dim3 g((N + 127) / 128, (M + 127) / 128, 1);
    mma_gemm_k<false,false><<<g, 128, GK_SMEM>>>(A, W, W, W, C, C, C, bias, res,
                                                 nullptr, nullptr, nullptr,
                                                 M, N, K, lda, ldb, ldc);
}
static void gemm_ln(const float* A, const float* W, const float* bias,
                    float* C, const float* lnst, const float* lnsc, const float* lnbi){
    cudaFuncSetAttribute(mma_gemm_k<false,true>,
                         cudaFuncAttributeMaxDynamicSharedMemorySize, GK_SMEM);
    dim3 g(CC / 128, MM / 128, 1);
    mma_gemm_k<false,true><<<g, 128, GK_SMEM>>>(A, W, W, W, C, C, C, bias, nullptr,
                                                lnst, lnsc, lnbi,
                                                MM, CC, CC, CC, CC, CC);
}
static void gemm_qkv_ln(const float* A, const float* W0, const float* W1, const float* W2,
                        float* C0, float* C1, float* C2,
                        const float* lnst, const float* lnsc, const float* lnbi){
    cudaFuncSetAttribute(mma_gemm_k<false,true>,
                         cudaFuncAttributeMaxDynamicSharedMemorySize, GK_SMEM);
    dim3 g(CC / 128, MM / 128, 3);
    mma_gemm_k<false,true><<<g, 128, GK_SMEM>>>(A, W0, W1, W2, C0, C1, C2,
                                                nullptr, nullptr,
                                                lnst, lnsc, lnbi,
                                                MM, CC, CC, CC, CC, CC);
}
static void gemm_kv2(const float* A, const float* W0, const float* W1,
                     float* C0, float* C1){
    cudaFuncSetAttribute(mma_gemm_k<false,false>,
                         cudaFuncAttributeMaxDynamicSharedMemorySize, GK_SMEM);
    dim3 g(CC / 128, (MKV + 127) / 128, 2);
    mma_gemm_k<false,false><<<g, 128, GK_SMEM>>>(A, W0, W1, W1, C0, C1, C1,
                                                 nullptr, nullptr,
                                                 nullptr, nullptr, nullptr,
                                                 MKV, CC, DCC, DCC, CC, CC);
}
static void gemm_geglu_ln(const float* A, const float* W1, const float* b1, float* G,
                          const float* lnst, const float* lnsc, const float* lnbi){
    cudaFuncSetAttribute(mma_gemm_k<true,true>,
                         cudaFuncAttributeMaxDynamicSharedMemorySize, GK_SMEM);
    dim3 g(2048 / 64, MM / 128, 1);
    mma_gemm_k<true,true><<<g, 128, GK_SMEM>>>(A, W1, W1, W1, G, G, G, b1, nullptr,
                                               lnst, lnsc, lnbi,
                                               MM, 4096, CC, CC, 4096, 2048);
}

extern "C" void kernel_launch(void* const* d_in, const int* in_sizes, int n_in,
                              void* d_out, int out_size){
    (void)in_sizes; (void)n_in; (void)out_size;
    const float* x      = (const float*)d_in[0];
    const float* cond   = (const float*)d_in[1];
    const float* gn_s   = (const float*)d_in[2];
    const float* gn_b   = (const float*)d_in[3];
    const float* pin_w  = (const float*)d_in[4];
    const float* pin_b  = (const float*)d_in[5];
    const float* pout_w = (const float*)d_in[6];
    const float* pout_b = (const float*)d_in[7];
    const float* ln1_s  = (const float*)d_in[8];
    const float* ln1_b  = (const float*)d_in[9];
    const float* sa_wq  = (const float*)d_in[10];
    const float* sa_wk  = (const float*)d_in[11];
    const float* sa_wv  = (const float*)d_in[12];
    const float* sa_wo  = (const float*)d_in[13];
    const float* sa_bo  = (const float*)d_in[14];
    const float* ln2_s  = (const float*)d_in[15];
    const float* ln2_b  = (const float*)d_in[16];
    const float* ca_wq  = (const float*)d_in[17];
    const float* ca_wk  = (const float*)d_in[18];
    const float* ca_wv  = (const float*)d_in[19];
    const float* ca_wo  = (const float*)d_in[20];
    const float* ca_bo  = (const float*)d_in[21];
    const float* ln3_s  = (const float*)d_in[22];
    const float* ln3_b  = (const float*)d_in[23];
    const float* ff_w1  = (const float*)d_in[24];
    const float* ff_b1  = (const float*)d_in[25];
    const float* ff_w2  = (const float*)d_in[26];
    const float* ff_b2  = (const float*)d_in[27];
    float* out = (float*)d_out;

    float *p_t, *p_tn, *p_q, *p_k, *p_v, *p_ao, *p_gg, *p_stats, *p_lnst;
    cudaGetSymbolAddress((void**)&p_t,    g_t);
    cudaGetSymbolAddress((void**)&p_tn,   g_tn);
    cudaGetSymbolAddress((void**)&p_q,    g_q);
    cudaGetSymbolAddress((void**)&p_k,    g_k);
    cudaGetSymbolAddress((void**)&p_v,    g_v);
    cudaGetSymbolAddress((void**)&p_ao,   g_ao);
    cudaGetSymbolAddress((void**)&p_gg,   g_gg);
    cudaGetSymbolAddress((void**)&p_stats,g_stats);
    cudaGetSymbolAddress((void**)&p_lnst, g_lnst);

    // flash smem sizes: self reuses Q for P (2 blocks/SM); cross dedicated P
    constexpr int SM_SELF  = (128 * 68 + 2 * 64 * 68 + 2 * 64 * 72) * 4;            // 106,496
    constexpr int SM_CROSS = (128 * 68 + 80 * 68 + 80 * 72 + 128 * (80 + 4)) * 4;   // 122,624
    cudaFuncSetAttribute(flash_k<64, 1024, 16, 2, true>,
                         cudaFuncAttributeMaxDynamicSharedMemorySize, SM_SELF);
    cudaFuncSetAttribute(flash_k<80, 77, 1, 1, false>,
                         cudaFuncAttributeMaxDynamicSharedMemorySize, SM_CROSS);

    gn_stats_k<<<BB * 32, 256>>>(x, p_stats);
    {
        dim3 g(SS / 32, CC / 32, BB);
        gn_apply_t_k<<<g, dim3(32, 8)>>>(x, p_stats, gn_s, gn_b, p_tn);
    }
    gemm_plain(p_tn, pin_w, pin_b, nullptr, p_t, MM, CC, CC, CC, CC, CC);

    for (int l = 0; l < 2; l++){
        const float* wq = sa_wq + (long)l * CC * CC;
        const float* wk = sa_wk + (long)l * CC * CC;
        const float* wv = sa_wv + (long)l * CC * CC;
        const float* wo = sa_wo + (long)l * CC * CC;
        const float* bo = sa_bo + (long)l * CC;
        const float* cwq = ca_wq + (long)l * CC * CC;
        const float* cwk = ca_wk + (long)l * DCC * CC;
        const float* cwv = ca_wv + (long)l * DCC * CC;
        const float* cwo = ca_wo + (long)l * CC * CC;
        const float* cbo = ca_bo + (long)l * CC;
        const float* w1 = ff_w1 + (long)l * CC * 4096;
        const float* b1 = ff_b1 + (long)l * 4096;
        const float* w2 = ff_w2 + (long)l * 2048 * CC;
        const float* b2 = ff_b2 + (long)l * CC;

        // ---- self-attention: LN1 fused into QKV (one 3-z launch) ----
        ln_stats_k<<<MM / 8, 256>>>(p_t, p_lnst);
        gemm_qkv_ln(p_t, wq, wk, wv, p_q, p_k, p_v,
                    p_lnst, ln1_s + l * CC, ln1_b + l * CC);
        flash_k<64, 1024, 16, 2, true><<<dim3(SS / 128, BB * NHH), 256, SM_SELF>>>(
            p_q, p_k, p_v, p_ao, (long)SS * CC);
        gemm_plain(p_ao, wo, bo, p_t, p_t, MM, CC, CC, CC, CC, CC);

        // ---- cross-attention: LN2 fused into Q; K/V batched (z=2) ----
        ln_stats_k<<<MM / 8, 256>>>(p_t, p_lnst);
        gemm_ln(p_t, cwq, nullptr, p_q, p_lnst, ln2_s + l * CC, ln2_b + l * CC);
        gemm_kv2(cond, cwk, cwv, p_k, p_v);
        flash_k<80, 77, 1, 1, false><<<dim3(SS / 128, BB * NHH), 256, SM_CROSS>>>(
            p_q, p_k, p_v, p_ao, (long)NCC * CC);
        gemm_plain(p_ao, cwo, cbo, p_t, p_t, MM, CC, CC, CC, CC, CC);

        // ---- FFN: LN3 + GEGLU both fused into FFN1 ----
        ln_stats_k<<<MM / 8, 256>>>(p_t, p_lnst);
        gemm_geglu_ln(p_t, w1, b1, p_gg, p_lnst, ln3_s + l * CC, ln3_b + l * CC);
        gemm_plain(p_gg, w2, b2, p_t, p_t, MM, CC, 2048, 2048, CC, CC);
    }

    gemm_plain(p_t, pout_w, pout_b, nullptr, p_tn, MM, CC, CC, CC, CC, CC);
    {
        dim3 g(SS / 32, CC / 32, BB);
        out_add_t_k<<<g, dim3(32, 8)>>>(p_tn, x, out);
    }
}

// round 11
// speedup vs baseline: 1.5550x; 1.5550x over previous
#include <cuda_runtime.h>
#include <cuda_fp16.h>
#include <math.h>
#include <stdint.h>

// ---------------- problem constants ----------------
constexpr int BB   = 8;
constexpr int CC   = 512;
constexpr int SS   = 1024;
constexpr int NHH  = 8;
constexpr int DHH  = 64;
constexpr int NCC  = 77;
constexpr int DCC  = 768;
constexpr int MM   = BB * SS;  // 8192
constexpr int MKV  = BB * NCC; // 616

// ---------------- scratch ----------------
__device__ __align__(256) float  g_t    [ (long)MM * CC ];     // fp32 residual
__device__ __align__(256) float  g_q    [ (long)MM * CC ];     // flash inputs (fp32)
__device__ __align__(256) float  g_k    [ (long)MM * CC ];
__device__ __align__(256) float  g_v    [ (long)MM * CC ];
__device__ __align__(256) __half g_tn_h [ (long)MM * CC ];     // LN/GN outputs (fp16)
__device__ __align__(256) __half g_ao_h [ (long)MM * CC ];     // flash output (fp16)
__device__ __align__(256) __half g_gg_h [ (long)MM * 2048 ];   // GEGLU output (fp16)
__device__ __align__(256) __half g_w16  [ 16252928 ];          // fp16 arena (weights+cond+t16)
__device__ __align__(256) float  g_stats[ 2 * BB * 32 ];

// ---------------- reductions ----------------
__inline__ __device__ float warpSum(float v){
    #pragma unroll
    for (int o = 16; o > 0; o >>= 1) v += __shfl_xor_sync(0xffffffffu, v, o);
    return v;
}

// ---------------- cp.async ----------------
__device__ __forceinline__ uint32_t smem_u32(const void* p){
    return (uint32_t)__cvta_generic_to_shared(p);
}
__device__ __forceinline__ void cp16(void* dst, const void* src, int bytes){
    asm volatile("cp.async.cg.shared.global [%0], [%1], 16, %2;\n"
                 :: "r"(smem_u32(dst)), "l"(src), "r"(bytes));
}
__device__ __forceinline__ void cp16a(uint32_t dst, const void* src, int bytes){
    asm volatile("cp.async.cg.shared.global [%0], [%1], 16, %2;\n"
                 :: "r"(dst), "l"(src), "r"(bytes));
}
__device__ __forceinline__ void cp_commit(){ asm volatile("cp.async.commit_group;\n"); }
template<int N> __device__ __forceinline__ void cp_wait(){
    asm volatile("cp.async.wait_group %0;\n" :: "n"(N));
}

// ---------------- ldmatrix / mma fp16 ----------------
__device__ __forceinline__ void ldsm_x4(uint32_t* r, uint32_t addr){
    asm volatile("ldmatrix.sync.aligned.m8n8.x4.shared.b16 {%0,%1,%2,%3}, [%4];"
        : "=r"(r[0]), "=r"(r[1]), "=r"(r[2]), "=r"(r[3]) : "r"(addr));
}
__device__ __forceinline__ void ldsm_x4_t(uint32_t* r, uint32_t addr){
    asm volatile("ldmatrix.sync.aligned.m8n8.x4.trans.shared.b16 {%0,%1,%2,%3}, [%4];"
        : "=r"(r[0]), "=r"(r[1]), "=r"(r[2]), "=r"(r[3]) : "r"(addr));
}
__device__ __forceinline__ void mma_f16(float* c, const uint32_t* a, const uint32_t* b){
    asm volatile("mma.sync.aligned.m16n8k16.row.col.f32.f16.f16.f32 "
        "{%0,%1,%2,%3}, {%4,%5,%6,%7}, {%8,%9}, {%0,%1,%2,%3};"
        : "+f"(c[0]), "+f"(c[1]), "+f"(c[2]), "+f"(c[3])
        : "r"(a[0]), "r"(a[1]), "r"(a[2]), "r"(a[3]), "r"(b[0]), "r"(b[1]));
}

// ---------------- mma tf32 (flash only) ----------------
__inline__ __device__ void mma_tf32(float* c, const uint32_t* a, const uint32_t* b){
    asm volatile(
        "mma.sync.aligned.m16n8k8.row.col.f32.tf32.tf32.f32 "
        "{%0,%1,%2,%3}, {%4,%5,%6,%7}, {%8,%9}, {%0,%1,%2,%3};"
        : "+f"(c[0]), "+f"(c[1]), "+f"(c[2]), "+f"(c[3])
        : "r"(a[0]), "r"(a[1]), "r"(a[2]), "r"(a[3]), "r"(b[0]), "r"(b[1]));
}
__inline__ __device__ void mma_tf32f(float* c, const float* a, float b0, float b1){
    uint32_t au[4] = {__float_as_uint(a[0]), __float_as_uint(a[1]),
                      __float_as_uint(a[2]), __float_as_uint(a[3])};
    uint32_t bu[2] = {__float_as_uint(b0), __float_as_uint(b1)};
    mma_tf32(c, au, bu);
}

__inline__ __device__ float gelu_exact(float x){
    return 0.5f * x * (1.f + erff(x * 0.70710678118654752f));
}

// ---------------- fp32 -> fp16 batched convert ----------------
struct CvtBatch { const float* s[16]; __half* d[16]; };
__global__ void cvt_k(CvtBatch cb, int n4){
    const float4* s = (const float4*)cb.s[blockIdx.z];
    __half2* d = (__half2*)cb.d[blockIdx.z];
    int i = blockIdx.x * blockDim.x + threadIdx.x;
    if (i >= n4) return;
    float4 v = s[i];
    d[2 * i]     = __floats2half2_rn(v.x, v.y);
    d[2 * i + 1] = __floats2half2_rn(v.z, v.w);
}

// ---------------- groupnorm stats ----------------
__global__ void gn_stats_k(const float* __restrict__ x, float* __restrict__ stats){
    long base = (long)blockIdx.x * 16384;
    float s = 0.f, q = 0.f;
    for (int i = threadIdx.x; i < 16384; i += blockDim.x){
        float v = x[base + i];
        s += v; q += v * v;
    }
    __shared__ float shs[8], shq[8];
    s = warpSum(s); q = warpSum(q);
    int w = threadIdx.x >> 5, l = threadIdx.x & 31;
    if (l == 0){ shs[w] = s; shq[w] = q; }
    __syncthreads();
    if (threadIdx.x < 32){
        s = (l < 8) ? shs[l] : 0.f;
        q = (l < 8) ? shq[l] : 0.f;
        s = warpSum(s); q = warpSum(q);
        if (l == 0){
            float mean = s * (1.f / 16384.f);
            float var  = q * (1.f / 16384.f) - mean * mean;
            stats[2 * blockIdx.x]     = mean;
            stats[2 * blockIdx.x + 1] = rsqrtf(var + 1e-6f);
        }
    }
}

// ---------------- groupnorm apply + transpose (fp16 out) ----------------
__global__ void gn_apply_t_k(const float* __restrict__ x, const float* __restrict__ stats,
                             const float* __restrict__ gs, const float* __restrict__ gb,
                             __half* __restrict__ out){
    __shared__ float tile[32][33];
    int b = blockIdx.z, c0 = blockIdx.y * 32, p0 = blockIdx.x * 32;
    int tx = threadIdx.x, ty = threadIdx.y;
    #pragma unroll
    for (int r = 0; r < 4; r++){
        int c = c0 + ty + r * 8;
        float v = x[((long)b * CC + c) * SS + p0 + tx];
        int grp = b * 32 + (c >> 4);
        v = (v - stats[2 * grp]) * stats[2 * grp + 1] * gs[c] + gb[c];
        tile[ty + r * 8][tx] = v;
    }
    __syncthreads();
    #pragma unroll
    for (int r = 0; r < 4; r++){
        int p = p0 + ty + r * 8;
        out[((long)b * SS + p) * CC + c0 + tx] = __float2half(tile[tx][ty + r * 8]);
    }
}

// ---------------- final transpose + x_in residual ----------------
__global__ void out_add_t_k(const float* __restrict__ z, const float* __restrict__ x,
                            float* __restrict__ out){
    __shared__ float tile[32][33];
    int b = blockIdx.z, c0 = blockIdx.y * 32, p0 = blockIdx.x * 32;
    int tx = threadIdx.x, ty = threadIdx.y;
    #pragma unroll
    for (int r = 0; r < 4; r++){
        int p = p0 + ty + r * 8;
        tile[ty + r * 8][tx] = z[((long)b * SS + p) * CC + c0 + tx];
    }
    __syncthreads();
    #pragma unroll
    for (int r = 0; r < 4; r++){
        int c = c0 + ty + r * 8;
        long o = ((long)b * CC + c) * SS + p0 + tx;
        out[o] = tile[tx][ty + r * 8] + x[o];
    }
}

// ---------------- layernorm (fp32 in, fp16 out) ----------------
__global__ void layernorm_k(const float* __restrict__ in, const float* __restrict__ sc,
                            const float* __restrict__ bi, __half* __restrict__ out){
    long row = blockIdx.x;
    const float4* x4 = (const float4*)(in + row * CC);
    float4 xv = x4[threadIdx.x];
    float s = xv.x + xv.y + xv.z + xv.w;
    float q = xv.x*xv.x + xv.y*xv.y + xv.z*xv.z + xv.w*xv.w;
    __shared__ float shs[4], shq[4];
    s = warpSum(s); q = warpSum(q);
    int w = threadIdx.x >> 5, l = threadIdx.x & 31;
    if (l == 0){ shs[w] = s; shq[w] = q; }
    __syncthreads();
    if (threadIdx.x < 32){
        float a = (l < 4) ? shs[l] : 0.f;
        float b2 = (l < 4) ? shq[l] : 0.f;
        a = warpSum(a); b2 = warpSum(b2);
        if (l == 0){ shs[0] = a; shq[0] = b2; }
    }
    __syncthreads();
    float mean = shs[0] * (1.f / 512.f);
    float rstd = rsqrtf(shq[0] * (1.f / 512.f) - mean * mean + 1e-5f);
    float4 sv = ((const float4*)sc)[threadIdx.x];
    float4 bv = ((const float4*)bi)[threadIdx.x];
    __half2* o2 = (__half2*)(out + row * CC);
    o2[2 * threadIdx.x]     = __floats2half2_rn((xv.x - mean) * rstd * sv.x + bv.x,
                                                (xv.y - mean) * rstd * sv.y + bv.y);
    o2[2 * threadIdx.x + 1] = __floats2half2_rn((xv.z - mean) * rstd * sv.z + bv.z,
                                                (xv.w - mean) * rstd * sv.w + bv.w);
}

// =====================================================================
// Flash attention (tf32 mma.sync, online softmax) — R7 config (passing),
// only change: fp16 output (consumed by fp16 wo/cwo GEMM).
// =====================================================================
template<int TKV, int KVLEN, int NTILES, int NSTAGE>
__global__ void flash_k(const float* __restrict__ Q, const float* __restrict__ K,
                        const float* __restrict__ V, __half* __restrict__ O,
                        long kv_bstride){
    constexpr int NT = TKV / 8;
    constexpr int LQ = 68, LK = 68, LV = 72, LP = TKV + 4;
    extern __shared__ float sm[];
    float* Qs = sm;
    float* Ks = sm + 128 * LQ;
    float* Vs = Ks + NSTAGE * TKV * LK;
    float* Pall = Vs + NSTAGE * TKV * LV;

    int tid = threadIdx.x;
    int w = tid >> 5, lane = tid & 31;
    int g = lane >> 2, tg = lane & 3;
    int qt = blockIdx.x;
    int b = blockIdx.y / NHH, h = blockIdx.y % NHH;

    const float* Qb = Q + ((long)(b * SS + qt * 128)) * CC + h * DHH;
    const float* Kb = K + (long)b * kv_bstride + h * DHH;
    const float* Vb = V + (long)b * kv_bstride + h * DHH;

    auto loadQ = [&](){
        #pragma unroll
        for (int i = 0; i < 8; i++){
            int c = tid + i * 256;
            int row = c >> 4, d4 = (c & 15) << 2;
            cp16(Qs + row * LQ + d4, Qb + (long)row * CC + d4, 16);
        }
    };
    auto loadKV = [&](int s, int t){
        constexpr int CH = TKV * 16;
        #pragma unroll
        for (int i = 0; i < CH / 256; i++){
            int c = tid + i * 256;
            int row = c >> 4, d4 = (c & 15) << 2;
            int r = t * TKV + row;
            int by = (r < KVLEN) ? 16 : 0;
            const float* ksrc = by ? (Kb + (long)r * CC + d4) : Kb;
            const float* vsrc = by ? (Vb + (long)r * CC + d4) : Vb;
            cp16(Ks + s * TKV * LK + row * LK + d4, ksrc, by);
            cp16(Vs + s * TKV * LV + row * LV + d4, vsrc, by);
        }
    };

    loadQ(); loadKV(0, 0); cp_commit();
    if (NTILES > 1){ loadKV(1, 1); cp_commit(); }

    float qa[8][4];
    float oacc[8][4];
    #pragma unroll
    for (int j = 0; j < 8; j++)
        #pragma unroll
        for (int r = 0; r < 4; r++) oacc[j][r] = 0.f;
    float m0 = -1e30f, m1 = -1e30f, l0 = 0.f, l1 = 0.f;
    float* Ps = Pall + w * 16 * LP;

    for (int t = 0; t < NTILES; t++){
        if (t + 1 < NTILES) cp_wait<1>(); else cp_wait<0>();
        __syncthreads();
        if (t == 0){
            const float* qsw = Qs + w * 16 * LQ;
            #pragma unroll
            for (int kk = 0; kk < 8; kk++){
                qa[kk][0] = qsw[(g    ) * LQ + kk * 8 + tg    ];
                qa[kk][1] = qsw[(g + 8) * LQ + kk * 8 + tg    ];
                qa[kk][2] = qsw[(g    ) * LQ + kk * 8 + tg + 4];
                qa[kk][3] = qsw[(g + 8) * LQ + kk * 8 + tg + 4];
            }
            __syncwarp();
        }
        const float* Kt = Ks + (t % NSTAGE) * TKV * LK;
        const float* Vt = Vs + (t % NSTAGE) * TKV * LV;

        float sacc[NT][4];
        #pragma unroll
        for (int j = 0; j < NT; j++)
            #pragma unroll
            for (int r = 0; r < 4; r++) sacc[j][r] = 0.f;
        #pragma unroll
        for (int j = 0; j < NT; j++){
            const float* krow = Kt + (j * 8 + g) * LK;
            #pragma unroll
            for (int kk = 0; kk < 8; kk++)
                mma_tf32f(sacc[j], qa[kk], krow[kk * 8 + tg], krow[kk * 8 + tg + 4]);
        }
        if (KVLEN < NTILES * TKV && t == NTILES - 1){
            #pragma unroll
            for (int j = 0; j < NT; j++){
                int col = t * TKV + j * 8 + 2 * tg;
                if (col     >= KVLEN){ sacc[j][0] = -1e30f; sacc[j][2] = -1e30f; }
                if (col + 1 >= KVLEN){ sacc[j][1] = -1e30f; sacc[j][3] = -1e30f; }
            }
        }
        float rm0 = -1e30f, rm1 = -1e30f;
        #pragma unroll
        for (int j = 0; j < NT; j++){
            rm0 = fmaxf(rm0, fmaxf(sacc[j][0], sacc[j][1]));
            rm1 = fmaxf(rm1, fmaxf(sacc[j][2], sacc[j][3]));
        }
        rm0 = fmaxf(rm0, __shfl_xor_sync(0xffffffffu, rm0, 1));
        rm0 = fmaxf(rm0, __shfl_xor_sync(0xffffffffu, rm0, 2));
        rm1 = fmaxf(rm1, __shfl_xor_sync(0xffffffffu, rm1, 1));
        rm1 = fmaxf(rm1, __shfl_xor_sync(0xffffffffu, rm1, 2));
        float mn0 = fmaxf(m0, rm0), mn1 = fmaxf(m1, rm1);
        float a0 = __expf(m0 - mn0), a1 = __expf(m1 - mn1);
        float rs0 = 0.f, rs1 = 0.f;
        #pragma unroll
        for (int j = 0; j < NT; j++){
            sacc[j][0] = __expf(sacc[j][0] - mn0);
            sacc[j][1] = __expf(sacc[j][1] - mn0);
            sacc[j][2] = __expf(sacc[j][2] - mn1);
            sacc[j][3] = __expf(sacc[j][3] - mn1);
            rs0 += sacc[j][0] + sacc[j][1];
            rs1 += sacc[j][2] + sacc[j][3];
        }
        rs0 += __shfl_xor_sync(0xffffffffu, rs0, 1);
        rs0 += __shfl_xor_sync(0xffffffffu, rs0, 2);
        rs1 += __shfl_xor_sync(0xffffffffu, rs1, 1);
        rs1 += __shfl_xor_sync(0xffffffffu, rs1, 2);
        l0 = l0 * a0 + rs0;  l1 = l1 * a1 + rs1;
        m0 = mn0;  m1 = mn1;
        #pragma unroll
        for (int jn = 0; jn < 8; jn++){
            oacc[jn][0] *= a0; oacc[jn][1] *= a0;
            oacc[jn][2] *= a1; oacc[jn][3] *= a1;
        }
        #pragma unroll
        for (int j = 0; j < NT; j++){
            Ps[(g    ) * LP + j * 8 + 2 * tg    ] = sacc[j][0];
            Ps[(g    ) * LP + j * 8 + 2 * tg + 1] = sacc[j][1];
            Ps[(g + 8) * LP + j * 8 + 2 * tg    ] = sacc[j][2];
            Ps[(g + 8) * LP + j * 8 + 2 * tg + 1] = sacc[j][3];
        }
        __syncwarp();
        #pragma unroll
        for (int kk = 0; kk < NT; kk++){
            float pa[4];
            pa[0] = Ps[(g    ) * LP + kk * 8 + tg    ];
            pa[1] = Ps[(g + 8) * LP + kk * 8 + tg    ];
            pa[2] = Ps[(g    ) * LP + kk * 8 + tg + 4];
            pa[3] = Ps[(g + 8) * LP + kk * 8 + tg + 4];
            #pragma unroll
            for (int jn = 0; jn < 8; jn++){
                float vb0 = Vt[(kk * 8 + tg    ) * LV + jn * 8 + g];
                float vb1 = Vt[(kk * 8 + tg + 4) * LV + jn * 8 + g];
                mma_tf32f(oacc[jn], pa, vb0, vb1);
            }
        }
        __syncthreads();
        if (t + 2 < NTILES) loadKV(t % 2, t + 2);
        cp_commit();
    }

    float inv0 = 1.f / l0, inv1 = 1.f / l1;
    __half* Ob = O + ((long)(b * SS + qt * 128 + w * 16)) * CC + h * DHH;
    #pragma unroll
    for (int jn = 0; jn < 8; jn++){
        int col = jn * 8 + 2 * tg;
        *(__half2*)&Ob[(long)(g    ) * CC + col] =
            __floats2half2_rn(oacc[jn][0] * inv0, oacc[jn][1] * inv0);
        *(__half2*)&Ob[(long)(g + 8) * CC + col] =
            __floats2half2_rn(oacc[jn][2] * inv1, oacc[jn][3] * inv1);
    }
}

// =====================================================================
// fp16 NN GEMM via mma.sync.m16n8k16 (HMMA.16816 = 2x tf32 rate).
// BM=128, BN=128, BK=64 halves, 4 warps of 64x64, 3-stage cp.async.
// A [M,K] fp16 row-major; B [K,N] fp16 row-major.
// A frags: ldmatrix.x4; B frags: ldmatrix.x4.trans (row-major [k][n] smem).
// GEGLU: B col remap + u*gelu(gate) epilogue -> fp16 G.
// WH: also write fp16 mirror of C (for proj_out input).
// =====================================================================
constexpr int HLA = 72;                     // A row stride (halves)
constexpr int HLB = 136;                    // B row stride (halves)
constexpr int HAW = 128 * HLA * 2;          // A stage bytes = 18432
constexpr int HBW = 64 * HLB * 2;           // B stage bytes = 17408
constexpr int H_SMEM = 3 * (HAW + HBW);     // 107,520 B

template<bool GEGLU, bool WH>
__global__ void hgemm_k(const __half* __restrict__ A, const __half* __restrict__ Bm,
                        const float* __restrict__ bias, const float* __restrict__ res,
                        float* __restrict__ C, __half* __restrict__ Gh,
                        int M, int N, int K, int lda, int ldb, int ldc){
    constexpr int BK = 64, STAGES = 3;
    extern __shared__ float smf[];
    uint32_t sb = smem_u32(smf);
    uint32_t Abase = sb;
    uint32_t Bbase = sb + 3 * HAW;

    int tid  = threadIdx.x;
    int warp = tid >> 5, lane = tid & 31;
    int g  = lane >> 2;
    int tg = lane & 3;
    int wm = (warp & 1) * 64;
    int wn = (warp >> 1) * 64;
    int row0 = blockIdx.y * 128;
    int col0 = GEGLU ? 0 : blockIdx.x * 128;
    int c0h  = blockIdx.x * 64;

    int lt = lane >> 3, lr = lane & 7;
    uint32_t a_lane = (uint32_t)(((lt & 1) * 8 + lr) * HLA + (lt >> 1) * 8) * 2;
    uint32_t b_lane = (uint32_t)(((lt & 1) * 8 + lr) * HLB + (lt >> 1) * 8) * 2;

    float acc[4][8][4];
    #pragma unroll
    for (int i = 0; i < 4; i++)
        #pragma unroll
        for (int j = 0; j < 8; j++)
            #pragma unroll
            for (int r = 0; r < 4; r++) acc[i][j][r] = 0.f;

    auto loadA = [&](int s, int kt){
        uint32_t base = Abase + s * HAW;
        #pragma unroll
        for (int it = 0; it < 8; it++){
            int c = tid + it * 128;
            int m  = c >> 3;
            int kc = (c & 7) * 8;
            int gm = row0 + m;
            int by = (gm < M) ? 16 : 0;
            const __half* src = by ? (A + (long)gm * lda + kt + kc) : A;
            cp16a(base + (uint32_t)(m * HLA + kc) * 2, src, by);
        }
    };
    auto loadB = [&](int s, int kt){
        uint32_t base = Bbase + s * HBW;
        #pragma unroll
        for (int it = 0; it < 8; it++){
            int c = tid + it * 128;
            int kr = c >> 4;
            int nc = (c & 15) * 8;
            int gk = kt + kr;
            long gn;
            if (GEGLU) gn = (nc < 64) ? (long)(c0h + nc) : (long)(2048 + c0h + nc - 64);
            else       gn = (long)(col0 + nc);
            int by = (gk < K) ? 16 : 0;
            const __half* src = by ? (Bm + (long)gk * ldb + gn) : Bm;
            cp16a(base + (uint32_t)(kr * HLB + nc) * 2, src, by);
        }
    };
    auto compute = [&](int s){
        uint32_t Ab = Abase + s * HAW;
        uint32_t Bb = Bbase + s * HBW;
        #pragma unroll
        for (int ks = 0; ks < 4; ks++){
            uint32_t bf[8][2];
            #pragma unroll
            for (int jp = 0; jp < 4; jp++){
                uint32_t r[4];
                ldsm_x4_t(r, Bb + b_lane +
                          (uint32_t)(ks * 16 * HLB + wn + jp * 16) * 2);
                bf[2*jp  ][0] = r[0]; bf[2*jp  ][1] = r[1];
                bf[2*jp+1][0] = r[2]; bf[2*jp+1][1] = r[3];
            }
            #pragma unroll
            for (int i = 0; i < 4; i++){
                uint32_t af[4];
                ldsm_x4(af, Ab + a_lane +
                        (uint32_t)((wm + i * 16) * HLA + ks * 16) * 2);
                #pragma unroll
                for (int j = 0; j < 8; j++)
                    mma_f16(acc[i][j], af, bf[j]);
            }
        }
    };

    int nk = (K + BK - 1) / BK;
    #pragma unroll
    for (int s = 0; s < STAGES - 1; s++){
        if (s < nk){ loadA(s, s * BK); loadB(s, s * BK); }
        cp_commit();
    }
    for (int t = 0; t < nk; t++){
        cp_wait<STAGES - 2>();
        __syncthreads();
        int tn = t + STAGES - 1;
        if (tn < nk){ loadA(tn % STAGES, tn * BK); loadB(tn % STAGES, tn * BK); }
        cp_commit();
        compute(t % STAGES);
    }

    if (!GEGLU){
        #pragma unroll
        for (int i = 0; i < 4; i++){
            int r0 = row0 + wm + i * 16 + g;
            int r1 = r0 + 8;
            #pragma unroll
            for (int j = 0; j < 8; j++){
                int c0 = col0 + wn + j * 8 + 2 * tg;
                float* a4 = acc[i][j];
                float b0 = 0.f, b1v = 0.f;
                if (bias){ b0 = bias[c0]; b1v = bias[c0 + 1]; }
                if (r0 < M){
                    float2 v = {a4[0] + b0, a4[1] + b1v};
                    if (res){
                        float2 rr = *(const float2*)&res[(long)r0 * ldc + c0];
                        v.x += rr.x; v.y += rr.y;
                    }
                    *(float2*)&C[(long)r0 * ldc + c0] = v;
                    if (WH) *(__half2*)&Gh[(long)r0 * ldc + c0] = __floats2half2_rn(v.x, v.y);
                }
                if (r1 < M){
                    float2 v = {a4[2] + b0, a4[3] + b1v};
                    if (res){
                        float2 rr = *(const float2*)&res[(long)r1 * ldc + c0];
                        v.x += rr.x; v.y += rr.y;
                    }
                    *(float2*)&C[(long)r1 * ldc + c0] = v;
                    if (WH) *(__half2*)&Gh[(long)r1 * ldc + c0] = __floats2half2_rn(v.x, v.y);
                }
            }
        }
    } else {
        constexpr int LE = 68;
        float* ex = smf;
        __syncthreads();
        if (wn == 64){
            #pragma unroll
            for (int i = 0; i < 4; i++){
                int lr0 = wm + i * 16 + g, lr1 = lr0 + 8;
                #pragma unroll
                for (int j = 0; j < 8; j++){
                    int gc = j * 8 + 2 * tg;
                    float bg0 = bias[c0h + gc + 2048];
                    float bg1 = bias[c0h + gc + 1 + 2048];
                    ex[lr0 * LE + gc    ] = gelu_exact(acc[i][j][0] + bg0);
                    ex[lr0 * LE + gc + 1] = gelu_exact(acc[i][j][1] + bg1);
                    ex[lr1 * LE + gc    ] = gelu_exact(acc[i][j][2] + bg0);
                    ex[lr1 * LE + gc + 1] = gelu_exact(acc[i][j][3] + bg1);
                }
            }
        }
        __syncthreads();
        if (wn == 0){
            #pragma unroll
            for (int i = 0; i < 4; i++){
                int lr0 = wm + i * 16 + g, lr1 = lr0 + 8;
                long gr0 = row0 + lr0, gr1 = row0 + lr1;
                #pragma unroll
                for (int j = 0; j < 8; j++){
                    int lc = j * 8 + 2 * tg;
                    float bu0 = bias[c0h + lc], bu1 = bias[c0h + lc + 1];
                    *(__half2*)&Gh[gr0 * ldc + c0h + lc] = __floats2half2_rn(
                        (acc[i][j][0] + bu0) * ex[lr0 * LE + lc],
                        (acc[i][j][1] + bu1) * ex[lr0 * LE + lc + 1]);
                    *(__half2*)&Gh[gr1 * ldc + c0h + lc] = __floats2half2_rn(
                        (acc[i][j][2] + bu0) * ex[lr1 * LE + lc],
                        (acc[i][j][3] + bu1) * ex[lr1 * LE + lc + 1]);
                }
            }
        }
    }
}

// ---------------- launch helpers ----------------
static void hgemm(const __half* A, const __half* W, const float* bias, const float* res,
                  float* C, int M, int N, int K, int lda, int ldb, int ldc){
    cudaFuncSetAttribute(hgemm_k<false,false>,
                         cudaFuncAttributeMaxDynamicSharedMemorySize, H_SMEM);
    dim3 g((N + 127) / 128, (M + 127) / 128, 1);
    hgemm_k<false,false><<<g, 128, H_SMEM>>>(A, W, bias, res, C, nullptr,
                                             M, N, K, lda, ldb, ldc);
}
static void hgemm_wh(const __half* A, const __half* W, const float* bias, const float* res,
                     float* C, __half* Ch, int M, int N, int K, int lda, int ldb, int ldc){
    cudaFuncSetAttribute(hgemm_k<false,true>,
                         cudaFuncAttributeMaxDynamicSharedMemorySize, H_SMEM);
    dim3 g((N + 127) / 128, (M + 127) / 128, 1);
    hgemm_k<false,true><<<g, 128, H_SMEM>>>(A, W, bias, res, C, Ch,
                                            M, N, K, lda, ldb, ldc);
}
static void hgemm_geglu(const __half* A, const __half* W1, const float* b1, __half* G){
    cudaFuncSetAttribute(hgemm_k<true,false>,
                         cudaFuncAttributeMaxDynamicSharedMemorySize, H_SMEM);
    dim3 g(2048 / 64, MM / 128, 1);
    hgemm_k<true,false><<<g, 128, H_SMEM>>>(A, W1, b1, nullptr, nullptr, G,
                                            MM, 4096, CC, CC, 4096, 2048);
}

extern "C" void kernel_launch(void* const* d_in, const int* in_sizes, int n_in,
                              void* d_out, int out_size){
    (void)in_sizes; (void)n_in; (void)out_size;
    const float* x      = (const float*)d_in[0];
    const float* cond   = (const float*)d_in[1];
    const float* gn_s   = (const float*)d_in[2];
    const float* gn_b   = (const float*)d_in[3];
    const float* pin_w  = (const float*)d_in[4];
    const float* pin_b  = (const float*)d_in[5];
    const float* pout_w = (const float*)d_in[6];
    const float* pout_b = (const float*)d_in[7];
    const float* ln1_s  = (const float*)d_in[8];
    const float* ln1_b  = (const float*)d_in[9];
    const float* sa_wq  = (const float*)d_in[10];
    const float* sa_wk  = (const float*)d_in[11];
    const float* sa_wv  = (const float*)d_in[12];
    const float* sa_wo  = (const float*)d_in[13];
    const float* sa_bo  = (const float*)d_in[14];
    const float* ln2_s  = (const float*)d_in[15];
    const float* ln2_b  = (const float*)d_in[16];
    const float* ca_wq  = (const float*)d_in[17];
    const float* ca_wk  = (const float*)d_in[18];
    const float* ca_wv  = (const float*)d_in[19];
    const float* ca_wo  = (const float*)d_in[20];
    const float* ca_bo  = (const float*)d_in[21];
    const float* ln3_s  = (const float*)d_in[22];
    const float* ln3_b  = (const float*)d_in[23];
    const float* ff_w1  = (const float*)d_in[24];
    const float* ff_b1  = (const float*)d_in[25];
    const float* ff_w2  = (const float*)d_in[26];
    const float* ff_b2  = (const float*)d_in[27];
    float* out = (float*)d_out;

    float  *p_t, *p_q, *p_k, *p_v, *p_stats;
    __half *p_tn, *p_ao, *p_gg, *p_w16;
    cudaGetSymbolAddress((void**)&p_t,    g_t);
    cudaGetSymbolAddress((void**)&p_q,    g_q);
    cudaGetSymbolAddress((void**)&p_k,    g_k);
    cudaGetSymbolAddress((void**)&p_v,    g_v);
    cudaGetSymbolAddress((void**)&p_tn,   g_tn_h);
    cudaGetSymbolAddress((void**)&p_ao,   g_ao_h);
    cudaGetSymbolAddress((void**)&p_gg,   g_gg_h);
    cudaGetSymbolAddress((void**)&p_w16,  g_w16);
    cudaGetSymbolAddress((void**)&p_stats,g_stats);

    // ---- fp16 arena layout ----
    const size_t S512 = 512 * 512, S768 = 768 * 512;
    const size_t SW1 = 512 * 4096, SW2 = 2048 * 512;
    __half* pin16  = p_w16;
    __half* pout16 = pin16 + S512;
    const size_t LSZ = 6 * S512 + 2 * S768 + SW1 + SW2;
    __half* lbase0 = pout16 + S512;
    auto LW = [&](int l){ return lbase0 + (size_t)l * LSZ; };
    __half* cond16 = lbase0 + 2 * LSZ;
    __half* p_t16  = cond16 + (size_t)BB * NCC * DCC;

    // ---- batched fp32->fp16 weight conversion ----
    {
        CvtBatch cb{};
        cb.s[0] = pin_w;  cb.d[0] = pin16;
        cb.s[1] = pout_w; cb.d[1] = pout16;
        int zi = 2;
        for (int l = 0; l < 2; l++){
            __half* b = LW(l);
            cb.s[zi] = sa_wq + (long)l * S512; cb.d[zi++] = b;
            cb.s[zi] = sa_wk + (long)l * S512; cb.d[zi++] = b + S512;
            cb.s[zi] = sa_wv + (long)l * S512; cb.d[zi++] = b + 2 * S512;
            cb.s[zi] = sa_wo + (long)l * S512; cb.d[zi++] = b + 3 * S512;
            cb.s[zi] = ca_wq + (long)l * S512; cb.d[zi++] = b + 4 * S512;
            cb.s[zi] = ca_wo + (long)l * S512; cb.d[zi++] = b + 5 * S512;
        }
        cvt_k<<<dim3((S512 / 4 + 255) / 256, 1, 14), 256>>>(cb, (int)(S512 / 4));
    }
    {
        CvtBatch cb{};
        int zi = 0;
        for (int l = 0; l < 2; l++){
            __half* b = LW(l) + 6 * S512;
            cb.s[zi] = ca_wk + (long)l * S768; cb.d[zi++] = b;
            cb.s[zi] = ca_wv + (long)l * S768; cb.d[zi++] = b + S768;
        }
        cvt_k<<<dim3((S768 / 4 + 255) / 256, 1, 4), 256>>>(cb, (int)(S768 / 4));
    }
    {
        CvtBatch cb{};
        cb.s[0] = ff_w1;       cb.d[0] = LW(0) + 6 * S512 + 2 * S768;
        cb.s[1] = ff_w1 + SW1; cb.d[1] = LW(1) + 6 * S512 + 2 * S768;
        cvt_k<<<dim3((SW1 / 4 + 255) / 256, 1, 2), 256>>>(cb, (int)(SW1 / 4));
    }
    {
        CvtBatch cb{};
        cb.s[0] = ff_w2;       cb.d[0] = LW(0) + 6 * S512 + 2 * S768 + SW1;
        cb.s[1] = ff_w2 + SW2; cb.d[1] = LW(1) + 6 * S512 + 2 * S768 + SW1;
        cvt_k<<<dim3((SW2 / 4 + 255) / 256, 1, 2), 256>>>(cb, (int)(SW2 / 4));
    }
    {
        CvtBatch cb{};
        cb.s[0] = cond; cb.d[0] = cond16;
        size_t n = (size_t)BB * NCC * DCC;
        cvt_k<<<dim3((n / 4 + 255) / 256, 1, 1), 256>>>(cb, (int)(n / 4));
    }

    // flash smem attrs (R7 config)
    constexpr int SM_SELF  = (128 * 68 + 2 * 64 * 68 + 2 * 64 * 72 + 128 * (64 + 4)) * 4;
    constexpr int SM_CROSS = (128 * 68 + 80 * 68 + 80 * 72 + 128 * (80 + 4)) * 4;
    cudaFuncSetAttribute(flash_k<64, 1024, 16, 2>,
                         cudaFuncAttributeMaxDynamicSharedMemorySize, SM_SELF);
    cudaFuncSetAttribute(flash_k<80, 77, 1, 1>,
                         cudaFuncAttributeMaxDynamicSharedMemorySize, SM_CROSS);

    gn_stats_k<<<BB * 32, 256>>>(x, p_stats);
    {
        dim3 g(SS / 32, CC / 32, BB);
        gn_apply_t_k<<<g, dim3(32, 8)>>>(x, p_stats, gn_s, gn_b, p_tn);
    }
    hgemm(p_tn, pin16, pin_b, nullptr, p_t, MM, CC, CC, CC, CC, CC);

    for (int l = 0; l < 2; l++){
        __half* b   = LW(l);
        __half* wq16  = b;
        __half* wk16  = b + S512;
        __half* wv16  = b + 2 * S512;
        __half* wo16  = b + 3 * S512;
        __half* cwq16 = b + 4 * S512;
        __half* cwo16 = b + 5 * S512;
        __half* cwk16 = b + 6 * S512;
        __half* cwv16 = b + 6 * S512 + S768;
        __half* w116  = b + 6 * S512 + 2 * S768;
        __half* w216  = w116 + SW1;
        const float* bo  = sa_bo + (long)l * CC;
        const float* cbo = ca_bo + (long)l * CC;
        const float* b1  = ff_b1 + (long)l * 4096;
        const float* b2  = ff_b2 + (long)l * CC;

        // ---- self-attention ----
        layernorm_k<<<MM, 128>>>(p_t, ln1_s + l * CC, ln1_b + l * CC, p_tn);
        hgemm(p_tn, wq16, nullptr, nullptr, p_q, MM, CC, CC, CC, CC, CC);
        hgemm(p_tn, wk16, nullptr, nullptr, p_k, MM, CC, CC, CC, CC, CC);
        hgemm(p_tn, wv16, nullptr, nullptr, p_v, MM, CC, CC, CC, CC, CC);
        flash_k<64, 1024, 16, 2><<<dim3(SS / 128, BB * NHH), 256, SM_SELF>>>(
            p_q, p_k, p_v, p_ao, (long)SS * CC);
        hgemm(p_ao, wo16, bo, p_t, p_t, MM, CC, CC, CC, CC, CC);

        // ---- cross-attention ----
        layernorm_k<<<MM, 128>>>(p_t, ln2_s + l * CC, ln2_b + l * CC, p_tn);
        hgemm(p_tn, cwq16, nullptr, nullptr, p_q, MM, CC, CC, CC, CC, CC);
        hgemm(cond16, cwk16, nullptr, nullptr, p_k, MKV, CC, DCC, DCC, CC, CC);
        hgemm(cond16, cwv16, nullptr, nullptr, p_v, MKV, CC, DCC, DCC, CC, CC);
        flash_k<80, 77, 1, 1><<<dim3(SS / 128, BB * NHH), 256, SM_CROSS>>>(
            p_q, p_k, p_v, p_ao, (long)NCC * CC);
        hgemm(p_ao, cwo16, cbo, p_t, p_t, MM, CC, CC, CC, CC, CC);

        // ---- FFN (GEGLU fused) ----
        layernorm_k<<<MM, 128>>>(p_t, ln3_s + l * CC, ln3_b + l * CC, p_tn);
        hgemm_geglu(p_tn, w116, b1, p_gg);
        if (l == 1)
            hgemm_wh(p_gg, w216, b2, p_t, p_t, p_t16, MM, CC, 2048, 2048, CC, CC);
        else
            hgemm(p_gg, w216, b2, p_t, p_t, MM, CC, 2048, 2048, CC, CC);
    }

    hgemm(p_t16, pout16, pout_b, nullptr, p_q, MM, CC, CC, CC, CC, CC);
    {
        dim3 g(SS / 32, CC / 32, BB);
        out_add_t_k<<<g, dim3(32, 8)>>>(p_q, x, out);
    }
}

// round 12
// speedup vs baseline: 1.8857x; 1.2127x over previous
#include <cuda_runtime.h>
#include <cuda_fp16.h>
#include <math.h>
#include <stdint.h>

// ---------------- problem constants ----------------
constexpr int BB   = 8;
constexpr int CC   = 512;
constexpr int SS   = 1024;
constexpr int NHH  = 8;
constexpr int DHH  = 64;
constexpr int NCC  = 77;
constexpr int DCC  = 768;
constexpr int MM   = BB * SS;  // 8192
constexpr int MKV  = BB * NCC; // 616

// ---------------- scratch ----------------
__device__ __align__(256) float  g_t    [ (long)MM * CC ];     // fp32 residual
__device__ __align__(256) float  g_q    [ (long)MM * CC ];     // reused as fp16 QKV
__device__ __align__(256) float  g_k    [ (long)MM * CC ];
__device__ __align__(256) float  g_v    [ (long)MM * CC ];
__device__ __align__(256) __half g_tn_h [ (long)MM * CC ];     // LN/GN outputs (fp16)
__device__ __align__(256) __half g_ao_h [ (long)MM * CC ];     // flash output (fp16)
__device__ __align__(256) __half g_gg_h [ (long)MM * 2048 ];   // GEGLU output (fp16)
__device__ __align__(256) __half g_w16  [ 16252928 ];          // fp16 arena
__device__ __align__(256) float  g_stats[ 2 * BB * 32 ];

// ---------------- reductions ----------------
__inline__ __device__ float warpSum(float v){
    #pragma unroll
    for (int o = 16; o > 0; o >>= 1) v += __shfl_xor_sync(0xffffffffu, v, o);
    return v;
}

// ---------------- cp.async ----------------
__device__ __forceinline__ uint32_t smem_u32(const void* p){
    return (uint32_t)__cvta_generic_to_shared(p);
}
__device__ __forceinline__ void cp16a(uint32_t dst, const void* src, int bytes){
    asm volatile("cp.async.cg.shared.global [%0], [%1], 16, %2;\n"
                 :: "r"(dst), "l"(src), "r"(bytes));
}
__device__ __forceinline__ void cp_commit(){ asm volatile("cp.async.commit_group;\n"); }
template<int N> __device__ __forceinline__ void cp_wait(){
    asm volatile("cp.async.wait_group %0;\n" :: "n"(N));
}

// ---------------- ldmatrix / mma fp16 ----------------
__device__ __forceinline__ void ldsm_x4(uint32_t* r, uint32_t addr){
    asm volatile("ldmatrix.sync.aligned.m8n8.x4.shared.b16 {%0,%1,%2,%3}, [%4];"
        : "=r"(r[0]), "=r"(r[1]), "=r"(r[2]), "=r"(r[3]) : "r"(addr));
}
__device__ __forceinline__ void ldsm_x4_t(uint32_t* r, uint32_t addr){
    asm volatile("ldmatrix.sync.aligned.m8n8.x4.trans.shared.b16 {%0,%1,%2,%3}, [%4];"
        : "=r"(r[0]), "=r"(r[1]), "=r"(r[2]), "=r"(r[3]) : "r"(addr));
}
__device__ __forceinline__ void mma_f16(float* c, const uint32_t* a, const uint32_t* b){
    asm volatile("mma.sync.aligned.m16n8k16.row.col.f32.f16.f16.f32 "
        "{%0,%1,%2,%3}, {%4,%5,%6,%7}, {%8,%9}, {%0,%1,%2,%3};"
        : "+f"(c[0]), "+f"(c[1]), "+f"(c[2]), "+f"(c[3])
        : "r"(a[0]), "r"(a[1]), "r"(a[2]), "r"(a[3]), "r"(b[0]), "r"(b[1]));
}
__device__ __forceinline__ uint32_t h2u(float a, float b){
    __half2 h = __floats2half2_rn(a, b);
    return *(uint32_t*)&h;
}

__inline__ __device__ float gelu_exact(float x){
    return 0.5f * x * (1.f + erff(x * 0.70710678118654752f));
}

// ---------------- fp32 -> fp16 batched convert ----------------
struct CvtBatch { const float* s[16]; __half* d[16]; };
__global__ void cvt_k(CvtBatch cb, int n4){
    const float4* s = (const float4*)cb.s[blockIdx.z];
    __half2* d = (__half2*)cb.d[blockIdx.z];
    int i = blockIdx.x * blockDim.x + threadIdx.x;
    if (i >= n4) return;
    float4 v = s[i];
    d[2 * i]     = __floats2half2_rn(v.x, v.y);
    d[2 * i + 1] = __floats2half2_rn(v.z, v.w);
}

// ---------------- groupnorm stats ----------------
__global__ void gn_stats_k(const float* __restrict__ x, float* __restrict__ stats){
    long base = (long)blockIdx.x * 16384;
    float s = 0.f, q = 0.f;
    for (int i = threadIdx.x; i < 16384; i += blockDim.x){
        float v = x[base + i];
        s += v; q += v * v;
    }
    __shared__ float shs[8], shq[8];
    s = warpSum(s); q = warpSum(q);
    int w = threadIdx.x >> 5, l = threadIdx.x & 31;
    if (l == 0){ shs[w] = s; shq[w] = q; }
    __syncthreads();
    if (threadIdx.x < 32){
        s = (l < 8) ? shs[l] : 0.f;
        q = (l < 8) ? shq[l] : 0.f;
        s = warpSum(s); q = warpSum(q);
        if (l == 0){
            float mean = s * (1.f / 16384.f);
            float var  = q * (1.f / 16384.f) - mean * mean;
            stats[2 * blockIdx.x]     = mean;
            stats[2 * blockIdx.x + 1] = rsqrtf(var + 1e-6f);
        }
    }
}

// ---------------- groupnorm apply + transpose (fp16 out) ----------------
__global__ void gn_apply_t_k(const float* __restrict__ x, const float* __restrict__ stats,
                             const float* __restrict__ gs, const float* __restrict__ gb,
                             __half* __restrict__ out){
    __shared__ float tile[32][33];
    int b = blockIdx.z, c0 = blockIdx.y * 32, p0 = blockIdx.x * 32;
    int tx = threadIdx.x, ty = threadIdx.y;
    #pragma unroll
    for (int r = 0; r < 4; r++){
        int c = c0 + ty + r * 8;
        float v = x[((long)b * CC + c) * SS + p0 + tx];
        int grp = b * 32 + (c >> 4);
        v = (v - stats[2 * grp]) * stats[2 * grp + 1] * gs[c] + gb[c];
        tile[ty + r * 8][tx] = v;
    }
    __syncthreads();
    #pragma unroll
    for (int r = 0; r < 4; r++){
        int p = p0 + ty + r * 8;
        out[((long)b * SS + p) * CC + c0 + tx] = __float2half(tile[tx][ty + r * 8]);
    }
}

// ---------------- final transpose + x_in residual ----------------
__global__ void out_add_t_k(const float* __restrict__ z, const float* __restrict__ x,
                            float* __restrict__ out){
    __shared__ float tile[32][33];
    int b = blockIdx.z, c0 = blockIdx.y * 32, p0 = blockIdx.x * 32;
    int tx = threadIdx.x, ty = threadIdx.y;
    #pragma unroll
    for (int r = 0; r < 4; r++){
        int p = p0 + ty + r * 8;
        tile[ty + r * 8][tx] = z[((long)b * SS + p) * CC + c0 + tx];
    }
    __syncthreads();
    #pragma unroll
    for (int r = 0; r < 4; r++){
        int c = c0 + ty + r * 8;
        long o = ((long)b * CC + c) * SS + p0 + tx;
        out[o] = tile[tx][ty + r * 8] + x[o];
    }
}

// ---------------- layernorm (fp32 in, fp16 out) ----------------
__global__ void layernorm_k(const float* __restrict__ in, const float* __restrict__ sc,
                            const float* __restrict__ bi, __half* __restrict__ out){
    long row = blockIdx.x;
    const float4* x4 = (const float4*)(in + row * CC);
    float4 xv = x4[threadIdx.x];
    float s = xv.x + xv.y + xv.z + xv.w;
    float q = xv.x*xv.x + xv.y*xv.y + xv.z*xv.z + xv.w*xv.w;
    __shared__ float shs[4], shq[4];
    s = warpSum(s); q = warpSum(q);
    int w = threadIdx.x >> 5, l = threadIdx.x & 31;
    if (l == 0){ shs[w] = s; shq[w] = q; }
    __syncthreads();
    if (threadIdx.x < 32){
        float a = (l < 4) ? shs[l] : 0.f;
        float b2 = (l < 4) ? shq[l] : 0.f;
        a = warpSum(a); b2 = warpSum(b2);
        if (l == 0){ shs[0] = a; shq[0] = b2; }
    }
    __syncthreads();
    float mean = shs[0] * (1.f / 512.f);
    float rstd = rsqrtf(shq[0] * (1.f / 512.f) - mean * mean + 1e-5f);
    float4 sv = ((const float4*)sc)[threadIdx.x];
    float4 bv = ((const float4*)bi)[threadIdx.x];
    __half2* o2 = (__half2*)(out + row * CC);
    o2[2 * threadIdx.x]     = __floats2half2_rn((xv.x - mean) * rstd * sv.x + bv.x,
                                                (xv.y - mean) * rstd * sv.y + bv.y);
    o2[2 * threadIdx.x + 1] = __floats2half2_rn((xv.z - mean) * rstd * sv.z + bv.z,
                                                (xv.w - mean) * rstd * sv.w + bv.w);
}

// =====================================================================
// fp16 flash attention (mma.m16n8k16, online softmax, register P).
// 256 thr = 8 warps x 16 q-rows = 128 q-rows/block.
// Q/K/V fp16 [row, 512], head slice 64 halves (128 B) per row.
// S = Q.K^T : K smem rows are n -> NON-trans ldmatrix gives B frag.
// P.V      : V smem rows are k -> trans ldmatrix (same as hgemm B).
// P stays in registers (S acc C-layout == next mma A-layout).
// =====================================================================
template<int TKV, int KVLEN, int NTILES, int NSTAGE>
__global__ void flash16_k(const __half* __restrict__ Q, const __half* __restrict__ K,
                          const __half* __restrict__ V, __half* __restrict__ O,
                          long kv_bstride){
    constexpr int NT = TKV / 8;
    constexpr int LH = 72;                       // halves per smem row (144 B)
    extern __shared__ char smraw[];
    __half* Qs = (__half*)smraw;                 // 128*LH
    __half* Ks = Qs + 128 * LH;                  // NSTAGE*TKV*LH
    __half* Vs = Ks + NSTAGE * TKV * LH;

    int tid = threadIdx.x;
    int w = tid >> 5, lane = tid & 31;
    int g = lane >> 2, tg = lane & 3;
    int lt = lane >> 3, lr = lane & 7;
    int qt = blockIdx.x;
    int b = blockIdx.y / NHH, h = blockIdx.y % NHH;

    const __half* Qb = Q + ((long)(b * SS + qt * 128)) * CC + h * DHH;
    const __half* Kb = K + (long)b * kv_bstride + h * DHH;
    const __half* Vb = V + (long)b * kv_bstride + h * DHH;

    uint32_t sQ = smem_u32(Qs), sK = smem_u32(Ks), sV = smem_u32(Vs);

    // ldmatrix lane offsets (halves)
    uint32_t a_ln  = (uint32_t)(((lt & 1) * 8 + lr) * LH + (lt >> 1) * 8);  // Q rows m
    uint32_t nk_ln = (uint32_t)(((lt >> 1) * 8 + lr) * LH + (lt & 1) * 8);  // K rows n
    uint32_t vt_ln = (uint32_t)(((lt & 1) * 8 + lr) * LH + (lt >> 1) * 8);  // V rows k (trans)

    auto loadQ = [&](){
        #pragma unroll
        for (int i = 0; i < 4; i++){             // 128 rows * 8 chunks / 256 thr
            int c = tid + i * 256;
            int row = c >> 3, kc = (c & 7) * 8;
            cp16a(sQ + (uint32_t)(row * LH + kc) * 2, Qb + (long)row * CC + kc, 16);
        }
    };
    auto loadKV = [&](int s, int t){
        constexpr int CH = TKV * 8;
        #pragma unroll
        for (int i = 0; i < (CH + 255) / 256; i++){
            int c = tid + i * 256;
            if (c < CH){
                int row = c >> 3, kc = (c & 7) * 8;
                int r = t * TKV + row;
                int by = (r < KVLEN) ? 16 : 0;
                const __half* ks = by ? (Kb + (long)r * CC + kc) : Kb;
                const __half* vs = by ? (Vb + (long)r * CC + kc) : Vb;
                cp16a(sK + (uint32_t)((s * TKV + row) * LH + kc) * 2, ks, by);
                cp16a(sV + (uint32_t)((s * TKV + row) * LH + kc) * 2, vs, by);
            }
        }
    };

    loadQ(); loadKV(0, 0); cp_commit();
    if (NTILES > 1){ loadKV(1, 1); cp_commit(); }

    uint32_t qa[4][4];
    float oacc[8][4];
    #pragma unroll
    for (int j = 0; j < 8; j++)
        #pragma unroll
        for (int r = 0; r < 4; r++) oacc[j][r] = 0.f;
    float m0 = -1e30f, m1 = -1e30f, l0 = 0.f, l1 = 0.f;

    for (int t = 0; t < NTILES; t++){
        if (t + 1 < NTILES) cp_wait<1>(); else cp_wait<0>();
        __syncthreads();
        if (t == 0){
            uint32_t qbase = sQ + (uint32_t)(w * 16 * LH) * 2;
            #pragma unroll
            for (int ks = 0; ks < 4; ks++)
                ldsm_x4(qa[ks], qbase + (a_ln + ks * 16) * 2);
        }
        uint32_t kbase = sK + (uint32_t)((t % NSTAGE) * TKV * LH) * 2;
        uint32_t vbase = sV + (uint32_t)((t % NSTAGE) * TKV * LH) * 2;

        // ---- S = Q K^T ----
        float sacc[NT][4];
        #pragma unroll
        for (int j = 0; j < NT; j++)
            #pragma unroll
            for (int r = 0; r < 4; r++) sacc[j][r] = 0.f;
        #pragma unroll
        for (int ks = 0; ks < 4; ks++){
            #pragma unroll
            for (int jp = 0; jp < NT / 2; jp++){
                uint32_t kb[4];
                ldsm_x4(kb, kbase + (uint32_t)(jp * 16 * LH) * 2 + (nk_ln + ks * 16) * 2);
                mma_f16(sacc[2 * jp    ], qa[ks], kb);
                mma_f16(sacc[2 * jp + 1], qa[ks], kb + 2);
            }
        }
        // ---- mask ragged last tile ----
        if (KVLEN < NTILES * TKV && t == NTILES - 1){
            #pragma unroll
            for (int j = 0; j < NT; j++){
                int col = t * TKV + j * 8 + 2 * tg;
                if (col     >= KVLEN){ sacc[j][0] = -1e30f; sacc[j][2] = -1e30f; }
                if (col + 1 >= KVLEN){ sacc[j][1] = -1e30f; sacc[j][3] = -1e30f; }
            }
        }
        // ---- online softmax (fp32) ----
        float rm0 = -1e30f, rm1 = -1e30f;
        #pragma unroll
        for (int j = 0; j < NT; j++){
            rm0 = fmaxf(rm0, fmaxf(sacc[j][0], sacc[j][1]));
            rm1 = fmaxf(rm1, fmaxf(sacc[j][2], sacc[j][3]));
        }
        rm0 = fmaxf(rm0, __shfl_xor_sync(0xffffffffu, rm0, 1));
        rm0 = fmaxf(rm0, __shfl_xor_sync(0xffffffffu, rm0, 2));
        rm1 = fmaxf(rm1, __shfl_xor_sync(0xffffffffu, rm1, 1));
        rm1 = fmaxf(rm1, __shfl_xor_sync(0xffffffffu, rm1, 2));
        float mn0 = fmaxf(m0, rm0), mn1 = fmaxf(m1, rm1);
        float a0 = __expf(m0 - mn0), a1 = __expf(m1 - mn1);
        float rs0 = 0.f, rs1 = 0.f;
        #pragma unroll
        for (int j = 0; j < NT; j++){
            sacc[j][0] = __expf(sacc[j][0] - mn0);
            sacc[j][1] = __expf(sacc[j][1] - mn0);
            sacc[j][2] = __expf(sacc[j][2] - mn1);
            sacc[j][3] = __expf(sacc[j][3] - mn1);
            rs0 += sacc[j][0] + sacc[j][1];
            rs1 += sacc[j][2] + sacc[j][3];
        }
        rs0 += __shfl_xor_sync(0xffffffffu, rs0, 1);
        rs0 += __shfl_xor_sync(0xffffffffu, rs0, 2);
        rs1 += __shfl_xor_sync(0xffffffffu, rs1, 1);
        rs1 += __shfl_xor_sync(0xffffffffu, rs1, 2);
        l0 = l0 * a0 + rs0;  l1 = l1 * a1 + rs1;
        m0 = mn0;  m1 = mn1;
        #pragma unroll
        for (int jn = 0; jn < 8; jn++){
            oacc[jn][0] *= a0; oacc[jn][1] *= a0;
            oacc[jn][2] *= a1; oacc[jn][3] *= a1;
        }
        // ---- O += P V  (P built in registers from S accs) ----
        #pragma unroll
        for (int ks = 0; ks < TKV / 16; ks++){
            uint32_t pa[4];
            pa[0] = h2u(sacc[2 * ks    ][0], sacc[2 * ks    ][1]);
            pa[1] = h2u(sacc[2 * ks    ][2], sacc[2 * ks    ][3]);
            pa[2] = h2u(sacc[2 * ks + 1][0], sacc[2 * ks + 1][1]);
            pa[3] = h2u(sacc[2 * ks + 1][2], sacc[2 * ks + 1][3]);
            #pragma unroll
            for (int jp = 0; jp < 4; jp++){
                uint32_t vb[4];
                ldsm_x4_t(vb, vbase + (uint32_t)(ks * 16 * LH) * 2
                              + (vt_ln + jp * 16) * 2);
                mma_f16(oacc[2 * jp    ], pa, vb);
                mma_f16(oacc[2 * jp + 1], pa, vb + 2);
            }
        }
        __syncthreads();
        if (t + 2 < NTILES) loadKV(t % 2, t + 2);
        cp_commit();
    }

    float inv0 = 1.f / l0, inv1 = 1.f / l1;
    __half* Ob = O + ((long)(b * SS + qt * 128 + w * 16)) * CC + h * DHH;
    #pragma unroll
    for (int jn = 0; jn < 8; jn++){
        int col = jn * 8 + 2 * tg;
        *(__half2*)&Ob[(long)(g    ) * CC + col] =
            __floats2half2_rn(oacc[jn][0] * inv0, oacc[jn][1] * inv0);
        *(__half2*)&Ob[(long)(g + 8) * CC + col] =
            __floats2half2_rn(oacc[jn][2] * inv1, oacc[jn][3] * inv1);
    }
}

// =====================================================================
// fp16 NN GEMM (R11, passing) with OUT: 0=fp32 C(+res), 1=fp16 only, 2=both.
// =====================================================================
constexpr int HLA = 72;
constexpr int HLB = 136;
constexpr int HAW = 128 * HLA * 2;
constexpr int HBW = 64 * HLB * 2;
constexpr int H_SMEM = 3 * (HAW + HBW);

template<bool GEGLU, int OUT>
__global__ void hgemm_k(const __half* __restrict__ A, const __half* __restrict__ Bm,
                        const float* __restrict__ bias, const float* __restrict__ res,
                        float* __restrict__ C, __half* __restrict__ Gh,
                        int M, int N, int K, int lda, int ldb, int ldc){
    constexpr int BK = 64, STAGES = 3;
    extern __shared__ float smf[];
    uint32_t sb = smem_u32(smf);
    uint32_t Abase = sb;
    uint32_t Bbase = sb + 3 * HAW;

    int tid  = threadIdx.x;
    int warp = tid >> 5, lane = tid & 31;
    int g  = lane >> 2;
    int tg = lane & 3;
    int wm = (warp & 1) * 64;
    int wn = (warp >> 1) * 64;
    int row0 = blockIdx.y * 128;
    int col0 = GEGLU ? 0 : blockIdx.x * 128;
    int c0h  = blockIdx.x * 64;

    int lt = lane >> 3, lr = lane & 7;
    uint32_t a_lane = (uint32_t)(((lt & 1) * 8 + lr) * HLA + (lt >> 1) * 8) * 2;
    uint32_t b_lane = (uint32_t)(((lt & 1) * 8 + lr) * HLB + (lt >> 1) * 8) * 2;

    float acc[4][8][4];
    #pragma unroll
    for (int i = 0; i < 4; i++)
        #pragma unroll
        for (int j = 0; j < 8; j++)
            #pragma unroll
            for (int r = 0; r < 4; r++) acc[i][j][r] = 0.f;

    auto loadA = [&](int s, int kt){
        uint32_t base = Abase + s * HAW;
        #pragma unroll
        for (int it = 0; it < 8; it++){
            int c = tid + it * 128;
            int m  = c >> 3;
            int kc = (c & 7) * 8;
            int gm = row0 + m;
            int by = (gm < M) ? 16 : 0;
            const __half* src = by ? (A + (long)gm * lda + kt + kc) : A;
            cp16a(base + (uint32_t)(m * HLA + kc) * 2, src, by);
        }
    };
    auto loadB = [&](int s, int kt){
        uint32_t base = Bbase + s * HBW;
        #pragma unroll
        for (int it = 0; it < 8; it++){
            int c = tid + it * 128;
            int kr = c >> 4;
            int nc = (c & 15) * 8;
            int gk = kt + kr;
            long gn;
            if (GEGLU) gn = (nc < 64) ? (long)(c0h + nc) : (long)(2048 + c0h + nc - 64);
            else       gn = (long)(col0 + nc);
            int by = (gk < K) ? 16 : 0;
            const __half* src = by ? (Bm + (long)gk * ldb + gn) : Bm;
            cp16a(base + (uint32_t)(kr * HLB + nc) * 2, src, by);
        }
    };
    auto compute = [&](int s){
        uint32_t Ab = Abase + s * HAW;
        uint32_t Bb = Bbase + s * HBW;
        #pragma unroll
        for (int ks = 0; ks < 4; ks++){
            uint32_t bf[8][2];
            #pragma unroll
            for (int jp = 0; jp < 4; jp++){
                uint32_t r[4];
                ldsm_x4_t(r, Bb + b_lane +
                          (uint32_t)(ks * 16 * HLB + wn + jp * 16) * 2);
                bf[2*jp  ][0] = r[0]; bf[2*jp  ][1] = r[1];
                bf[2*jp+1][0] = r[2]; bf[2*jp+1][1] = r[3];
            }
            #pragma unroll
            for (int i = 0; i < 4; i++){
                uint32_t af[4];
                ldsm_x4(af, Ab + a_lane +
                        (uint32_t)((wm + i * 16) * HLA + ks * 16) * 2);
                #pragma unroll
                for (int j = 0; j < 8; j++)
                    mma_f16(acc[i][j], af, bf[j]);
            }
        }
    };

    int nk = (K + BK - 1) / BK;
    #pragma unroll
    for (int s = 0; s < STAGES - 1; s++){
        if (s < nk){ loadA(s, s * BK); loadB(s, s * BK); }
        cp_commit();
    }
    for (int t = 0; t < nk; t++){
        cp_wait<STAGES - 2>();
        __syncthreads();
        int tn = t + STAGES - 1;
        if (tn < nk){ loadA(tn % STAGES, tn * BK); loadB(tn % STAGES, tn * BK); }
        cp_commit();
        compute(t % STAGES);
    }

    if (!GEGLU){
        #pragma unroll
        for (int i = 0; i < 4; i++){
            int r0 = row0 + wm + i * 16 + g;
            int r1 = r0 + 8;
            #pragma unroll
            for (int j = 0; j < 8; j++){
                int c0 = col0 + wn + j * 8 + 2 * tg;
                float* a4 = acc[i][j];
                float b0 = 0.f, b1v = 0.f;
                if (bias){ b0 = bias[c0]; b1v = bias[c0 + 1]; }
                if (r0 < M){
                    float2 v = {a4[0] + b0, a4[1] + b1v};
                    if (res){
                        float2 rr = *(const float2*)&res[(long)r0 * ldc + c0];
                        v.x += rr.x; v.y += rr.y;
                    }
                    if (OUT != 1) *(float2*)&C[(long)r0 * ldc + c0] = v;
                    if (OUT != 0) *(__half2*)&Gh[(long)r0 * ldc + c0] = __floats2half2_rn(v.x, v.y);
                }
                if (r1 < M){
                    float2 v = {a4[2] + b0, a4[3] + b1v};
                    if (res){
                        float2 rr = *(const float2*)&res[(long)r1 * ldc + c0];
                        v.x += rr.x; v.y += rr.y;
                    }
                    if (OUT != 1) *(float2*)&C[(long)r1 * ldc + c0] = v;
                    if (OUT != 0) *(__half2*)&Gh[(long)r1 * ldc + c0] = __floats2half2_rn(v.x, v.y);
                }
            }
        }
    } else {
        constexpr int LE = 68;
        float* ex = smf;
        __syncthreads();
        if (wn == 64){
            #pragma unroll
            for (int i = 0; i < 4; i++){
                int lr0 = wm + i * 16 + g, lr1 = lr0 + 8;
                #pragma unroll
                for (int j = 0; j < 8; j++){
                    int gc = j * 8 + 2 * tg;
                    float bg0 = bias[c0h + gc + 2048];
                    float bg1 = bias[c0h + gc + 1 + 2048];
                    ex[lr0 * LE + gc    ] = gelu_exact(acc[i][j][0] + bg0);
                    ex[lr0 * LE + gc + 1] = gelu_exact(acc[i][j][1] + bg1);
                    ex[lr1 * LE + gc    ] = gelu_exact(acc[i][j][2] + bg0);
                    ex[lr1 * LE + gc + 1] = gelu_exact(acc[i][j][3] + bg1);
                }
            }
        }
        __syncthreads();
        if (wn == 0){
            #pragma unroll
            for (int i = 0; i < 4; i++){
                int lr0 = wm + i * 16 + g, lr1 = lr0 + 8;
                long gr0 = row0 + lr0, gr1 = row0 + lr1;
                #pragma unroll
                for (int j = 0; j < 8; j++){
                    int lc = j * 8 + 2 * tg;
                    float bu0 = bias[c0h + lc], bu1 = bias[c0h + lc + 1];
                    *(__half2*)&Gh[gr0 * ldc + c0h + lc] = __floats2half2_rn(
                        (acc[i][j][0] + bu0) * ex[lr0 * LE + lc],
                        (acc[i][j][1] + bu1) * ex[lr0 * LE + lc + 1]);
                    *(__half2*)&Gh[gr1 * ldc + c0h + lc] = __floats2half2_rn(
                        (acc[i][j][2] + bu0) * ex[lr1 * LE + lc],
                        (acc[i][j][3] + bu1) * ex[lr1 * LE + lc + 1]);
                }
            }
        }
    }
}

// ---------------- launch helpers ----------------
static void hgemm(const __half* A, const __half* W, const float* bias, const float* res,
                  float* C, int M, int N, int K, int lda, int ldb, int ldc){
    cudaFuncSetAttribute(hgemm_k<false,0>,
                         cudaFuncAttributeMaxDynamicSharedMemorySize, H_SMEM);
    dim3 g((N + 127) / 128, (M + 127) / 128, 1);
    hgemm_k<false,0><<<g, 128, H_SMEM>>>(A, W, bias, res, C, nullptr,
                                         M, N, K, lda, ldb, ldc);
}
static void hgemm_h16(const __half* A, const __half* W, __half* Ch,
                      int M, int N, int K, int lda, int ldb, int ldc){
    cudaFuncSetAttribute(hgemm_k<false,1>,
                         cudaFuncAttributeMaxDynamicSharedMemorySize, H_SMEM);
    dim3 g((N + 127) / 128, (M + 127) / 128, 1);
    hgemm_k<false,1><<<g, 128, H_SMEM>>>(A, W, nullptr, nullptr, nullptr, Ch,
                                         M, N, K, lda, ldb, ldc);
}
static void hgemm_wh(const __half* A, const __half* W, const float* bias, const float* res,
                     float* C, __half* Ch, int M, int N, int K, int lda, int ldb, int ldc){
    cudaFuncSetAttribute(hgemm_k<false,2>,
                         cudaFuncAttributeMaxDynamicSharedMemorySize, H_SMEM);
    dim3 g((N + 127) / 128, (M + 127) / 128, 1);
    hgemm_k<false,2><<<g, 128, H_SMEM>>>(A, W, bias, res, C, Ch,
                                         M, N, K, lda, ldb, ldc);
}
static void hgemm_geglu(const __half* A, const __half* W1, const float* b1, __half* G){
    cudaFuncSetAttribute(hgemm_k<true,0>,
                         cudaFuncAttributeMaxDynamicSharedMemorySize, H_SMEM);
    dim3 g(2048 / 64, MM / 128, 1);
    hgemm_k<true,0><<<g, 128, H_SMEM>>>(A, W1, b1, nullptr, nullptr, G,
                                        MM, 4096, CC, CC, 4096, 2048);
}

extern "C" void kernel_launch(void* const* d_in, const int* in_sizes, int n_in,
                              void* d_out, int out_size){
    (void)in_sizes; (void)n_in; (void)out_size;
    const float* x      = (const float*)d_in[0];
    const float* cond   = (const float*)d_in[1];
    const float* gn_s   = (const float*)d_in[2];
    const float* gn_b   = (const float*)d_in[3];
    const float* pin_w  = (const float*)d_in[4];
    const float* pin_b  = (const float*)d_in[5];
    const float* pout_w = (const float*)d_in[6];
    const float* pout_b = (const float*)d_in[7];
    const float* ln1_s  = (const float*)d_in[8];
    const float* ln1_b  = (const float*)d_in[9];
    const float* sa_wq  = (const float*)d_in[10];
    const float* sa_wk  = (const float*)d_in[11];
    const float* sa_wv  = (const float*)d_in[12];
    const float* sa_wo  = (const float*)d_in[13];
    const float* sa_bo  = (const float*)d_in[14];
    const float* ln2_s  = (const float*)d_in[15];
    const float* ln2_b  = (const float*)d_in[16];
    const float* ca_wq  = (const float*)d_in[17];
    const float* ca_wk  = (const float*)d_in[18];
    const float* ca_wv  = (const float*)d_in[19];
    const float* ca_wo  = (const float*)d_in[20];
    const float* ca_bo  = (const float*)d_in[21];
    const float* ln3_s  = (const float*)d_in[22];
    const float* ln3_b  = (const float*)d_in[23];
    const float* ff_w1  = (const float*)d_in[24];
    const float* ff_b1  = (const float*)d_in[25];
    const float* ff_w2  = (const float*)d_in[26];
    const float* ff_b2  = (const float*)d_in[27];
    float* out = (float*)d_out;

    float  *p_t, *p_qf, *p_kf, *p_vf, *p_stats;
    __half *p_tn, *p_ao, *p_gg, *p_w16;
    cudaGetSymbolAddress((void**)&p_t,    g_t);
    cudaGetSymbolAddress((void**)&p_qf,   g_q);
    cudaGetSymbolAddress((void**)&p_kf,   g_k);
    cudaGetSymbolAddress((void**)&p_vf,   g_v);
    cudaGetSymbolAddress((void**)&p_tn,   g_tn_h);
    cudaGetSymbolAddress((void**)&p_ao,   g_ao_h);
    cudaGetSymbolAddress((void**)&p_gg,   g_gg_h);
    cudaGetSymbolAddress((void**)&p_w16,  g_w16);
    cudaGetSymbolAddress((void**)&p_stats,g_stats);
    __half* p_q16 = (__half*)p_qf;
    __half* p_k16 = (__half*)p_kf;
    __half* p_v16 = (__half*)p_vf;

    // ---- fp16 arena layout ----
    const size_t S512 = 512 * 512, S768 = 768 * 512;
    const size_t SW1 = 512 * 4096, SW2 = 2048 * 512;
    __half* pin16  = p_w16;
    __half* pout16 = pin16 + S512;
    const size_t LSZ = 6 * S512 + 2 * S768 + SW1 + SW2;
    __half* lbase0 = pout16 + S512;
    auto LW = [&](int l){ return lbase0 + (size_t)l * LSZ; };
    __half* cond16 = lbase0 + 2 * LSZ;
    __half* p_t16  = cond16 + (size_t)BB * NCC * DCC;

    // ---- batched fp32->fp16 weight conversion ----
    {
        CvtBatch cb{};
        cb.s[0] = pin_w;  cb.d[0] = pin16;
        cb.s[1] = pout_w; cb.d[1] = pout16;
        int zi = 2;
        for (int l = 0; l < 2; l++){
            __half* b = LW(l);
            cb.s[zi] = sa_wq + (long)l * S512; cb.d[zi++] = b;
            cb.s[zi] = sa_wk + (long)l * S512; cb.d[zi++] = b + S512;
            cb.s[zi] = sa_wv + (long)l * S512; cb.d[zi++] = b + 2 * S512;
            cb.s[zi] = sa_wo + (long)l * S512; cb.d[zi++] = b + 3 * S512;
            cb.s[zi] = ca_wq + (long)l * S512; cb.d[zi++] = b + 4 * S512;
            cb.s[zi] = ca_wo + (long)l * S512; cb.d[zi++] = b + 5 * S512;
        }
        cvt_k<<<dim3((S512 / 4 + 255) / 256, 1, 14), 256>>>(cb, (int)(S512 / 4));
    }
    {
        CvtBatch cb{};
        int zi = 0;
        for (int l = 0; l < 2; l++){
            __half* b = LW(l) + 6 * S512;
            cb.s[zi] = ca_wk + (long)l * S768; cb.d[zi++] = b;
            cb.s[zi] = ca_wv + (long)l * S768; cb.d[zi++] = b + S768;
        }
        cvt_k<<<dim3((S768 / 4 + 255) / 256, 1, 4), 256>>>(cb, (int)(S768 / 4));
    }
    {
        CvtBatch cb{};
        cb.s[0] = ff_w1;       cb.d[0] = LW(0) + 6 * S512 + 2 * S768;
        cb.s[1] = ff_w1 + SW1; cb.d[1] = LW(1) + 6 * S512 + 2 * S768;
        cvt_k<<<dim3((SW1 / 4 + 255) / 256, 1, 2), 256>>>(cb, (int)(SW1 / 4));
    }
    {
        CvtBatch cb{};
        cb.s[0] = ff_w2;       cb.d[0] = LW(0) + 6 * S512 + 2 * S768 + SW1;
        cb.s[1] = ff_w2 + SW2; cb.d[1] = LW(1) + 6 * S512 + 2 * S768 + SW1;
        cvt_k<<<dim3((SW2 / 4 + 255) / 256, 1, 2), 256>>>(cb, (int)(SW2 / 4));
    }
    {
        CvtBatch cb{};
        cb.s[0] = cond; cb.d[0] = cond16;
        size_t n = (size_t)BB * NCC * DCC;
        cvt_k<<<dim3((n / 4 + 255) / 256, 1, 1), 256>>>(cb, (int)(n / 4));
    }

    // flash smem (bytes): (128 + 2*NSTAGE*TKV) rows * 72 halves * 2
    constexpr int SM_SELF16  = (128 * 72 + 2 * 64 * 72 + 2 * 64 * 72) * 2;   // 55,296
    constexpr int SM_CROSS16 = (128 * 72 + 80 * 72 + 80 * 72) * 2;           // 41,472
    cudaFuncSetAttribute(flash16_k<64, 1024, 16, 2>,
                         cudaFuncAttributeMaxDynamicSharedMemorySize, SM_SELF16);
    cudaFuncSetAttribute(flash16_k<80, 77, 1, 1>,
                         cudaFuncAttributeMaxDynamicSharedMemorySize, SM_CROSS16);

    gn_stats_k<<<BB * 32, 256>>>(x, p_stats);
    {
        dim3 g(SS / 32, CC / 32, BB);
        gn_apply_t_k<<<g, dim3(32, 8)>>>(x, p_stats, gn_s, gn_b, p_tn);
    }
    hgemm(p_tn, pin16, pin_b, nullptr, p_t, MM, CC, CC, CC, CC, CC);

    for (int l = 0; l < 2; l++){
        __half* b   = LW(l);
        __half* wq16  = b;
        __half* wk16  = b + S512;
        __half* wv16  = b + 2 * S512;
        __half* wo16  = b + 3 * S512;
        __half* cwq16 = b + 4 * S512;
        __half* cwo16 = b + 5 * S512;
        __half* cwk16 = b + 6 * S512;
        __half* cwv16 = b + 6 * S512 + S768;
        __half* w116  = b + 6 * S512 + 2 * S768;
        __half* w216  = w116 + SW1;
        const float* bo  = sa_bo + (long)l * CC;
        const float* cbo = ca_bo + (long)l * CC;
        const float* b1  = ff_b1 + (long)l * 4096;
        const float* b2  = ff_b2 + (long)l * CC;

        // ---- self-attention (fp16 QKV -> fp16 flash) ----
        layernorm_k<<<MM, 128>>>(p_t, ln1_s + l * CC, ln1_b + l * CC, p_tn);
        hgemm_h16(p_tn, wq16, p_q16, MM, CC, CC, CC, CC, CC);
        hgemm_h16(p_tn, wk16, p_k16, MM, CC, CC, CC, CC, CC);
        hgemm_h16(p_tn, wv16, p_v16, MM, CC, CC, CC, CC, CC);
        flash16_k<64, 1024, 16, 2><<<dim3(SS / 128, BB * NHH), 256, SM_SELF16>>>(
            p_q16, p_k16, p_v16, p_ao, (long)SS * CC);
        hgemm(p_ao, wo16, bo, p_t, p_t, MM, CC, CC, CC, CC, CC);

        // ---- cross-attention ----
        layernorm_k<<<MM, 128>>>(p_t, ln2_s + l * CC, ln2_b + l * CC, p_tn);
        hgemm_h16(p_tn, cwq16, p_q16, MM, CC, CC, CC, CC, CC);
        hgemm_h16(cond16, cwk16, p_k16, MKV, CC, DCC, DCC, CC, CC);
        hgemm_h16(cond16, cwv16, p_v16, MKV, CC, DCC, DCC, CC, CC);
        flash16_k<80, 77, 1, 1><<<dim3(SS / 128, BB * NHH), 256, SM_CROSS16>>>(
            p_q16, p_k16, p_v16, p_ao, (long)NCC * CC);
        hgemm(p_ao, cwo16, cbo, p_t, p_t, MM, CC, CC, CC, CC, CC);

        // ---- FFN (GEGLU fused) ----
        layernorm_k<<<MM, 128>>>(p_t, ln3_s + l * CC, ln3_b + l * CC, p_tn);
        hgemm_geglu(p_tn, w116, b1, p_gg);
        if (l == 1)
            hgemm_wh(p_gg, w216, b2, p_t, p_t, p_t16, MM, CC, 2048, 2048, CC, CC);
        else
            hgemm(p_gg, w216, b2, p_t, p_t, MM, CC, 2048, 2048, CC, CC);
    }

    hgemm(p_t16, pout16, pout_b, nullptr, p_qf, MM, CC, CC, CC, CC, CC);
    {
        dim3 g(SS / 32, CC / 32, BB);
        out_add_t_k<<<g, dim3(32, 8)>>>(p_qf, x, out);
    }
}

// round 13
// speedup vs baseline: 1.9509x; 1.0346x over previous
#include <cuda_runtime.h>
#include <cuda_fp16.h>
#include <math.h>
#include <stdint.h>

// ---------------- problem constants ----------------
constexpr int BB   = 8;
constexpr int CC   = 512;
constexpr int SS   = 1024;
constexpr int NHH  = 8;
constexpr int DHH  = 64;
constexpr int NCC  = 77;
constexpr int DCC  = 768;
constexpr int MM   = BB * SS;  // 8192
constexpr int MKV  = BB * NCC; // 616

// ---------------- scratch ----------------
__device__ __align__(256) float  g_t    [ (long)MM * CC ];     // fp32 residual
__device__ __align__(256) float  g_q    [ (long)MM * CC ];     // reused as fp16 QKV
__device__ __align__(256) float  g_k    [ (long)MM * CC ];
__device__ __align__(256) float  g_v    [ (long)MM * CC ];
__device__ __align__(256) __half g_tn_h [ (long)MM * CC ];     // LN/GN outputs (fp16)
__device__ __align__(256) __half g_ao_h [ (long)MM * CC ];     // flash output (fp16)
__device__ __align__(256) __half g_gg_h [ (long)MM * 2048 ];   // GEGLU output (fp16)
__device__ __align__(256) __half g_w16  [ 17500160 ];          // fp16 arena
__device__ __align__(256) float  g_stats[ 2 * BB * 32 ];

// ---------------- reductions ----------------
__inline__ __device__ float warpSum(float v){
    #pragma unroll
    for (int o = 16; o > 0; o >>= 1) v += __shfl_xor_sync(0xffffffffu, v, o);
    return v;
}

// ---------------- cp.async ----------------
__device__ __forceinline__ uint32_t smem_u32(const void* p){
    return (uint32_t)__cvta_generic_to_shared(p);
}
__device__ __forceinline__ void cp16a(uint32_t dst, const void* src, int bytes){
    asm volatile("cp.async.cg.shared.global [%0], [%1], 16, %2;\n"
                 :: "r"(dst), "l"(src), "r"(bytes));
}
__device__ __forceinline__ void cp_commit(){ asm volatile("cp.async.commit_group;\n"); }
template<int N> __device__ __forceinline__ void cp_wait(){
    asm volatile("cp.async.wait_group %0;\n" :: "n"(N));
}

// ---------------- ldmatrix / mma fp16 ----------------
__device__ __forceinline__ void ldsm_x4(uint32_t* r, uint32_t addr){
    asm volatile("ldmatrix.sync.aligned.m8n8.x4.shared.b16 {%0,%1,%2,%3}, [%4];"
        : "=r"(r[0]), "=r"(r[1]), "=r"(r[2]), "=r"(r[3]) : "r"(addr));
}
__device__ __forceinline__ void ldsm_x4_t(uint32_t* r, uint32_t addr){
    asm volatile("ldmatrix.sync.aligned.m8n8.x4.trans.shared.b16 {%0,%1,%2,%3}, [%4];"
        : "=r"(r[0]), "=r"(r[1]), "=r"(r[2]), "=r"(r[3]) : "r"(addr));
}
__device__ __forceinline__ void mma_f16(float* c, const uint32_t* a, const uint32_t* b){
    asm volatile("mma.sync.aligned.m16n8k16.row.col.f32.f16.f16.f32 "
        "{%0,%1,%2,%3}, {%4,%5,%6,%7}, {%8,%9}, {%0,%1,%2,%3};"
        : "+f"(c[0]), "+f"(c[1]), "+f"(c[2]), "+f"(c[3])
        : "r"(a[0]), "r"(a[1]), "r"(a[2]), "r"(a[3]), "r"(b[0]), "r"(b[1]));
}
__device__ __forceinline__ uint32_t h2u(float a, float b){
    __half2 h = __floats2half2_rn(a, b);
    return *(uint32_t*)&h;
}

__inline__ __device__ float gelu_exact(float x){
    return 0.5f * x * (1.f + erff(x * 0.70710678118654752f));
}

// ---------------- fp32 -> fp16 batched convert (single launch) ----------------
struct CvtBatch { const float* s[24]; __half* d[24]; int n4[24]; };
__global__ void cvt_k(CvtBatch cb){
    int zi = blockIdx.z;
    int n4 = cb.n4[zi];
    int i = blockIdx.x * blockDim.x + threadIdx.x;
    if (i >= n4) return;
    const float4* s = (const float4*)cb.s[zi];
    __half2* d = (__half2*)cb.d[zi];
    float4 v = s[i];
    d[2 * i]     = __floats2half2_rn(v.x, v.y);
    d[2 * i + 1] = __floats2half2_rn(v.z, v.w);
}

// ---------------- groupnorm stats ----------------
__global__ void gn_stats_k(const float* __restrict__ x, float* __restrict__ stats){
    long base = (long)blockIdx.x * 16384;
    float s = 0.f, q = 0.f;
    for (int i = threadIdx.x; i < 16384; i += blockDim.x){
        float v = x[base + i];
        s += v; q += v * v;
    }
    __shared__ float shs[8], shq[8];
    s = warpSum(s); q = warpSum(q);
    int w = threadIdx.x >> 5, l = threadIdx.x & 31;
    if (l == 0){ shs[w] = s; shq[w] = q; }
    __syncthreads();
    if (threadIdx.x < 32){
        s = (l < 8) ? shs[l] : 0.f;
        q = (l < 8) ? shq[l] : 0.f;
        s = warpSum(s); q = warpSum(q);
        if (l == 0){
            float mean = s * (1.f / 16384.f);
            float var  = q * (1.f / 16384.f) - mean * mean;
            stats[2 * blockIdx.x]     = mean;
            stats[2 * blockIdx.x + 1] = rsqrtf(var + 1e-6f);
        }
    }
}

// ---------------- groupnorm apply + transpose (fp16 out) ----------------
__global__ void gn_apply_t_k(const float* __restrict__ x, const float* __restrict__ stats,
                             const float* __restrict__ gs, const float* __restrict__ gb,
                             __half* __restrict__ out){
    __shared__ float tile[32][33];
    int b = blockIdx.z, c0 = blockIdx.y * 32, p0 = blockIdx.x * 32;
    int tx = threadIdx.x, ty = threadIdx.y;
    #pragma unroll
    for (int r = 0; r < 4; r++){
        int c = c0 + ty + r * 8;
        float v = x[((long)b * CC + c) * SS + p0 + tx];
        int grp = b * 32 + (c >> 4);
        v = (v - stats[2 * grp]) * stats[2 * grp + 1] * gs[c] + gb[c];
        tile[ty + r * 8][tx] = v;
    }
    __syncthreads();
    #pragma unroll
    for (int r = 0; r < 4; r++){
        int p = p0 + ty + r * 8;
        out[((long)b * SS + p) * CC + c0 + tx] = __float2half(tile[tx][ty + r * 8]);
    }
}

// ---------------- final transpose + x_in residual ----------------
__global__ void out_add_t_k(const float* __restrict__ z, const float* __restrict__ x,
                            float* __restrict__ out){
    __shared__ float tile[32][33];
    int b = blockIdx.z, c0 = blockIdx.y * 32, p0 = blockIdx.x * 32;
    int tx = threadIdx.x, ty = threadIdx.y;
    #pragma unroll
    for (int r = 0; r < 4; r++){
        int p = p0 + ty + r * 8;
        tile[ty + r * 8][tx] = z[((long)b * SS + p) * CC + c0 + tx];
    }
    __syncthreads();
    #pragma unroll
    for (int r = 0; r < 4; r++){
        int c = c0 + ty + r * 8;
        long o = ((long)b * CC + c) * SS + p0 + tx;
        out[o] = tile[tx][ty + r * 8] + x[o];
    }
}

// ---------------- layernorm (fp32 in, fp16 out) ----------------
__global__ void layernorm_k(const float* __restrict__ in, const float* __restrict__ sc,
                            const float* __restrict__ bi, __half* __restrict__ out){
    long row = blockIdx.x;
    const float4* x4 = (const float4*)(in + row * CC);
    float4 xv = x4[threadIdx.x];
    float s = xv.x + xv.y + xv.z + xv.w;
    float q = xv.x*xv.x + xv.y*xv.y + xv.z*xv.z + xv.w*xv.w;
    __shared__ float shs[4], shq[4];
    s = warpSum(s); q = warpSum(q);
    int w = threadIdx.x >> 5, l = threadIdx.x & 31;
    if (l == 0){ shs[w] = s; shq[w] = q; }
    __syncthreads();
    if (threadIdx.x < 32){
        float a = (l < 4) ? shs[l] : 0.f;
        float b2 = (l < 4) ? shq[l] : 0.f;
        a = warpSum(a); b2 = warpSum(b2);
        if (l == 0){ shs[0] = a; shq[0] = b2; }
    }
    __syncthreads();
    float mean = shs[0] * (1.f / 512.f);
    float rstd = rsqrtf(shq[0] * (1.f / 512.f) - mean * mean + 1e-5f);
    float4 sv = ((const float4*)sc)[threadIdx.x];
    float4 bv = ((const float4*)bi)[threadIdx.x];
    __half2* o2 = (__half2*)(out + row * CC);
    o2[2 * threadIdx.x]     = __floats2half2_rn((xv.x - mean) * rstd * sv.x + bv.x,
                                                (xv.y - mean) * rstd * sv.y + bv.y);
    o2[2 * threadIdx.x + 1] = __floats2half2_rn((xv.z - mean) * rstd * sv.z + bv.z,
                                                (xv.w - mean) * rstd * sv.w + bv.w);
}

// =====================================================================
// fp16 flash attention (R12, passing) — unchanged.
// =====================================================================
template<int TKV, int KVLEN, int NTILES, int NSTAGE>
__global__ void flash16_k(const __half* __restrict__ Q, const __half* __restrict__ K,
                          const __half* __restrict__ V, __half* __restrict__ O,
                          long kv_bstride){
    constexpr int NT = TKV / 8;
    constexpr int LH = 72;
    extern __shared__ char smraw[];
    __half* Qs = (__half*)smraw;
    __half* Ks = Qs + 128 * LH;
    __half* Vs = Ks + NSTAGE * TKV * LH;

    int tid = threadIdx.x;
    int w = tid >> 5, lane = tid & 31;
    int g = lane >> 2, tg = lane & 3;
    int lt = lane >> 3, lr = lane & 7;
    int qt = blockIdx.x;
    int b = blockIdx.y / NHH, h = blockIdx.y % NHH;

    const __half* Qb = Q + ((long)(b * SS + qt * 128)) * CC + h * DHH;
    const __half* Kb = K + (long)b * kv_bstride + h * DHH;
    const __half* Vb = V + (long)b * kv_bstride + h * DHH;

    uint32_t sQ = smem_u32(Qs), sK = smem_u32(Ks), sV = smem_u32(Vs);

    uint32_t a_ln  = (uint32_t)(((lt & 1) * 8 + lr) * LH + (lt >> 1) * 8);
    uint32_t nk_ln = (uint32_t)(((lt >> 1) * 8 + lr) * LH + (lt & 1) * 8);
    uint32_t vt_ln = (uint32_t)(((lt & 1) * 8 + lr) * LH + (lt >> 1) * 8);

    auto loadQ = [&](){
        #pragma unroll
        for (int i = 0; i < 4; i++){
            int c = tid + i * 256;
            int row = c >> 3, kc = (c & 7) * 8;
            cp16a(sQ + (uint32_t)(row * LH + kc) * 2, Qb + (long)row * CC + kc, 16);
        }
    };
    auto loadKV = [&](int s, int t){
        constexpr int CH = TKV * 8;
        #pragma unroll
        for (int i = 0; i < (CH + 255) / 256; i++){
            int c = tid + i * 256;
            if (c < CH){
                int row = c >> 3, kc = (c & 7) * 8;
                int r = t * TKV + row;
                int by = (r < KVLEN) ? 16 : 0;
                const __half* ks = by ? (Kb + (long)r * CC + kc) : Kb;
                const __half* vs = by ? (Vb + (long)r * CC + kc) : Vb;
                cp16a(sK + (uint32_t)((s * TKV + row) * LH + kc) * 2, ks, by);
                cp16a(sV + (uint32_t)((s * TKV + row) * LH + kc) * 2, vs, by);
            }
        }
    };

    loadQ(); loadKV(0, 0); cp_commit();
    if (NTILES > 1){ loadKV(1, 1); cp_commit(); }

    uint32_t qa[4][4];
    float oacc[8][4];
    #pragma unroll
    for (int j = 0; j < 8; j++)
        #pragma unroll
        for (int r = 0; r < 4; r++) oacc[j][r] = 0.f;
    float m0 = -1e30f, m1 = -1e30f, l0 = 0.f, l1 = 0.f;

    for (int t = 0; t < NTILES; t++){
        if (t + 1 < NTILES) cp_wait<1>(); else cp_wait<0>();
        __syncthreads();
        if (t == 0){
            uint32_t qbase = sQ + (uint32_t)(w * 16 * LH) * 2;
            #pragma unroll
            for (int ks = 0; ks < 4; ks++)
                ldsm_x4(qa[ks], qbase + (a_ln + ks * 16) * 2);
        }
        uint32_t kbase = sK + (uint32_t)((t % NSTAGE) * TKV * LH) * 2;
        uint32_t vbase = sV + (uint32_t)((t % NSTAGE) * TKV * LH) * 2;

        float sacc[NT][4];
        #pragma unroll
        for (int j = 0; j < NT; j++)
            #pragma unroll
            for (int r = 0; r < 4; r++) sacc[j][r] = 0.f;
        #pragma unroll
        for (int ks = 0; ks < 4; ks++){
            #pragma unroll
            for (int jp = 0; jp < NT / 2; jp++){
                uint32_t kb[4];
                ldsm_x4(kb, kbase + (uint32_t)(jp * 16 * LH) * 2 + (nk_ln + ks * 16) * 2);
                mma_f16(sacc[2 * jp    ], qa[ks], kb);
                mma_f16(sacc[2 * jp + 1], qa[ks], kb + 2);
            }
        }
        if (KVLEN < NTILES * TKV && t == NTILES - 1){
            #pragma unroll
            for (int j = 0; j < NT; j++){
                int col = t * TKV + j * 8 + 2 * tg;
                if (col     >= KVLEN){ sacc[j][0] = -1e30f; sacc[j][2] = -1e30f; }
                if (col + 1 >= KVLEN){ sacc[j][1] = -1e30f; sacc[j][3] = -1e30f; }
            }
        }
        float rm0 = -1e30f, rm1 = -1e30f;
        #pragma unroll
        for (int j = 0; j < NT; j++){
            rm0 = fmaxf(rm0, fmaxf(sacc[j][0], sacc[j][1]));
            rm1 = fmaxf(rm1, fmaxf(sacc[j][2], sacc[j][3]));
        }
        rm0 = fmaxf(rm0, __shfl_xor_sync(0xffffffffu, rm0, 1));
        rm0 = fmaxf(rm0, __shfl_xor_sync(0xffffffffu, rm0, 2));
        rm1 = fmaxf(rm1, __shfl_xor_sync(0xffffffffu, rm1, 1));
        rm1 = fmaxf(rm1, __shfl_xor_sync(0xffffffffu, rm1, 2));
        float mn0 = fmaxf(m0, rm0), mn1 = fmaxf(m1, rm1);
        float a0 = __expf(m0 - mn0), a1 = __expf(m1 - mn1);
        float rs0 = 0.f, rs1 = 0.f;
        #pragma unroll
        for (int j = 0; j < NT; j++){
            sacc[j][0] = __expf(sacc[j][0] - mn0);
            sacc[j][1] = __expf(sacc[j][1] - mn0);
            sacc[j][2] = __expf(sacc[j][2] - mn1);
            sacc[j][3] = __expf(sacc[j][3] - mn1);
            rs0 += sacc[j][0] + sacc[j][1];
            rs1 += sacc[j][2] + sacc[j][3];
        }
        rs0 += __shfl_xor_sync(0xffffffffu, rs0, 1);
        rs0 += __shfl_xor_sync(0xffffffffu, rs0, 2);
        rs1 += __shfl_xor_sync(0xffffffffu, rs1, 1);
        rs1 += __shfl_xor_sync(0xffffffffu, rs1, 2);
        l0 = l0 * a0 + rs0;  l1 = l1 * a1 + rs1;
        m0 = mn0;  m1 = mn1;
        #pragma unroll
        for (int jn = 0; jn < 8; jn++){
            oacc[jn][0] *= a0; oacc[jn][1] *= a0;
            oacc[jn][2] *= a1; oacc[jn][3] *= a1;
        }
        #pragma unroll
        for (int ks = 0; ks < TKV / 16; ks++){
            uint32_t pa[4];
            pa[0] = h2u(sacc[2 * ks    ][0], sacc[2 * ks    ][1]);
            pa[1] = h2u(sacc[2 * ks    ][2], sacc[2 * ks    ][3]);
            pa[2] = h2u(sacc[2 * ks + 1][0], sacc[2 * ks + 1][1]);
            pa[3] = h2u(sacc[2 * ks + 1][2], sacc[2 * ks + 1][3]);
            #pragma unroll
            for (int jp = 0; jp < 4; jp++){
                uint32_t vb[4];
                ldsm_x4_t(vb, vbase + (uint32_t)(ks * 16 * LH) * 2
                              + (vt_ln + jp * 16) * 2);
                mma_f16(oacc[2 * jp    ], pa, vb);
                mma_f16(oacc[2 * jp + 1], pa, vb + 2);
            }
        }
        __syncthreads();
        if (t + 2 < NTILES) loadKV(t % 2, t + 2);
        cp_commit();
    }

    float inv0 = 1.f / l0, inv1 = 1.f / l1;
    __half* Ob = O + ((long)(b * SS + qt * 128 + w * 16)) * CC + h * DHH;
    #pragma unroll
    for (int jn = 0; jn < 8; jn++){
        int col = jn * 8 + 2 * tg;
        *(__half2*)&Ob[(long)(g    ) * CC + col] =
            __floats2half2_rn(oacc[jn][0] * inv0, oacc[jn][1] * inv0);
        *(__half2*)&Ob[(long)(g + 8) * CC + col] =
            __floats2half2_rn(oacc[jn][2] * inv1, oacc[jn][3] * inv1);
    }
}

// =====================================================================
// fp16 NN GEMM (R12 mainloop, passing) with z-select on B / fp16 out.
// OUT: 0=fp32 C(+res), 1=fp16 only, 2=both. blockIdx.z picks B/Gh slot.
// =====================================================================
constexpr int HLA = 72;
constexpr int HLB = 136;
constexpr int HAW = 128 * HLA * 2;
constexpr int HBW = 64 * HLB * 2;
constexpr int H_SMEM = 3 * (HAW + HBW);

template<bool GEGLU, int OUT>
__global__ void hgemm_k(const __half* __restrict__ A,
                        const __half* __restrict__ B0, const __half* __restrict__ B1,
                        const __half* __restrict__ B2, const __half* __restrict__ B3,
                        const float* __restrict__ bias, const float* __restrict__ res,
                        float* __restrict__ C,
                        __half* __restrict__ G0, __half* __restrict__ G1,
                        __half* __restrict__ G2, __half* __restrict__ G3,
                        int M, int N, int K, int lda, int ldb, int ldc){
    constexpr int BK = 64, STAGES = 3;
    extern __shared__ float smf[];
    uint32_t sb = smem_u32(smf);
    uint32_t Abase = sb;
    uint32_t Bbase = sb + 3 * HAW;

    int z = blockIdx.z;
    const __half* Bm = (z == 0) ? B0 : (z == 1) ? B1 : (z == 2) ? B2 : B3;
    __half*       Gh = (z == 0) ? G0 : (z == 1) ? G1 : (z == 2) ? G2 : G3;

    int tid  = threadIdx.x;
    int warp = tid >> 5, lane = tid & 31;
    int g  = lane >> 2;
    int tg = lane & 3;
    int wm = (warp & 1) * 64;
    int wn = (warp >> 1) * 64;
    int row0 = blockIdx.y * 128;
    int col0 = GEGLU ? 0 : blockIdx.x * 128;
    int c0h  = blockIdx.x * 64;

    int lt = lane >> 3, lr = lane & 7;
    uint32_t a_lane = (uint32_t)(((lt & 1) * 8 + lr) * HLA + (lt >> 1) * 8) * 2;
    uint32_t b_lane = (uint32_t)(((lt & 1) * 8 + lr) * HLB + (lt >> 1) * 8) * 2;

    float acc[4][8][4];
    #pragma unroll
    for (int i = 0; i < 4; i++)
        #pragma unroll
        for (int j = 0; j < 8; j++)
            #pragma unroll
            for (int r = 0; r < 4; r++) acc[i][j][r] = 0.f;

    auto loadA = [&](int s, int kt){
        uint32_t base = Abase + s * HAW;
        #pragma unroll
        for (int it = 0; it < 8; it++){
            int c = tid + it * 128;
            int m  = c >> 3;
            int kc = (c & 7) * 8;
            int gm = row0 + m;
            int by = (gm < M) ? 16 : 0;
            const __half* src = by ? (A + (long)gm * lda + kt + kc) : A;
            cp16a(base + (uint32_t)(m * HLA + kc) * 2, src, by);
        }
    };
    auto loadB = [&](int s, int kt){
        uint32_t base = Bbase + s * HBW;
        #pragma unroll
        for (int it = 0; it < 8; it++){
            int c = tid + it * 128;
            int kr = c >> 4;
            int nc = (c & 15) * 8;
            int gk = kt + kr;
            long gn;
            if (GEGLU) gn = (nc < 64) ? (long)(c0h + nc) : (long)(2048 + c0h + nc - 64);
            else       gn = (long)(col0 + nc);
            int by = (gk < K) ? 16 : 0;
            const __half* src = by ? (Bm + (long)gk * ldb + gn) : Bm;
            cp16a(base + (uint32_t)(kr * HLB + nc) * 2, src, by);
        }
    };
    auto compute = [&](int s){
        uint32_t Ab = Abase + s * HAW;
        uint32_t Bb = Bbase + s * HBW;
        #pragma unroll
        for (int ks = 0; ks < 4; ks++){
            uint32_t bf[8][2];
            #pragma unroll
            for (int jp = 0; jp < 4; jp++){
                uint32_t r[4];
                ldsm_x4_t(r, Bb + b_lane +
                          (uint32_t)(ks * 16 * HLB + wn + jp * 16) * 2);
                bf[2*jp  ][0] = r[0]; bf[2*jp  ][1] = r[1];
                bf[2*jp+1][0] = r[2]; bf[2*jp+1][1] = r[3];
            }
            #pragma unroll
            for (int i = 0; i < 4; i++){
                uint32_t af[4];
                ldsm_x4(af, Ab + a_lane +
                        (uint32_t)((wm + i * 16) * HLA + ks * 16) * 2);
                #pragma unroll
                for (int j = 0; j < 8; j++)
                    mma_f16(acc[i][j], af, bf[j]);
            }
        }
    };

    int nk = (K + BK - 1) / BK;
    #pragma unroll
    for (int s = 0; s < STAGES - 1; s++){
        if (s < nk){ loadA(s, s * BK); loadB(s, s * BK); }
        cp_commit();
    }
    for (int t = 0; t < nk; t++){
        cp_wait<STAGES - 2>();
        __syncthreads();
        int tn = t + STAGES - 1;
        if (tn < nk){ loadA(tn % STAGES, tn * BK); loadB(tn % STAGES, tn * BK); }
        cp_commit();
        compute(t % STAGES);
    }

    if (!GEGLU){
        #pragma unroll
        for (int i = 0; i < 4; i++){
            int r0 = row0 + wm + i * 16 + g;
            int r1 = r0 + 8;
            #pragma unroll
            for (int j = 0; j < 8; j++){
                int c0 = col0 + wn + j * 8 + 2 * tg;
                float* a4 = acc[i][j];
                float b0 = 0.f, b1v = 0.f;
                if (bias){ b0 = bias[c0]; b1v = bias[c0 + 1]; }
                if (r0 < M){
                    float2 v = {a4[0] + b0, a4[1] + b1v};
                    if (res){
                        float2 rr = *(const float2*)&res[(long)r0 * ldc + c0];
                        v.x += rr.x; v.y += rr.y;
                    }
                    if (OUT != 1) *(float2*)&C[(long)r0 * ldc + c0] = v;
                    if (OUT != 0) *(__half2*)&Gh[(long)r0 * ldc + c0] = __floats2half2_rn(v.x, v.y);
                }
                if (r1 < M){
                    float2 v = {a4[2] + b0, a4[3] + b1v};
                    if (res){
                        float2 rr = *(const float2*)&res[(long)r1 * ldc + c0];
                        v.x += rr.x; v.y += rr.y;
                    }
                    if (OUT != 1) *(float2*)&C[(long)r1 * ldc + c0] = v;
                    if (OUT != 0) *(__half2*)&Gh[(long)r1 * ldc + c0] = __floats2half2_rn(v.x, v.y);
                }
            }
        }
    } else {
        constexpr int LE = 68;
        float* ex = smf;
        __syncthreads();
        if (wn == 64){
            #pragma unroll
            for (int i = 0; i < 4; i++){
                int lr0 = wm + i * 16 + g, lr1 = lr0 + 8;
                #pragma unroll
                for (int j = 0; j < 8; j++){
                    int gc = j * 8 + 2 * tg;
                    float bg0 = bias[c0h + gc + 2048];
                    float bg1 = bias[c0h + gc + 1 + 2048];
                    ex[lr0 * LE + gc    ] = gelu_exact(acc[i][j][0] + bg0);
                    ex[lr0 * LE + gc + 1] = gelu_exact(acc[i][j][1] + bg1);
                    ex[lr1 * LE + gc    ] = gelu_exact(acc[i][j][2] + bg0);
                    ex[lr1 * LE + gc + 1] = gelu_exact(acc[i][j][3] + bg1);
                }
            }
        }
        __syncthreads();
        if (wn == 0){
            #pragma unroll
            for (int i = 0; i < 4; i++){
                int lr0 = wm + i * 16 + g, lr1 = lr0 + 8;
                long gr0 = row0 + lr0, gr1 = row0 + lr1;
                #pragma unroll
                for (int j = 0; j < 8; j++){
                    int lc = j * 8 + 2 * tg;
                    float bu0 = bias[c0h + lc], bu1 = bias[c0h + lc + 1];
                    *(__half2*)&Gh[gr0 * ldc + c0h + lc] = __floats2half2_rn(
                        (acc[i][j][0] + bu0) * ex[lr0 * LE + lc],
                        (acc[i][j][1] + bu1) * ex[lr0 * LE + lc + 1]);
                    *(__half2*)&Gh[gr1 * ldc + c0h + lc] = __floats2half2_rn(
                        (acc[i][j][2] + bu0) * ex[lr1 * LE + lc],
                        (acc[i][j][3] + bu1) * ex[lr1 * LE + lc + 1]);
                }
            }
        }
    }
}

// ---------------- launch helpers ----------------
static void hgemm(const __half* A, const __half* W, const float* bias, const float* res,
                  float* C, int M, int N, int K, int lda, int ldb, int ldc){
    cudaFuncSetAttribute(hgemm_k<false,0>,
                         cudaFuncAttributeMaxDynamicSharedMemorySize, H_SMEM);
    dim3 g((N + 127) / 128, (M + 127) / 128, 1);
    hgemm_k<false,0><<<g, 128, H_SMEM>>>(A, W, W, W, W, bias, res, C,
                                         nullptr, nullptr, nullptr, nullptr,
                                         M, N, K, lda, ldb, ldc);
}
static void hgemm_h16z(const __half* A,
                       const __half* W0, const __half* W1, const __half* W2, const __half* W3,
                       __half* C0, __half* C1, __half* C2, __half* C3, int nz,
                       int M, int N, int K, int lda, int ldb, int ldc){
    cudaFuncSetAttribute(hgemm_k<false,1>,
                         cudaFuncAttributeMaxDynamicSharedMemorySize, H_SMEM);
    dim3 g((N + 127) / 128, (M + 127) / 128, nz);
    hgemm_k<false,1><<<g, 128, H_SMEM>>>(A, W0, W1, W2, W3, nullptr, nullptr, nullptr,
                                         C0, C1, C2, C3, M, N, K, lda, ldb, ldc);
}
static void hgemm_wh(const __half* A, const __half* W, const float* bias, const float* res,
                     float* C, __half* Ch, int M, int N, int K, int lda, int ldb, int ldc){
    cudaFuncSetAttribute(hgemm_k<false,2>,
                         cudaFuncAttributeMaxDynamicSharedMemorySize, H_SMEM);
    dim3 g((N + 127) / 128, (M + 127) / 128, 1);
    hgemm_k<false,2><<<g, 128, H_SMEM>>>(A, W, W, W, W, bias, res, C,
                                         Ch, Ch, Ch, Ch, M, N, K, lda, ldb, ldc);
}
static void hgemm_geglu(const __half* A, const __half* W1, const float* b1, __half* G){
    cudaFuncSetAttribute(hgemm_k<true,0>,
                         cudaFuncAttributeMaxDynamicSharedMemorySize, H_SMEM);
    dim3 g(2048 / 64, MM / 128, 1);
    hgemm_k<true,0><<<g, 128, H_SMEM>>>(A, W1, W1, W1, W1, b1, nullptr, nullptr,
                                        G, G, G, G, MM, 4096, CC, CC, 4096, 2048);
}

extern "C" void kernel_launch(void* const* d_in, const int* in_sizes, int n_in,
                              void* d_out, int out_size){
    (void)in_sizes; (void)n_in; (void)out_size;
    const float* x      = (const float*)d_in[0];
    const float* cond   = (const float*)d_in[1];
    const float* gn_s   = (const float*)d_in[2];
    const float* gn_b   = (const float*)d_in[3];
    const float* pin_w  = (const float*)d_in[4];
    const float* pin_b  = (const float*)d_in[5];
    const float* pout_w = (const float*)d_in[6];
    const float* pout_b = (const float*)d_in[7];
    const float* ln1_s  = (const float*)d_in[8];
    const float* ln1_b  = (const float*)d_in[9];
    const float* sa_wq  = (const float*)d_in[10];
    const float* sa_wk  = (const float*)d_in[11];
    const float* sa_wv  = (const float*)d_in[12];
    const float* sa_wo  = (const float*)d_in[13];
    const float* sa_bo  = (const float*)d_in[14];
    const float* ln2_s  = (const float*)d_in[15];
    const float* ln2_b  = (const float*)d_in[16];
    const float* ca_wq  = (const float*)d_in[17];
    const float* ca_wk  = (const float*)d_in[18];
    const float* ca_wv  = (const float*)d_in[19];
    const float* ca_wo  = (const float*)d_in[20];
    const float* ca_bo  = (const float*)d_in[21];
    const float* ln3_s  = (const float*)d_in[22];
    const float* ln3_b  = (const float*)d_in[23];
    const float* ff_w1  = (const float*)d_in[24];
    const float* ff_b1  = (const float*)d_in[25];
    const float* ff_w2  = (const float*)d_in[26];
    const float* ff_b2  = (const float*)d_in[27];
    float* out = (float*)d_out;

    float  *p_t, *p_qf, *p_kf, *p_vf, *p_stats;
    __half *p_tn, *p_ao, *p_gg, *p_w16;
    cudaGetSymbolAddress((void**)&p_t,    g_t);
    cudaGetSymbolAddress((void**)&p_qf,   g_q);
    cudaGetSymbolAddress((void**)&p_kf,   g_k);
    cudaGetSymbolAddress((void**)&p_vf,   g_v);
    cudaGetSymbolAddress((void**)&p_tn,   g_tn_h);
    cudaGetSymbolAddress((void**)&p_ao,   g_ao_h);
    cudaGetSymbolAddress((void**)&p_gg,   g_gg_h);
    cudaGetSymbolAddress((void**)&p_w16,  g_w16);
    cudaGetSymbolAddress((void**)&p_stats,g_stats);
    __half* p_q16 = (__half*)p_qf;
    __half* p_k16 = (__half*)p_kf;
    __half* p_v16 = (__half*)p_vf;

    // ---- fp16 arena layout ----
    const size_t S512 = 512 * 512, S768 = 768 * 512;
    const size_t SW1 = 512 * 4096, SW2 = 2048 * 512;
    __half* pin16  = p_w16;
    __half* pout16 = pin16 + S512;
    const size_t LSZ = 6 * S512 + 2 * S768 + SW1 + SW2;
    __half* lbase0 = pout16 + S512;
    auto LW = [&](int l){ return lbase0 + (size_t)l * LSZ; };
    __half* cond16 = lbase0 + 2 * LSZ;
    __half* p_t16  = cond16 + (size_t)BB * NCC * DCC;
    // precomputed cross K/V (per layer): 616*512 halves each
    const size_t SKV = (size_t)MKV * CC;
    __half* ckv_k0 = p_t16 + (size_t)MM * CC;
    __half* ckv_v0 = ckv_k0 + SKV;
    __half* ckv_k1 = ckv_v0 + SKV;
    __half* ckv_v1 = ckv_k1 + SKV;

    // ---- single batched fp32->fp16 conversion (23 slots) ----
    {
        CvtBatch cb{};
        int zi = 0;
        auto add = [&](const float* s, __half* d, size_t n){
            cb.s[zi] = s; cb.d[zi] = d; cb.n4[zi] = (int)(n / 4); zi++;
        };
        add(pin_w,  pin16,  S512);
        add(pout_w, pout16, S512);
        for (int l = 0; l < 2; l++){
            __half* b = LW(l);
            add(sa_wq + (long)l * S512, b,             S512);
            add(sa_wk + (long)l * S512, b + S512,      S512);
            add(sa_wv + (long)l * S512, b + 2 * S512,  S512);
            add(sa_wo + (long)l * S512, b + 3 * S512,  S512);
            add(ca_wq + (long)l * S512, b + 4 * S512,  S512);
            add(ca_wo + (long)l * S512, b + 5 * S512,  S512);
            add(ca_wk + (long)l * S768, b + 6 * S512,         S768);
            add(ca_wv + (long)l * S768, b + 6 * S512 + S768,  S768);
            add(ff_w1 + (long)l * SW1,  b + 6 * S512 + 2 * S768,       SW1);
            add(ff_w2 + (long)l * SW2,  b + 6 * S512 + 2 * S768 + SW1, SW2);
        }
        add(cond, cond16, (size_t)BB * NCC * DCC);
        int maxb = (int)((SW1 / 4 + 255) / 256);
        cvt_k<<<dim3(maxb, 1, zi), 256>>>(cb);
    }

    // ---- precompute ALL cross-attn K/V (depends only on cond) ----
    hgemm_h16z(cond16,
               LW(0) + 6 * S512, LW(0) + 6 * S512 + S768,
               LW(1) + 6 * S512, LW(1) + 6 * S512 + S768,
               ckv_k0, ckv_v0, ckv_k1, ckv_v1, 4,
               MKV, CC, DCC, DCC, CC, CC);

    // flash smem
    constexpr int SM_SELF16  = (128 * 72 + 2 * 64 * 72 + 2 * 64 * 72) * 2;
    constexpr int SM_CROSS16 = (128 * 72 + 80 * 72 + 80 * 72) * 2;
    cudaFuncSetAttribute(flash16_k<64, 1024, 16, 2>,
                         cudaFuncAttributeMaxDynamicSharedMemorySize, SM_SELF16);
    cudaFuncSetAttribute(flash16_k<80, 77, 1, 1>,
                         cudaFuncAttributeMaxDynamicSharedMemorySize, SM_CROSS16);

    gn_stats_k<<<BB * 32, 256>>>(x, p_stats);
    {
        dim3 g(SS / 32, CC / 32, BB);
        gn_apply_t_k<<<g, dim3(32, 8)>>>(x, p_stats, gn_s, gn_b, p_tn);
    }
    hgemm(p_tn, pin16, pin_b, nullptr, p_t, MM, CC, CC, CC, CC, CC);

    for (int l = 0; l < 2; l++){
        __half* b   = LW(l);
        __half* wq16  = b;
        __half* wk16  = b + S512;
        __half* wv16  = b + 2 * S512;
        __half* wo16  = b + 3 * S512;
        __half* cwq16 = b + 4 * S512;
        __half* cwo16 = b + 5 * S512;
        __half* w116  = b + 6 * S512 + 2 * S768;
        __half* w216  = w116 + SW1;
        const float* bo  = sa_bo + (long)l * CC;
        const float* cbo = ca_bo + (long)l * CC;
        const float* b1  = ff_b1 + (long)l * 4096;
        const float* b2  = ff_b2 + (long)l * CC;
        __half* ck = (l == 0) ? ckv_k0 : ckv_k1;
        __half* cv = (l == 0) ? ckv_v0 : ckv_v1;

        // ---- self-attention: fused QKV (one z=3 launch) ----
        layernorm_k<<<MM, 128>>>(p_t, ln1_s + l * CC, ln1_b + l * CC, p_tn);
        hgemm_h16z(p_tn, wq16, wk16, wv16, wq16,
                   p_q16, p_k16, p_v16, p_q16, 3,
                   MM, CC, CC, CC, CC, CC);
        flash16_k<64, 1024, 16, 2><<<dim3(SS / 128, BB * NHH), 256, SM_SELF16>>>(
            p_q16, p_k16, p_v16, p_ao, (long)SS * CC);
        hgemm(p_ao, wo16, bo, p_t, p_t, MM, CC, CC, CC, CC, CC);

        // ---- cross-attention: K/V already precomputed ----
        layernorm_k<<<MM, 128>>>(p_t, ln2_s + l * CC, ln2_b + l * CC, p_tn);
        hgemm_h16z(p_tn, cwq16, cwq16, cwq16, cwq16,
                   p_q16, p_q16, p_q16, p_q16, 1,
                   MM, CC, CC, CC, CC, CC);
        flash16_k<80, 77, 1, 1><<<dim3(SS / 128, BB * NHH), 256, SM_CROSS16>>>(
            p_q16, ck, cv, p_ao, (long)NCC * CC);
        hgemm(p_ao, cwo16, cbo, p_t, p_t, MM, CC, CC, CC, CC, CC);

        // ---- FFN (GEGLU fused) ----
        layernorm_k<<<MM, 128>>>(p_t, ln3_s + l * CC, ln3_b + l * CC, p_tn);
        hgemm_geglu(p_tn, w116, b1, p_gg);
        if (l == 1)
            hgemm_wh(p_gg, w216, b2, p_t, p_t, p_t16, MM, CC, 2048, 2048, CC, CC);
        else
            hgemm(p_gg, w216, b2, p_t, p_t, MM, CC, 2048, 2048, CC, CC);
    }

    hgemm(p_t16, pout16, pout_b, nullptr, p_qf, MM, CC, CC, CC, CC, CC);
    {
        dim3 g(SS / 32, CC / 32, BB);
        out_add_t_k<<<g, dim3(32, 8)>>>(p_qf, x, out);
    }
}

// round 14
// speedup vs baseline: 1.9864x; 1.0182x over previous
#include <cuda_runtime.h>
#include <cuda_fp16.h>
#include <math.h>
#include <stdint.h>

// ---------------- problem constants ----------------
constexpr int BB   = 8;
constexpr int CC   = 512;
constexpr int SS   = 1024;
constexpr int NHH  = 8;
constexpr int DHH  = 64;
constexpr int NCC  = 77;
constexpr int DCC  = 768;
constexpr int MM   = BB * SS;  // 8192
constexpr int MKV  = BB * NCC; // 616

// ---------------- scratch ----------------
__device__ __align__(256) float  g_t    [ (long)MM * CC ];     // fp32 residual
__device__ __align__(256) float  g_q    [ (long)MM * CC ];     // reused as fp16 QKV
__device__ __align__(256) float  g_k    [ (long)MM * CC ];
__device__ __align__(256) float  g_v    [ (long)MM * CC ];
__device__ __align__(256) __half g_tn_h [ (long)MM * CC ];
__device__ __align__(256) __half g_ao_h [ (long)MM * CC ];
__device__ __align__(256) __half g_gg_h [ (long)MM * 2048 ];
__device__ __align__(256) __half g_w16  [ 17500160 ];          // fp16 arena

// ---------------- reductions ----------------
__inline__ __device__ float warpSum(float v){
    #pragma unroll
    for (int o = 16; o > 0; o >>= 1) v += __shfl_xor_sync(0xffffffffu, v, o);
    return v;
}

// ---------------- cp.async ----------------
__device__ __forceinline__ uint32_t smem_u32(const void* p){
    return (uint32_t)__cvta_generic_to_shared(p);
}
__device__ __forceinline__ void cp16a(uint32_t dst, const void* src, int bytes){
    asm volatile("cp.async.cg.shared.global [%0], [%1], 16, %2;\n"
                 :: "r"(dst), "l"(src), "r"(bytes));
}
__device__ __forceinline__ void cp_commit(){ asm volatile("cp.async.commit_group;\n"); }
template<int N> __device__ __forceinline__ void cp_wait(){
    asm volatile("cp.async.wait_group %0;\n" :: "n"(N));
}

// ---------------- ldmatrix / mma fp16 ----------------
__device__ __forceinline__ void ldsm_x4(uint32_t* r, uint32_t addr){
    asm volatile("ldmatrix.sync.aligned.m8n8.x4.shared.b16 {%0,%1,%2,%3}, [%4];"
        : "=r"(r[0]), "=r"(r[1]), "=r"(r[2]), "=r"(r[3]) : "r"(addr));
}
__device__ __forceinline__ void ldsm_x4_t(uint32_t* r, uint32_t addr){
    asm volatile("ldmatrix.sync.aligned.m8n8.x4.trans.shared.b16 {%0,%1,%2,%3}, [%4];"
        : "=r"(r[0]), "=r"(r[1]), "=r"(r[2]), "=r"(r[3]) : "r"(addr));
}
__device__ __forceinline__ void mma_f16(float* c, const uint32_t* a, const uint32_t* b){
    asm volatile("mma.sync.aligned.m16n8k16.row.col.f32.f16.f16.f32 "
        "{%0,%1,%2,%3}, {%4,%5,%6,%7}, {%8,%9}, {%0,%1,%2,%3};"
        : "+f"(c[0]), "+f"(c[1]), "+f"(c[2]), "+f"(c[3])
        : "r"(a[0]), "r"(a[1]), "r"(a[2]), "r"(a[3]), "r"(b[0]), "r"(b[1]));
}
__device__ __forceinline__ uint32_t h2u(float a, float b){
    __half2 h = __floats2half2_rn(a, b);
    return *(uint32_t*)&h;
}

__inline__ __device__ float gelu_exact(float x){
    return 0.5f * x * (1.f + erff(x * 0.70710678118654752f));
}

// ---------------- fp32 -> fp16 batched convert (single launch) ----------------
struct CvtBatch { const float* s[24]; __half* d[24]; int n4[24]; };
__global__ void cvt_k(CvtBatch cb){
    int zi = blockIdx.z;
    int n4 = cb.n4[zi];
    int i = blockIdx.x * blockDim.x + threadIdx.x;
    if (i >= n4) return;
    const float4* s = (const float4*)cb.s[zi];
    __half2* d = (__half2*)cb.d[zi];
    float4 v = s[i];
    d[2 * i]     = __floats2half2_rn(v.x, v.y);
    d[2 * i + 1] = __floats2half2_rn(v.z, v.w);
}

// ---------------- fused groupnorm (stats + apply + transpose) ----------------
// one block per (b, group): 16 channels x 1024 px staged in 64KB smem.
__global__ void gn_fused_k(const float* __restrict__ x,
                           const float* __restrict__ gs, const float* __restrict__ gb,
                           __half* __restrict__ out){
    __shared__ float sm[16384];
    __shared__ float shs[8], shq[8], s_mean, s_rstd;
    int b = blockIdx.x >> 5, grp = blockIdx.x & 31;
    long base = ((long)b * CC + grp * 16) * SS;
    int tid = threadIdx.x;

    float s = 0.f, q = 0.f;
    #pragma unroll
    for (int i = 0; i < 16; i++){
        int c = tid + i * 256;
        float4 v = ((const float4*)(x + base))[c];
        ((float4*)sm)[c] = v;
        s += v.x + v.y + v.z + v.w;
        q += v.x*v.x + v.y*v.y + v.z*v.z + v.w*v.w;
    }
    s = warpSum(s); q = warpSum(q);
    int w = tid >> 5, l = tid & 31;
    if (l == 0){ shs[w] = s; shq[w] = q; }
    __syncthreads();
    if (tid < 32){
        s = (l < 8) ? shs[l] : 0.f;
        q = (l < 8) ? shq[l] : 0.f;
        s = warpSum(s); q = warpSum(q);
        if (l == 0){
            float mean = s * (1.f / 16384.f);
            s_mean = mean;
            s_rstd = rsqrtf(q * (1.f / 16384.f) - mean * mean + 1e-6f);
        }
    }
    __syncthreads();
    float mean = s_mean, rstd = s_rstd;
    // per-channel affine
    float sc[2], bi[2];
    int c2 = tid & 7;                        // half2 channel pair 0..7
    sc[0] = gs[grp * 16 + 2 * c2];     bi[0] = gb[grp * 16 + 2 * c2];
    sc[1] = gs[grp * 16 + 2 * c2 + 1]; bi[1] = gb[grp * 16 + 2 * c2 + 1];
    // write transposed: out[(b*SS+p)*CC + grp*16 + 2*c2 .. +1]
    __half2* ob = (__half2*)(out + (long)b * SS * CC + grp * 16) + c2;
    #pragma unroll
    for (int i = 0; i < 32; i++){
        int p = (tid >> 3) + i * 32;
        float v0 = (sm[(2 * c2    ) * 1024 + p] - mean) * rstd * sc[0] + bi[0];
        float v1 = (sm[(2 * c2 + 1) * 1024 + p] - mean) * rstd * sc[1] + bi[1];
        ob[(long)p * (CC / 2)] = __floats2half2_rn(v0, v1);
    }
}

// ---------------- layernorm (warp per row, fp32 in, fp16 out) ----------------
__global__ void layernorm_k(const float* __restrict__ in, const float* __restrict__ sc,
                            const float* __restrict__ bi, __half* __restrict__ out){
    int row = blockIdx.x * 8 + (threadIdx.x >> 5);
    int lane = threadIdx.x & 31;
    const float4* x4 = (const float4*)(in + (long)row * CC);
    float4 xv[4];
    float s = 0.f, q = 0.f;
    #pragma unroll
    for (int t = 0; t < 4; t++){
        xv[t] = x4[lane + t * 32];
        s += xv[t].x + xv[t].y + xv[t].z + xv[t].w;
        q += xv[t].x*xv[t].x + xv[t].y*xv[t].y + xv[t].z*xv[t].z + xv[t].w*xv[t].w;
    }
    s = warpSum(s); q = warpSum(q);
    float mean = s * (1.f / 512.f);
    float rstd = rsqrtf(q * (1.f / 512.f) - mean * mean + 1e-5f);
    __half2* o2 = (__half2*)(out + (long)row * CC);
    #pragma unroll
    for (int t = 0; t < 4; t++){
        int c = lane + t * 32;
        float4 sv = ((const float4*)sc)[c];
        float4 bv = ((const float4*)bi)[c];
        o2[2 * c]     = __floats2half2_rn((xv[t].x - mean) * rstd * sv.x + bv.x,
                                          (xv[t].y - mean) * rstd * sv.y + bv.y);
        o2[2 * c + 1] = __floats2half2_rn((xv[t].z - mean) * rstd * sv.z + bv.z,
                                          (xv[t].w - mean) * rstd * sv.w + bv.w);
    }
}

// =====================================================================
// fp16 flash attention (R12, passing) — unchanged.
// =====================================================================
template<int TKV, int KVLEN, int NTILES, int NSTAGE>
__global__ void flash16_k(const __half* __restrict__ Q, const __half* __restrict__ K,
                          const __half* __restrict__ V, __half* __restrict__ O,
                          long kv_bstride){
    constexpr int NT = TKV / 8;
    constexpr int LH = 72;
    extern __shared__ char smraw[];
    __half* Qs = (__half*)smraw;
    __half* Ks = Qs + 128 * LH;
    __half* Vs = Ks + NSTAGE * TKV * LH;

    int tid = threadIdx.x;
    int w = tid >> 5, lane = tid & 31;
    int g = lane >> 2, tg = lane & 3;
    int lt = lane >> 3, lr = lane & 7;
    int qt = blockIdx.x;
    int b = blockIdx.y / NHH, h = blockIdx.y % NHH;

    const __half* Qb = Q + ((long)(b * SS + qt * 128)) * CC + h * DHH;
    const __half* Kb = K + (long)b * kv_bstride + h * DHH;
    const __half* Vb = V + (long)b * kv_bstride + h * DHH;

    uint32_t sQ = smem_u32(Qs), sK = smem_u32(Ks), sV = smem_u32(Vs);

    uint32_t a_ln  = (uint32_t)(((lt & 1) * 8 + lr) * LH + (lt >> 1) * 8);
    uint32_t nk_ln = (uint32_t)(((lt >> 1) * 8 + lr) * LH + (lt & 1) * 8);
    uint32_t vt_ln = (uint32_t)(((lt & 1) * 8 + lr) * LH + (lt >> 1) * 8);

    auto loadQ = [&](){
        #pragma unroll
        for (int i = 0; i < 4; i++){
            int c = tid + i * 256;
            int row = c >> 3, kc = (c & 7) * 8;
            cp16a(sQ + (uint32_t)(row * LH + kc) * 2, Qb + (long)row * CC + kc, 16);
        }
    };
    auto loadKV = [&](int s, int t){
        constexpr int CH = TKV * 8;
        #pragma unroll
        for (int i = 0; i < (CH + 255) / 256; i++){
            int c = tid + i * 256;
            if (c < CH){
                int row = c >> 3, kc = (c & 7) * 8;
                int r = t * TKV + row;
                int by = (r < KVLEN) ? 16 : 0;
                const __half* ks = by ? (Kb + (long)r * CC + kc) : Kb;
                const __half* vs = by ? (Vb + (long)r * CC + kc) : Vb;
                cp16a(sK + (uint32_t)((s * TKV + row) * LH + kc) * 2, ks, by);
                cp16a(sV + (uint32_t)((s * TKV + row) * LH + kc) * 2, vs, by);
            }
        }
    };

    loadQ(); loadKV(0, 0); cp_commit();
    if (NTILES > 1){ loadKV(1, 1); cp_commit(); }

    uint32_t qa[4][4];
    float oacc[8][4];
    #pragma unroll
    for (int j = 0; j < 8; j++)
        #pragma unroll
        for (int r = 0; r < 4; r++) oacc[j][r] = 0.f;
    float m0 = -1e30f, m1 = -1e30f, l0 = 0.f, l1 = 0.f;

    for (int t = 0; t < NTILES; t++){
        if (t + 1 < NTILES) cp_wait<1>(); else cp_wait<0>();
        __syncthreads();
        if (t == 0){
            uint32_t qbase = sQ + (uint32_t)(w * 16 * LH) * 2;
            #pragma unroll
            for (int ks = 0; ks < 4; ks++)
                ldsm_x4(qa[ks], qbase + (a_ln + ks * 16) * 2);
        }
        uint32_t kbase = sK + (uint32_t)((t % NSTAGE) * TKV * LH) * 2;
        uint32_t vbase = sV + (uint32_t)((t % NSTAGE) * TKV * LH) * 2;

        float sacc[NT][4];
        #pragma unroll
        for (int j = 0; j < NT; j++)
            #pragma unroll
            for (int r = 0; r < 4; r++) sacc[j][r] = 0.f;
        #pragma unroll
        for (int ks = 0; ks < 4; ks++){
            #pragma unroll
            for (int jp = 0; jp < NT / 2; jp++){
                uint32_t kb[4];
                ldsm_x4(kb, kbase + (uint32_t)(jp * 16 * LH) * 2 + (nk_ln + ks * 16) * 2);
                mma_f16(sacc[2 * jp    ], qa[ks], kb);
                mma_f16(sacc[2 * jp + 1], qa[ks], kb + 2);
            }
        }
        if (KVLEN < NTILES * TKV && t == NTILES - 1){
            #pragma unroll
            for (int j = 0; j < NT; j++){
                int col = t * TKV + j * 8 + 2 * tg;
                if (col     >= KVLEN){ sacc[j][0] = -1e30f; sacc[j][2] = -1e30f; }
                if (col + 1 >= KVLEN){ sacc[j][1] = -1e30f; sacc[j][3] = -1e30f; }
            }
        }
        float rm0 = -1e30f, rm1 = -1e30f;
        #pragma unroll
        for (int j = 0; j < NT; j++){
            rm0 = fmaxf(rm0, fmaxf(sacc[j][0], sacc[j][1]));
            rm1 = fmaxf(rm1, fmaxf(sacc[j][2], sacc[j][3]));
        }
        rm0 = fmaxf(rm0, __shfl_xor_sync(0xffffffffu, rm0, 1));
        rm0 = fmaxf(rm0, __shfl_xor_sync(0xffffffffu, rm0, 2));
        rm1 = fmaxf(rm1, __shfl_xor_sync(0xffffffffu, rm1, 1));
        rm1 = fmaxf(rm1, __shfl_xor_sync(0xffffffffu, rm1, 2));
        float mn0 = fmaxf(m0, rm0), mn1 = fmaxf(m1, rm1);
        float a0 = __expf(m0 - mn0), a1 = __expf(m1 - mn1);
        float rs0 = 0.f, rs1 = 0.f;
        #pragma unroll
        for (int j = 0; j < NT; j++){
            sacc[j][0] = __expf(sacc[j][0] - mn0);
            sacc[j][1] = __expf(sacc[j][1] - mn0);
            sacc[j][2] = __expf(sacc[j][2] - mn1);
            sacc[j][3] = __expf(sacc[j][3] - mn1);
            rs0 += sacc[j][0] + sacc[j][1];
            rs1 += sacc[j][2] + sacc[j][3];
        }
        rs0 += __shfl_xor_sync(0xffffffffu, rs0, 1);
        rs0 += __shfl_xor_sync(0xffffffffu, rs0, 2);
        rs1 += __shfl_xor_sync(0xffffffffu, rs1, 1);
        rs1 += __shfl_xor_sync(0xffffffffu, rs1, 2);
        l0 = l0 * a0 + rs0;  l1 = l1 * a1 + rs1;
        m0 = mn0;  m1 = mn1;
        #pragma unroll
        for (int jn = 0; jn < 8; jn++){
            oacc[jn][0] *= a0; oacc[jn][1] *= a0;
            oacc[jn][2] *= a1; oacc[jn][3] *= a1;
        }
        #pragma unroll
        for (int ks = 0; ks < TKV / 16; ks++){
            uint32_t pa[4];
            pa[0] = h2u(sacc[2 * ks    ][0], sacc[2 * ks    ][1]);
            pa[1] = h2u(sacc[2 * ks    ][2], sacc[2 * ks    ][3]);
            pa[2] = h2u(sacc[2 * ks + 1][0], sacc[2 * ks + 1][1]);
            pa[3] = h2u(sacc[2 * ks + 1][2], sacc[2 * ks + 1][3]);
            #pragma unroll
            for (int jp = 0; jp < 4; jp++){
                uint32_t vb[4];
                ldsm_x4_t(vb, vbase + (uint32_t)(ks * 16 * LH) * 2
                              + (vt_ln + jp * 16) * 2);
                mma_f16(oacc[2 * jp    ], pa, vb);
                mma_f16(oacc[2 * jp + 1], pa, vb + 2);
            }
        }
        __syncthreads();
        if (t + 2 < NTILES) loadKV(t % 2, t + 2);
        cp_commit();
    }

    float inv0 = 1.f / l0, inv1 = 1.f / l1;
    __half* Ob = O + ((long)(b * SS + qt * 128 + w * 16)) * CC + h * DHH;
    #pragma unroll
    for (int jn = 0; jn < 8; jn++){
        int col = jn * 8 + 2 * tg;
        *(__half2*)&Ob[(long)(g    ) * CC + col] =
            __floats2half2_rn(oacc[jn][0] * inv0, oacc[jn][1] * inv0);
        *(__half2*)&Ob[(long)(g + 8) * CC + col] =
            __floats2half2_rn(oacc[jn][2] * inv1, oacc[jn][3] * inv1);
    }
}

// =====================================================================
// fp16 NN GEMM (R13, passing).
// OUT: 0=fp32 C(+res), 1=fp16 only (z-select), 2=both,
//      3=final: write transposed fp32 + x residual (C=out, res=x).
// =====================================================================
constexpr int HLA = 72;
constexpr int HLB = 136;
constexpr int HAW = 128 * HLA * 2;
constexpr int HBW = 64 * HLB * 2;
constexpr int H_SMEM = 3 * (HAW + HBW);

template<bool GEGLU, int OUT>
__global__ void hgemm_k(const __half* __restrict__ A,
                        const __half* __restrict__ B0, const __half* __restrict__ B1,
                        const __half* __restrict__ B2, const __half* __restrict__ B3,
                        const float* __restrict__ bias, const float* __restrict__ res,
                        float* __restrict__ C,
                        __half* __restrict__ G0, __half* __restrict__ G1,
                        __half* __restrict__ G2, __half* __restrict__ G3,
                        int M, int N, int K, int lda, int ldb, int ldc){
    constexpr int BK = 64, STAGES = 3;
    extern __shared__ float smf[];
    uint32_t sb = smem_u32(smf);
    uint32_t Abase = sb;
    uint32_t Bbase = sb + 3 * HAW;

    int z = blockIdx.z;
    const __half* Bm = (z == 0) ? B0 : (z == 1) ? B1 : (z == 2) ? B2 : B3;
    __half*       Gh = (z == 0) ? G0 : (z == 1) ? G1 : (z == 2) ? G2 : G3;

    int tid  = threadIdx.x;
    int warp = tid >> 5, lane = tid & 31;
    int g  = lane >> 2;
    int tg = lane & 3;
    int wm = (warp & 1) * 64;
    int wn = (warp >> 1) * 64;
    int row0 = blockIdx.y * 128;
    int col0 = GEGLU ? 0 : blockIdx.x * 128;
    int c0h  = blockIdx.x * 64;

    int lt = lane >> 3, lr = lane & 7;
    uint32_t a_lane = (uint32_t)(((lt & 1) * 8 + lr) * HLA + (lt >> 1) * 8) * 2;
    uint32_t b_lane = (uint32_t)(((lt & 1) * 8 + lr) * HLB + (lt >> 1) * 8) * 2;

    float acc[4][8][4];
    #pragma unroll
    for (int i = 0; i < 4; i++)
        #pragma unroll
        for (int j = 0; j < 8; j++)
            #pragma unroll
            for (int r = 0; r < 4; r++) acc[i][j][r] = 0.f;

    auto loadA = [&](int s, int kt){
        uint32_t base = Abase + s * HAW;
        #pragma unroll
        for (int it = 0; it < 8; it++){
            int c = tid + it * 128;
            int m  = c >> 3;
            int kc = (c & 7) * 8;
            int gm = row0 + m;
            int by = (gm < M) ? 16 : 0;
            const __half* src = by ? (A + (long)gm * lda + kt + kc) : A;
            cp16a(base + (uint32_t)(m * HLA + kc) * 2, src, by);
        }
    };
    auto loadB = [&](int s, int kt){
        uint32_t base = Bbase + s * HBW;
        #pragma unroll
        for (int it = 0; it < 8; it++){
            int c = tid + it * 128;
            int kr = c >> 4;
            int nc = (c & 15) * 8;
            int gk = kt + kr;
            long gn;
            if (GEGLU) gn = (nc < 64) ? (long)(c0h + nc) : (long)(2048 + c0h + nc - 64);
            else       gn = (long)(col0 + nc);
            int by = (gk < K) ? 16 : 0;
            const __half* src = by ? (Bm + (long)gk * ldb + gn) : Bm;
            cp16a(base + (uint32_t)(kr * HLB + nc) * 2, src, by);
        }
    };
    auto compute = [&](int s){
        uint32_t Ab = Abase + s * HAW;
        uint32_t Bb = Bbase + s * HBW;
        #pragma unroll
        for (int ks = 0; ks < 4; ks++){
            uint32_t bf[8][2];
            #pragma unroll
            for (int jp = 0; jp < 4; jp++){
                uint32_t r[4];
                ldsm_x4_t(r, Bb + b_lane +
                          (uint32_t)(ks * 16 * HLB + wn + jp * 16) * 2);
                bf[2*jp  ][0] = r[0]; bf[2*jp  ][1] = r[1];
                bf[2*jp+1][0] = r[2]; bf[2*jp+1][1] = r[3];
            }
            #pragma unroll
            for (int i = 0; i < 4; i++){
                uint32_t af[4];
                ldsm_x4(af, Ab + a_lane +
                        (uint32_t)((wm + i * 16) * HLA + ks * 16) * 2);
                #pragma unroll
                for (int j = 0; j < 8; j++)
                    mma_f16(acc[i][j], af, bf[j]);
            }
        }
    };

    int nk = (K + BK - 1) / BK;
    #pragma unroll
    for (int s = 0; s < STAGES - 1; s++){
        if (s < nk){ loadA(s, s * BK); loadB(s, s * BK); }
        cp_commit();
    }
    for (int t = 0; t < nk; t++){
        cp_wait<STAGES - 2>();
        __syncthreads();
        int tn = t + STAGES - 1;
        if (tn < nk){ loadA(tn % STAGES, tn * BK); loadB(tn % STAGES, tn * BK); }
        cp_commit();
        compute(t % STAGES);
    }

    if (OUT == 3){
        // final: out[(b*CC + n)*SS + p] = acc + bias[n] + x[same], p = m % SS
        #pragma unroll
        for (int i = 0; i < 4; i++){
            int m0i = row0 + wm + i * 16 + g;
            int m1i = m0i + 8;
            long pb0 = ((long)(m0i >> 10) * CC) * SS + (m0i & 1023);
            long pb1 = ((long)(m1i >> 10) * CC) * SS + (m1i & 1023);
            #pragma unroll
            for (int j = 0; j < 8; j++){
                int c0 = col0 + wn + j * 8 + 2 * tg;
                float* a4 = acc[i][j];
                float b0 = bias[c0], b1v = bias[c0 + 1];
                long o00 = pb0 + (long)c0 * SS, o01 = o00 + SS;
                long o10 = pb1 + (long)c0 * SS, o11 = o10 + SS;
                C[o00] = a4[0] + b0  + res[o00];
                C[o01] = a4[1] + b1v + res[o01];
                C[o10] = a4[2] + b0  + res[o10];
                C[o11] = a4[3] + b1v + res[o11];
            }
        }
    } else if (!GEGLU){
        #pragma unroll
        for (int i = 0; i < 4; i++){
            int r0 = row0 + wm + i * 16 + g;
            int r1 = r0 + 8;
            #pragma unroll
            for (int j = 0; j < 8; j++){
                int c0 = col0 + wn + j * 8 + 2 * tg;
                float* a4 = acc[i][j];
                float b0 = 0.f, b1v = 0.f;
                if (bias){ b0 = bias[c0]; b1v = bias[c0 + 1]; }
                if (r0 < M){
                    float2 v = {a4[0] + b0, a4[1] + b1v};
                    if (res){
                        float2 rr = *(const float2*)&res[(long)r0 * ldc + c0];
                        v.x += rr.x; v.y += rr.y;
                    }
                    if (OUT != 1) *(float2*)&C[(long)r0 * ldc + c0] = v;
                    if (OUT != 0) *(__half2*)&Gh[(long)r0 * ldc + c0] = __floats2half2_rn(v.x, v.y);
                }
                if (r1 < M){
                    float2 v = {a4[2] + b0, a4[3] + b1v};
                    if (res){
                        float2 rr = *(const float2*)&res[(long)r1 * ldc + c0];
                        v.x += rr.x; v.y += rr.y;
                    }
                    if (OUT != 1) *(float2*)&C[(long)r1 * ldc + c0] = v;
                    if (OUT != 0) *(__half2*)&Gh[(long)r1 * ldc + c0] = __floats2half2_rn(v.x, v.y);
                }
            }
        }
    } else {
        constexpr int LE = 68;
        float* ex = smf;
        __syncthreads();
        if (wn == 64){
            #pragma unroll
            for (int i = 0; i < 4; i++){
                int lr0 = wm + i * 16 + g, lr1 = lr0 + 8;
                #pragma unroll
                for (int j = 0; j < 8; j++){
                    int gc = j * 8 + 2 * tg;
                    float bg0 = bias[c0h + gc + 2048];
                    float bg1 = bias[c0h + gc + 1 + 2048];
                    ex[lr0 * LE + gc    ] = gelu_exact(acc[i][j][0] + bg0);
                    ex[lr0 * LE + gc + 1] = gelu_exact(acc[i][j][1] + bg1);
                    ex[lr1 * LE + gc    ] = gelu_exact(acc[i][j][2] + bg0);
                    ex[lr1 * LE + gc + 1] = gelu_exact(acc[i][j][3] + bg1);
                }
            }
        }
        __syncthreads();
        if (wn == 0){
            #pragma unroll
            for (int i = 0; i < 4; i++){
                int lr0 = wm + i * 16 + g, lr1 = lr0 + 8;
                long gr0 = row0 + lr0, gr1 = row0 + lr1;
                #pragma unroll
                for (int j = 0; j < 8; j++){
                    int lc = j * 8 + 2 * tg;
                    float bu0 = bias[c0h + lc], bu1 = bias[c0h + lc + 1];
                    *(__half2*)&G0[gr0 * ldc + c0h + lc] = __floats2half2_rn(
                        (acc[i][j][0] + bu0) * ex[lr0 * LE + lc],
                        (acc[i][j][1] + bu1) * ex[lr0 * LE + lc + 1]);
                    *(__half2*)&G0[gr1 * ldc + c0h + lc] = __floats2half2_rn(
                        (acc[i][j][2] + bu0) * ex[lr1 * LE + lc],
                        (acc[i][j][3] + bu1) * ex[lr1 * LE + lc + 1]);
                }
            }
        }
    }
}

// ---------------- launch helpers ----------------
static void hgemm(const __half* A, const __half* W, const float* bias, const float* res,
                  float* C, int M, int N, int K, int lda, int ldb, int ldc){
    cudaFuncSetAttribute(hgemm_k<false,0>,
                         cudaFuncAttributeMaxDynamicSharedMemorySize, H_SMEM);
    dim3 g((N + 127) / 128, (M + 127) / 128, 1);
    hgemm_k<false,0><<<g, 128, H_SMEM>>>(A, W, W, W, W, bias, res, C,
                                         nullptr, nullptr, nullptr, nullptr,
                                         M, N, K, lda, ldb, ldc);
}
static void hgemm_h16z(const __half* A,
                       const __half* W0, const __half* W1, const __half* W2, const __half* W3,
                       __half* C0, __half* C1, __half* C2, __half* C3, int nz,
                       int M, int N, int K, int lda, int ldb, int ldc){
    cudaFuncSetAttribute(hgemm_k<false,1>,
                         cudaFuncAttributeMaxDynamicSharedMemorySize, H_SMEM);
    dim3 g((N + 127) / 128, (M + 127) / 128, nz);
    hgemm_k<false,1><<<g, 128, H_SMEM>>>(A, W0, W1, W2, W3, nullptr, nullptr, nullptr,
                                         C0, C1, C2, C3, M, N, K, lda, ldb, ldc);
}
static void hgemm_wh(const __half* A, const __half* W, const float* bias, const float* res,
                     float* C, __half* Ch, int M, int N, int K, int lda, int ldb, int ldc){
    cudaFuncSetAttribute(hgemm_k<false,2>,
                         cudaFuncAttributeMaxDynamicSharedMemorySize, H_SMEM);
    dim3 g((N + 127) / 128, (M + 127) / 128, 1);
    hgemm_k<false,2><<<g, 128, H_SMEM>>>(A, W, W, W, W, bias, res, C,
                                         Ch, Ch, Ch, Ch, M, N, K, lda, ldb, ldc);
}
static void hgemm_final(const __half* A, const __half* W, const float* bias,
                        const float* x, float* out){
    cudaFuncSetAttribute(hgemm_k<false,3>,
                         cudaFuncAttributeMaxDynamicSharedMemorySize, H_SMEM);
    dim3 g(CC / 128, MM / 128, 1);
    hgemm_k<false,3><<<g, 128, H_SMEM>>>(A, W, W, W, W, bias, x, out,
                                         nullptr, nullptr, nullptr, nullptr,
                                         MM, CC, CC, CC, CC, CC);
}
static void hgemm_geglu(const __half* A, const __half* W1, const float* b1, __half* G){
    cudaFuncSetAttribute(hgemm_k<true,0>,
                         cudaFuncAttributeMaxDynamicSharedMemorySize, H_SMEM);
    dim3 g(2048 / 64, MM / 128, 1);
    hgemm_k<true,0><<<g, 128, H_SMEM>>>(A, W1, W1, W1, W1, b1, nullptr, nullptr,
                                        G, G, G, G, MM, 4096, CC, CC, 4096, 2048);
}

extern "C" void kernel_launch(void* const* d_in, const int* in_sizes, int n_in,
                              void* d_out, int out_size){
    (void)in_sizes; (void)n_in; (void)out_size;
    const float* x      = (const float*)d_in[0];
    const float* cond   = (const float*)d_in[1];
    const float* gn_s   = (const float*)d_in[2];
    const float* gn_b   = (const float*)d_in[3];
    const float* pin_w  = (const float*)d_in[4];
    const float* pin_b  = (const float*)d_in[5];
    const float* pout_w = (const float*)d_in[6];
    const float* pout_b = (const float*)d_in[7];
    const float* ln1_s  = (const float*)d_in[8];
    const float* ln1_b  = (const float*)d_in[9];
    const float* sa_wq  = (const float*)d_in[10];
    const float* sa_wk  = (const float*)d_in[11];
    const float* sa_wv  = (const float*)d_in[12];
    const float* sa_wo  = (const float*)d_in[13];
    const float* sa_bo  = (const float*)d_in[14];
    const float* ln2_s  = (const float*)d_in[15];
    const float* ln2_b  = (const float*)d_in[16];
    const float* ca_wq  = (const float*)d_in[17];
    const float* ca_wk  = (const float*)d_in[18];
    const float* ca_wv  = (const float*)d_in[19];
    const float* ca_wo  = (const float*)d_in[20];
    const float* ca_bo  = (const float*)d_in[21];
    const float* ln3_s  = (const float*)d_in[22];
    const float* ln3_b  = (const float*)d_in[23];
    const float* ff_w1  = (const float*)d_in[24];
    const float* ff_b1  = (const float*)d_in[25];
    const float* ff_w2  = (const float*)d_in[26];
    const float* ff_b2  = (const float*)d_in[27];
    float* out = (float*)d_out;

    float  *p_t, *p_qf, *p_kf, *p_vf;
    __half *p_tn, *p_ao, *p_gg, *p_w16;
    cudaGetSymbolAddress((void**)&p_t,    g_t);
    cudaGetSymbolAddress((void**)&p_qf,   g_q);
    cudaGetSymbolAddress((void**)&p_kf,   g_k);
    cudaGetSymbolAddress((void**)&p_vf,   g_v);
    cudaGetSymbolAddress((void**)&p_tn,   g_tn_h);
    cudaGetSymbolAddress((void**)&p_ao,   g_ao_h);
    cudaGetSymbolAddress((void**)&p_gg,   g_gg_h);
    cudaGetSymbolAddress((void**)&p_w16,  g_w16);
    __half* p_q16 = (__half*)p_qf;
    __half* p_k16 = (__half*)p_kf;
    __half* p_v16 = (__half*)p_vf;

    // ---- fp16 arena layout ----
    const size_t S512 = 512 * 512, S768 = 768 * 512;
    const size_t SW1 = 512 * 4096, SW2 = 2048 * 512;
    __half* pin16  = p_w16;
    __half* pout16 = pin16 + S512;
    const size_t LSZ = 6 * S512 + 2 * S768 + SW1 + SW2;
    __half* lbase0 = pout16 + S512;
    auto LW = [&](int l){ return lbase0 + (size_t)l * LSZ; };
    __half* cond16 = lbase0 + 2 * LSZ;
    __half* p_t16  = cond16 + (size_t)BB * NCC * DCC;
    const size_t SKV = (size_t)MKV * CC;
    __half* ckv_k0 = p_t16 + (size_t)MM * CC;
    __half* ckv_v0 = ckv_k0 + SKV;
    __half* ckv_k1 = ckv_v0 + SKV;
    __half* ckv_v1 = ckv_k1 + SKV;

    // ---- single batched fp32->fp16 conversion ----
    {
        CvtBatch cb{};
        int zi = 0;
        auto add = [&](const float* s, __half* d, size_t n){
            cb.s[zi] = s; cb.d[zi] = d; cb.n4[zi] = (int)(n / 4); zi++;
        };
        add(pin_w,  pin16,  S512);
        add(pout_w, pout16, S512);
        for (int l = 0; l < 2; l++){
            __half* b = LW(l);
            add(sa_wq + (long)l * S512, b,             S512);
            add(sa_wk + (long)l * S512, b + S512,      S512);
            add(sa_wv + (long)l * S512, b + 2 * S512,  S512);
            add(sa_wo + (long)l * S512, b + 3 * S512,  S512);
            add(ca_wq + (long)l * S512, b + 4 * S512,  S512);
            add(ca_wo + (long)l * S512, b + 5 * S512,  S512);
            add(ca_wk + (long)l * S768, b + 6 * S512,         S768);
            add(ca_wv + (long)l * S768, b + 6 * S512 + S768,  S768);
            add(ff_w1 + (long)l * SW1,  b + 6 * S512 + 2 * S768,       SW1);
            add(ff_w2 + (long)l * SW2,  b + 6 * S512 + 2 * S768 + SW1, SW2);
        }
        add(cond, cond16, (size_t)BB * NCC * DCC);
        int maxb = (int)((SW1 / 4 + 255) / 256);
        cvt_k<<<dim3(maxb, 1, zi), 256>>>(cb);
    }

    // ---- precompute ALL cross-attn K/V ----
    hgemm_h16z(cond16,
               LW(0) + 6 * S512, LW(0) + 6 * S512 + S768,
               LW(1) + 6 * S512, LW(1) + 6 * S512 + S768,
               ckv_k0, ckv_v0, ckv_k1, ckv_v1, 4,
               MKV, CC, DCC, DCC, CC, CC);

    // flash smem
    constexpr int SM_SELF16  = (128 * 72 + 2 * 64 * 72 + 2 * 64 * 72) * 2;
    constexpr int SM_CROSS16 = (128 * 72 + 80 * 72 + 80 * 72) * 2;
    cudaFuncSetAttribute(flash16_k<64, 1024, 16, 2>,
                         cudaFuncAttributeMaxDynamicSharedMemorySize, SM_SELF16);
    cudaFuncSetAttribute(flash16_k<80, 77, 1, 1>,
                         cudaFuncAttributeMaxDynamicSharedMemorySize, SM_CROSS16);

    // fused groupnorm (stats + apply + transpose)
    gn_fused_k<<<BB * 32, 256>>>(x, gn_s, gn_b, p_tn);
    hgemm(p_tn, pin16, pin_b, nullptr, p_t, MM, CC, CC, CC, CC, CC);

    for (int l = 0; l < 2; l++){
        __half* b   = LW(l);
        __half* wq16  = b;
        __half* wk16  = b + S512;
        __half* wv16  = b + 2 * S512;
        __half* wo16  = b + 3 * S512;
        __half* cwq16 = b + 4 * S512;
        __half* cwo16 = b + 5 * S512;
        __half* w116  = b + 6 * S512 + 2 * S768;
        __half* w216  = w116 + SW1;
        const float* bo  = sa_bo + (long)l * CC;
        const float* cbo = ca_bo + (long)l * CC;
        const float* b1  = ff_b1 + (long)l * 4096;
        const float* b2  = ff_b2 + (long)l * CC;
        __half* ck = (l == 0) ? ckv_k0 : ckv_k1;
        __half* cv = (l == 0) ? ckv_v0 : ckv_v1;

        // ---- self-attention ----
        layernorm_k<<<MM / 8, 256>>>(p_t, ln1_s + l * CC, ln1_b + l * CC, p_tn);
        hgemm_h16z(p_tn, wq16, wk16, wv16, wq16,
                   p_q16, p_k16, p_v16, p_q16, 3,
                   MM, CC, CC, CC, CC, CC);
        flash16_k<64, 1024, 16, 2><<<dim3(SS / 128, BB * NHH), 256, SM_SELF16>>>(
            p_q16, p_k16, p_v16, p_ao, (long)SS * CC);
        hgemm(p_ao, wo16, bo, p_t, p_t, MM, CC, CC, CC, CC, CC);

        // ---- cross-attention ----
        layernorm_k<<<MM / 8, 256>>>(p_t, ln2_s + l * CC, ln2_b + l * CC, p_tn);
        hgemm_h16z(p_tn, cwq16, cwq16, cwq16, cwq16,
                   p_q16, p_q16, p_q16, p_q16, 1,
                   MM, CC, CC, CC, CC, CC);
        flash16_k<80, 77, 1, 1><<<dim3(SS / 128, BB * NHH), 256, SM_CROSS16>>>(
            p_q16, ck, cv, p_ao, (long)NCC * CC);
        hgemm(p_ao, cwo16, cbo, p_t, p_t, MM, CC, CC, CC, CC, CC);

        // ---- FFN (GEGLU fused) ----
        layernorm_k<<<MM / 8, 256>>>(p_t, ln3_s + l * CC, ln3_b + l * CC, p_tn);
        hgemm_geglu(p_tn, w116, b1, p_gg);
        if (l == 1)
            hgemm_wh(p_gg, w216, b2, p_t, p_t, p_t16, MM, CC, 2048, 2048, CC, CC);
        else
            hgemm(p_gg, w216, b2, p_t, p_t, MM, CC, 2048, 2048, CC, CC);
    }

    // final: pout GEMM with fused transpose + x residual epilogue
    hgemm_final(p_t16, pout16, pout_b, x, out);
}

// round 15
// speedup vs baseline: 2.2219x; 1.1185x over previous
#include <cuda_runtime.h>
#include <cuda_fp16.h>
#include <math.h>
#include <stdint.h>

// ---------------- problem constants ----------------
constexpr int BB   = 8;
constexpr int CC   = 512;
constexpr int SS   = 1024;
constexpr int NHH  = 8;
constexpr int DHH  = 64;
constexpr int NCC  = 77;
constexpr int DCC  = 768;
constexpr int MM   = BB * SS;  // 8192
constexpr int MKV  = BB * NCC; // 616

// ---------------- scratch ----------------
__device__ __align__(256) float  g_t    [ (long)MM * CC ];
__device__ __align__(256) float  g_q    [ (long)MM * CC ];
__device__ __align__(256) float  g_k    [ (long)MM * CC ];
__device__ __align__(256) float  g_v    [ (long)MM * CC ];
__device__ __align__(256) __half g_tn_h [ (long)MM * CC ];
__device__ __align__(256) __half g_ao_h [ (long)MM * CC ];
__device__ __align__(256) __half g_gg_h [ (long)MM * 2048 ];
__device__ __align__(256) __half g_w16  [ 17500160 ];

// ---------------- reductions ----------------
__inline__ __device__ float warpSum(float v){
    #pragma unroll
    for (int o = 16; o > 0; o >>= 1) v += __shfl_xor_sync(0xffffffffu, v, o);
    return v;
}

// ---------------- cp.async ----------------
__device__ __forceinline__ uint32_t smem_u32(const void* p){
    return (uint32_t)__cvta_generic_to_shared(p);
}
__device__ __forceinline__ void cp16a(uint32_t dst, const void* src, int bytes){
    asm volatile("cp.async.cg.shared.global [%0], [%1], 16, %2;\n"
                 :: "r"(dst), "l"(src), "r"(bytes));
}
__device__ __forceinline__ void cp_commit(){ asm volatile("cp.async.commit_group;\n"); }
template<int N> __device__ __forceinline__ void cp_wait(){
    asm volatile("cp.async.wait_group %0;\n" :: "n"(N));
}

// ---------------- ldmatrix / mma fp16 ----------------
__device__ __forceinline__ void ldsm_x4(uint32_t* r, uint32_t addr){
    asm volatile("ldmatrix.sync.aligned.m8n8.x4.shared.b16 {%0,%1,%2,%3}, [%4];"
        : "=r"(r[0]), "=r"(r[1]), "=r"(r[2]), "=r"(r[3]) : "r"(addr));
}
__device__ __forceinline__ void ldsm_x4_t(uint32_t* r, uint32_t addr){
    asm volatile("ldmatrix.sync.aligned.m8n8.x4.trans.shared.b16 {%0,%1,%2,%3}, [%4];"
        : "=r"(r[0]), "=r"(r[1]), "=r"(r[2]), "=r"(r[3]) : "r"(addr));
}
__device__ __forceinline__ void mma_f16(float* c, const uint32_t* a, const uint32_t* b){
    asm volatile("mma.sync.aligned.m16n8k16.row.col.f32.f16.f16.f32 "
        "{%0,%1,%2,%3}, {%4,%5,%6,%7}, {%8,%9}, {%0,%1,%2,%3};"
        : "+f"(c[0]), "+f"(c[1]), "+f"(c[2]), "+f"(c[3])
        : "r"(a[0]), "r"(a[1]), "r"(a[2]), "r"(a[3]), "r"(b[0]), "r"(b[1]));
}
__device__ __forceinline__ uint32_t h2u(float a, float b){
    __half2 h = __floats2half2_rn(a, b);
    return *(uint32_t*)&h;
}

__inline__ __device__ float gelu_exact(float x){
    return 0.5f * x * (1.f + erff(x * 0.70710678118654752f));
}

// ---------------- fp32 -> fp16 batched convert (single launch) ----------------
struct CvtBatch { const float* s[24]; __half* d[24]; int n4[24]; };
__global__ void cvt_k(CvtBatch cb){
    int zi = blockIdx.z;
    int n4 = cb.n4[zi];
    int i = blockIdx.x * blockDim.x + threadIdx.x;
    if (i >= n4) return;
    const float4* s = (const float4*)cb.s[zi];
    __half2* d = (__half2*)cb.d[zi];
    float4 v = s[i];
    d[2 * i]     = __floats2half2_rn(v.x, v.y);
    d[2 * i + 1] = __floats2half2_rn(v.z, v.w);
}

// ---------------- fused groupnorm (stats + apply + transpose) ----------------
__global__ void gn_fused_k(const float* __restrict__ x,
                           const float* __restrict__ gs, const float* __restrict__ gb,
                           __half* __restrict__ out){
    __shared__ float sm[16384];
    __shared__ float shs[8], shq[8], s_mean, s_rstd;
    int b = blockIdx.x >> 5, grp = blockIdx.x & 31;
    long base = ((long)b * CC + grp * 16) * SS;
    int tid = threadIdx.x;

    float s = 0.f, q = 0.f;
    #pragma unroll
    for (int i = 0; i < 16; i++){
        int c = tid + i * 256;
        float4 v = ((const float4*)(x + base))[c];
        ((float4*)sm)[c] = v;
        s += v.x + v.y + v.z + v.w;
        q += v.x*v.x + v.y*v.y + v.z*v.z + v.w*v.w;
    }
    s = warpSum(s); q = warpSum(q);
    int w = tid >> 5, l = tid & 31;
    if (l == 0){ shs[w] = s; shq[w] = q; }
    __syncthreads();
    if (tid < 32){
        s = (l < 8) ? shs[l] : 0.f;
        q = (l < 8) ? shq[l] : 0.f;
        s = warpSum(s); q = warpSum(q);
        if (l == 0){
            float mean = s * (1.f / 16384.f);
            s_mean = mean;
            s_rstd = rsqrtf(q * (1.f / 16384.f) - mean * mean + 1e-6f);
        }
    }
    __syncthreads();
    float mean = s_mean, rstd = s_rstd;
    float sc[2], bi[2];
    int c2 = tid & 7;
    sc[0] = gs[grp * 16 + 2 * c2];     bi[0] = gb[grp * 16 + 2 * c2];
    sc[1] = gs[grp * 16 + 2 * c2 + 1]; bi[1] = gb[grp * 16 + 2 * c2 + 1];
    __half2* ob = (__half2*)(out + (long)b * SS * CC + grp * 16) + c2;
    #pragma unroll
    for (int i = 0; i < 32; i++){
        int p = (tid >> 3) + i * 32;
        float v0 = (sm[(2 * c2    ) * 1024 + p] - mean) * rstd * sc[0] + bi[0];
        float v1 = (sm[(2 * c2 + 1) * 1024 + p] - mean) * rstd * sc[1] + bi[1];
        ob[(long)p * (CC / 2)] = __floats2half2_rn(v0, v1);
    }
}

// ---------------- layernorm (warp per row, fp32 in, fp16 out) ----------------
__global__ void layernorm_k(const float* __restrict__ in, const float* __restrict__ sc,
                            const float* __restrict__ bi, __half* __restrict__ out){
    int row = blockIdx.x * 8 + (threadIdx.x >> 5);
    int lane = threadIdx.x & 31;
    const float4* x4 = (const float4*)(in + (long)row * CC);
    float4 xv[4];
    float s = 0.f, q = 0.f;
    #pragma unroll
    for (int t = 0; t < 4; t++){
        xv[t] = x4[lane + t * 32];
        s += xv[t].x + xv[t].y + xv[t].z + xv[t].w;
        q += xv[t].x*xv[t].x + xv[t].y*xv[t].y + xv[t].z*xv[t].z + xv[t].w*xv[t].w;
    }
    s = warpSum(s); q = warpSum(q);
    float mean = s * (1.f / 512.f);
    float rstd = rsqrtf(q * (1.f / 512.f) - mean * mean + 1e-5f);
    __half2* o2 = (__half2*)(out + (long)row * CC);
    #pragma unroll
    for (int t = 0; t < 4; t++){
        int c = lane + t * 32;
        float4 sv = ((const float4*)sc)[c];
        float4 bv = ((const float4*)bi)[c];
        o2[2 * c]     = __floats2half2_rn((xv[t].x - mean) * rstd * sv.x + bv.x,
                                          (xv[t].y - mean) * rstd * sv.y + bv.y);
        o2[2 * c + 1] = __floats2half2_rn((xv[t].z - mean) * rstd * sv.z + bv.z,
                                          (xv[t].w - mean) * rstd * sv.w + bv.w);
    }
}

// =====================================================================
// fp16 flash attention (R12, passing) — unchanged.
// =====================================================================
template<int TKV, int KVLEN, int NTILES, int NSTAGE>
__global__ void flash16_k(const __half* __restrict__ Q, const __half* __restrict__ K,
                          const __half* __restrict__ V, __half* __restrict__ O,
                          long kv_bstride){
    constexpr int NT = TKV / 8;
    constexpr int LH = 72;
    extern __shared__ char smraw[];
    __half* Qs = (__half*)smraw;
    __half* Ks = Qs + 128 * LH;
    __half* Vs = Ks + NSTAGE * TKV * LH;

    int tid = threadIdx.x;
    int w = tid >> 5, lane = tid & 31;
    int g = lane >> 2, tg = lane & 3;
    int lt = lane >> 3, lr = lane & 7;
    int qt = blockIdx.x;
    int b = blockIdx.y / NHH, h = blockIdx.y % NHH;

    const __half* Qb = Q + ((long)(b * SS + qt * 128)) * CC + h * DHH;
    const __half* Kb = K + (long)b * kv_bstride + h * DHH;
    const __half* Vb = V + (long)b * kv_bstride + h * DHH;

    uint32_t sQ = smem_u32(Qs), sK = smem_u32(Ks), sV = smem_u32(Vs);

    uint32_t a_ln  = (uint32_t)(((lt & 1) * 8 + lr) * LH + (lt >> 1) * 8);
    uint32_t nk_ln = (uint32_t)(((lt >> 1) * 8 + lr) * LH + (lt & 1) * 8);
    uint32_t vt_ln = (uint32_t)(((lt & 1) * 8 + lr) * LH + (lt >> 1) * 8);

    auto loadQ = [&](){
        #pragma unroll
        for (int i = 0; i < 4; i++){
            int c = tid + i * 256;
            int row = c >> 3, kc = (c & 7) * 8;
            cp16a(sQ + (uint32_t)(row * LH + kc) * 2, Qb + (long)row * CC + kc, 16);
        }
    };
    auto loadKV = [&](int s, int t){
        constexpr int CH = TKV * 8;
        #pragma unroll
        for (int i = 0; i < (CH + 255) / 256; i++){
            int c = tid + i * 256;
            if (c < CH){
                int row = c >> 3, kc = (c & 7) * 8;
                int r = t * TKV + row;
                int by = (r < KVLEN) ? 16 : 0;
                const __half* ks = by ? (Kb + (long)r * CC + kc) : Kb;
                const __half* vs = by ? (Vb + (long)r * CC + kc) : Vb;
                cp16a(sK + (uint32_t)((s * TKV + row) * LH + kc) * 2, ks, by);
                cp16a(sV + (uint32_t)((s * TKV + row) * LH + kc) * 2, vs, by);
            }
        }
    };

    loadQ(); loadKV(0, 0); cp_commit();
    if (NTILES > 1){ loadKV(1, 1); cp_commit(); }

    uint32_t qa[4][4];
    float oacc[8][4];
    #pragma unroll
    for (int j = 0; j < 8; j++)
        #pragma unroll
        for (int r = 0; r < 4; r++) oacc[j][r] = 0.f;
    float m0 = -1e30f, m1 = -1e30f, l0 = 0.f, l1 = 0.f;

    for (int t = 0; t < NTILES; t++){
        if (t + 1 < NTILES) cp_wait<1>(); else cp_wait<0>();
        __syncthreads();
        if (t == 0){
            uint32_t qbase = sQ + (uint32_t)(w * 16 * LH) * 2;
            #pragma unroll
            for (int ks = 0; ks < 4; ks++)
                ldsm_x4(qa[ks], qbase + (a_ln + ks * 16) * 2);
        }
        uint32_t kbase = sK + (uint32_t)((t % NSTAGE) * TKV * LH) * 2;
        uint32_t vbase = sV + (uint32_t)((t % NSTAGE) * TKV * LH) * 2;

        float sacc[NT][4];
        #pragma unroll
        for (int j = 0; j < NT; j++)
            #pragma unroll
            for (int r = 0; r < 4; r++) sacc[j][r] = 0.f;
        #pragma unroll
        for (int ks = 0; ks < 4; ks++){
            #pragma unroll
            for (int jp = 0; jp < NT / 2; jp++){
                uint32_t kb[4];
                ldsm_x4(kb, kbase + (uint32_t)(jp * 16 * LH) * 2 + (nk_ln + ks * 16) * 2);
                mma_f16(sacc[2 * jp    ], qa[ks], kb);
                mma_f16(sacc[2 * jp + 1], qa[ks], kb + 2);
            }
        }
        if (KVLEN < NTILES * TKV && t == NTILES - 1){
            #pragma unroll
            for (int j = 0; j < NT; j++){
                int col = t * TKV + j * 8 + 2 * tg;
                if (col     >= KVLEN){ sacc[j][0] = -1e30f; sacc[j][2] = -1e30f; }
                if (col + 1 >= KVLEN){ sacc[j][1] = -1e30f; sacc[j][3] = -1e30f; }
            }
        }
        float rm0 = -1e30f, rm1 = -1e30f;
        #pragma unroll
        for (int j = 0; j < NT; j++){
            rm0 = fmaxf(rm0, fmaxf(sacc[j][0], sacc[j][1]));
            rm1 = fmaxf(rm1, fmaxf(sacc[j][2], sacc[j][3]));
        }
        rm0 = fmaxf(rm0, __shfl_xor_sync(0xffffffffu, rm0, 1));
        rm0 = fmaxf(rm0, __shfl_xor_sync(0xffffffffu, rm0, 2));
        rm1 = fmaxf(rm1, __shfl_xor_sync(0xffffffffu, rm1, 1));
        rm1 = fmaxf(rm1, __shfl_xor_sync(0xffffffffu, rm1, 2));
        float mn0 = fmaxf(m0, rm0), mn1 = fmaxf(m1, rm1);
        float a0 = __expf(m0 - mn0), a1 = __expf(m1 - mn1);
        float rs0 = 0.f, rs1 = 0.f;
        #pragma unroll
        for (int j = 0; j < NT; j++){
            sacc[j][0] = __expf(sacc[j][0] - mn0);
            sacc[j][1] = __expf(sacc[j][1] - mn0);
            sacc[j][2] = __expf(sacc[j][2] - mn1);
            sacc[j][3] = __expf(sacc[j][3] - mn1);
            rs0 += sacc[j][0] + sacc[j][1];
            rs1 += sacc[j][2] + sacc[j][3];
        }
        rs0 += __shfl_xor_sync(0xffffffffu, rs0, 1);
        rs0 += __shfl_xor_sync(0xffffffffu, rs0, 2);
        rs1 += __shfl_xor_sync(0xffffffffu, rs1, 1);
        rs1 += __shfl_xor_sync(0xffffffffu, rs1, 2);
        l0 = l0 * a0 + rs0;  l1 = l1 * a1 + rs1;
        m0 = mn0;  m1 = mn1;
        #pragma unroll
        for (int jn = 0; jn < 8; jn++){
            oacc[jn][0] *= a0; oacc[jn][1] *= a0;
            oacc[jn][2] *= a1; oacc[jn][3] *= a1;
        }
        #pragma unroll
        for (int ks = 0; ks < TKV / 16; ks++){
            uint32_t pa[4];
            pa[0] = h2u(sacc[2 * ks    ][0], sacc[2 * ks    ][1]);
            pa[1] = h2u(sacc[2 * ks    ][2], sacc[2 * ks    ][3]);
            pa[2] = h2u(sacc[2 * ks + 1][0], sacc[2 * ks + 1][1]);
            pa[3] = h2u(sacc[2 * ks + 1][2], sacc[2 * ks + 1][3]);
            #pragma unroll
            for (int jp = 0; jp < 4; jp++){
                uint32_t vb[4];
                ldsm_x4_t(vb, vbase + (uint32_t)(ks * 16 * LH) * 2
                              + (vt_ln + jp * 16) * 2);
                mma_f16(oacc[2 * jp    ], pa, vb);
                mma_f16(oacc[2 * jp + 1], pa, vb + 2);
            }
        }
        __syncthreads();
        if (t + 2 < NTILES) loadKV(t % 2, t + 2);
        cp_commit();
    }

    float inv0 = 1.f / l0, inv1 = 1.f / l1;
    __half* Ob = O + ((long)(b * SS + qt * 128 + w * 16)) * CC + h * DHH;
    #pragma unroll
    for (int jn = 0; jn < 8; jn++){
        int col = jn * 8 + 2 * tg;
        *(__half2*)&Ob[(long)(g    ) * CC + col] =
            __floats2half2_rn(oacc[jn][0] * inv0, oacc[jn][1] * inv0);
        *(__half2*)&Ob[(long)(g + 8) * CC + col] =
            __floats2half2_rn(oacc[jn][2] * inv1, oacc[jn][3] * inv1);
    }
}

// =====================================================================
// fp16 NN GEMM — RETILED: 256 thr, 8 warps of 64x32 (was 4 of 64x64).
// 2 blocks/SM x 8 warps = 16 warps/SM for latency hiding.
// OUT: 0=fp32 C(+res), 1=fp16 only (z-select), 2=both, 3=final transpose+x.
// =====================================================================
constexpr int HLA = 72;
constexpr int HLB = 136;
constexpr int HAW = 128 * HLA * 2;
constexpr int HBW = 64 * HLB * 2;
constexpr int H_SMEM = 3 * (HAW + HBW);

template<bool GEGLU, int OUT>
__global__ void __launch_bounds__(256, 2)
hgemm_k(const __half* __restrict__ A,
        const __half* __restrict__ B0, const __half* __restrict__ B1,
        const __half* __restrict__ B2, const __half* __restrict__ B3,
        const float* __restrict__ bias, const float* __restrict__ res,
        float* __restrict__ C,
        __half* __restrict__ G0, __half* __restrict__ G1,
        __half* __restrict__ G2, __half* __restrict__ G3,
        int M, int N, int K, int lda, int ldb, int ldc){
    constexpr int BK = 64, STAGES = 3;
    extern __shared__ float smf[];
    uint32_t sb = smem_u32(smf);
    uint32_t Abase = sb;
    uint32_t Bbase = sb + 3 * HAW;

    int z = blockIdx.z;
    const __half* Bm = (z == 0) ? B0 : (z == 1) ? B1 : (z == 2) ? B2 : B3;
    __half*       Gh = (z == 0) ? G0 : (z == 1) ? G1 : (z == 2) ? G2 : G3;

    int tid  = threadIdx.x;
    int warp = tid >> 5, lane = tid & 31;
    int g  = lane >> 2;
    int tg = lane & 3;
    int wm = (warp & 1) * 64;          // 2 warps along M
    int wn = (warp >> 1) * 32;         // 4 warps along N
    int row0 = blockIdx.y * 128;
    int col0 = GEGLU ? 0 : blockIdx.x * 128;
    int c0h  = blockIdx.x * 64;

    int lt = lane >> 3, lr = lane & 7;
    uint32_t a_lane = (uint32_t)(((lt & 1) * 8 + lr) * HLA + (lt >> 1) * 8) * 2;
    uint32_t b_lane = (uint32_t)(((lt & 1) * 8 + lr) * HLB + (lt >> 1) * 8) * 2;

    float acc[4][4][4];
    #pragma unroll
    for (int i = 0; i < 4; i++)
        #pragma unroll
        for (int j = 0; j < 4; j++)
            #pragma unroll
            for (int r = 0; r < 4; r++) acc[i][j][r] = 0.f;

    auto loadA = [&](int s, int kt){
        uint32_t base = Abase + s * HAW;
        #pragma unroll
        for (int it = 0; it < 4; it++){          // 128 rows * 8 chunks / 256 thr
            int c = tid + it * 256;
            int m  = c >> 3;
            int kc = (c & 7) * 8;
            int gm = row0 + m;
            int by = (gm < M) ? 16 : 0;
            const __half* src = by ? (A + (long)gm * lda + kt + kc) : A;
            cp16a(base + (uint32_t)(m * HLA + kc) * 2, src, by);
        }
    };
    auto loadB = [&](int s, int kt){
        uint32_t base = Bbase + s * HBW;
        #pragma unroll
        for (int it = 0; it < 4; it++){          // 64 rows * 16 chunks / 256 thr
            int c = tid + it * 256;
            int kr = c >> 4;
            int nc = (c & 15) * 8;
            int gk = kt + kr;
            long gn;
            if (GEGLU) gn = (nc < 64) ? (long)(c0h + nc) : (long)(2048 + c0h + nc - 64);
            else       gn = (long)(col0 + nc);
            int by = (gk < K) ? 16 : 0;
            const __half* src = by ? (Bm + (long)gk * ldb + gn) : Bm;
            cp16a(base + (uint32_t)(kr * HLB + nc) * 2, src, by);
        }
    };
    auto compute = [&](int s){
        uint32_t Ab = Abase + s * HAW;
        uint32_t Bb = Bbase + s * HBW;
        #pragma unroll
        for (int ks = 0; ks < 4; ks++){
            uint32_t bf[4][2];
            #pragma unroll
            for (int jp = 0; jp < 2; jp++){
                uint32_t r[4];
                ldsm_x4_t(r, Bb + b_lane +
                          (uint32_t)(ks * 16 * HLB + wn + jp * 16) * 2);
                bf[2*jp  ][0] = r[0]; bf[2*jp  ][1] = r[1];
                bf[2*jp+1][0] = r[2]; bf[2*jp+1][1] = r[3];
            }
            #pragma unroll
            for (int i = 0; i < 4; i++){
                uint32_t af[4];
                ldsm_x4(af, Ab + a_lane +
                        (uint32_t)((wm + i * 16) * HLA + ks * 16) * 2);
                #pragma unroll
                for (int j = 0; j < 4; j++)
                    mma_f16(acc[i][j], af, bf[j]);
            }
        }
    };

    int nk = (K + BK - 1) / BK;
    #pragma unroll
    for (int s = 0; s < STAGES - 1; s++){
        if (s < nk){ loadA(s, s * BK); loadB(s, s * BK); }
        cp_commit();
    }
    for (int t = 0; t < nk; t++){
        cp_wait<STAGES - 2>();
        __syncthreads();
        int tn = t + STAGES - 1;
        if (tn < nk){ loadA(tn % STAGES, tn * BK); loadB(tn % STAGES, tn * BK); }
        cp_commit();
        compute(t % STAGES);
    }

    if (OUT == 3){
        #pragma unroll
        for (int i = 0; i < 4; i++){
            int m0i = row0 + wm + i * 16 + g;
            int m1i = m0i + 8;
            long pb0 = ((long)(m0i >> 10) * CC) * SS + (m0i & 1023);
            long pb1 = ((long)(m1i >> 10) * CC) * SS + (m1i & 1023);
            #pragma unroll
            for (int j = 0; j < 4; j++){
                int c0 = col0 + wn + j * 8 + 2 * tg;
                float* a4 = acc[i][j];
                float b0 = bias[c0], b1v = bias[c0 + 1];
                long o00 = pb0 + (long)c0 * SS, o01 = o00 + SS;
                long o10 = pb1 + (long)c0 * SS, o11 = o10 + SS;
                C[o00] = a4[0] + b0  + res[o00];
                C[o01] = a4[1] + b1v + res[o01];
                C[o10] = a4[2] + b0  + res[o10];
                C[o11] = a4[3] + b1v + res[o11];
            }
        }
    } else if (!GEGLU){
        #pragma unroll
        for (int i = 0; i < 4; i++){
            int r0 = row0 + wm + i * 16 + g;
            int r1 = r0 + 8;
            #pragma unroll
            for (int j = 0; j < 4; j++){
                int c0 = col0 + wn + j * 8 + 2 * tg;
                float* a4 = acc[i][j];
                float b0 = 0.f, b1v = 0.f;
                if (bias){ b0 = bias[c0]; b1v = bias[c0 + 1]; }
                if (r0 < M){
                    float2 v = {a4[0] + b0, a4[1] + b1v};
                    if (res){
                        float2 rr = *(const float2*)&res[(long)r0 * ldc + c0];
                        v.x += rr.x; v.y += rr.y;
                    }
                    if (OUT != 1) *(float2*)&C[(long)r0 * ldc + c0] = v;
                    if (OUT != 0) *(__half2*)&Gh[(long)r0 * ldc + c0] = __floats2half2_rn(v.x, v.y);
                }
                if (r1 < M){
                    float2 v = {a4[2] + b0, a4[3] + b1v};
                    if (res){
                        float2 rr = *(const float2*)&res[(long)r1 * ldc + c0];
                        v.x += rr.x; v.y += rr.y;
                    }
                    if (OUT != 1) *(float2*)&C[(long)r1 * ldc + c0] = v;
                    if (OUT != 0) *(__half2*)&Gh[(long)r1 * ldc + c0] = __floats2half2_rn(v.x, v.y);
                }
            }
        }
    } else {
        // GEGLU: u warps (wn<64, B cols 0..63) x gate warps (wn>=64 -> gate cols wn-64..wn-33)
        constexpr int LE = 68;
        float* ex = smf;
        __syncthreads();
        if (wn >= 64){
            int gbase = wn - 64;
            #pragma unroll
            for (int i = 0; i < 4; i++){
                int lr0 = wm + i * 16 + g, lr1 = lr0 + 8;
                #pragma unroll
                for (int j = 0; j < 4; j++){
                    int gc = gbase + j * 8 + 2 * tg;
                    float bg0 = bias[c0h + gc + 2048];
                    float bg1 = bias[c0h + gc + 1 + 2048];
                    ex[lr0 * LE + gc    ] = gelu_exact(acc[i][j][0] + bg0);
                    ex[lr0 * LE + gc + 1] = gelu_exact(acc[i][j][1] + bg1);
                    ex[lr1 * LE + gc    ] = gelu_exact(acc[i][j][2] + bg0);
                    ex[lr1 * LE + gc + 1] = gelu_exact(acc[i][j][3] + bg1);
                }
            }
        }
        __syncthreads();
        if (wn < 64){
            #pragma unroll
            for (int i = 0; i < 4; i++){
                int lr0 = wm + i * 16 + g, lr1 = lr0 + 8;
                long gr0 = row0 + lr0, gr1 = row0 + lr1;
                #pragma unroll
                for (int j = 0; j < 4; j++){
                    int lc = wn + j * 8 + 2 * tg;
                    float bu0 = bias[c0h + lc], bu1 = bias[c0h + lc + 1];
                    *(__half2*)&G0[gr0 * ldc + c0h + lc] = __floats2half2_rn(
                        (acc[i][j][0] + bu0) * ex[lr0 * LE + lc],
                        (acc[i][j][1] + bu1) * ex[lr0 * LE + lc + 1]);
                    *(__half2*)&G0[gr1 * ldc + c0h + lc] = __floats2half2_rn(
                        (acc[i][j][2] + bu0) * ex[lr1 * LE + lc],
                        (acc[i][j][3] + bu1) * ex[lr1 * LE + lc + 1]);
                }
            }
        }
    }
}

// ---------------- launch helpers ----------------
static void hgemm(const __half* A, const __half* W, const float* bias, const float* res,
                  float* C, int M, int N, int K, int lda, int ldb, int ldc){
    cudaFuncSetAttribute(hgemm_k<false,0>,
                         cudaFuncAttributeMaxDynamicSharedMemorySize, H_SMEM);
    dim3 g((N + 127) / 128, (M + 127) / 128, 1);
    hgemm_k<false,0><<<g, 256, H_SMEM>>>(A, W, W, W, W, bias, res, C,
                                         nullptr, nullptr, nullptr, nullptr,
                                         M, N, K, lda, ldb, ldc);
}
static void hgemm_h16z(const __half* A,
                       const __half* W0, const __half* W1, const __half* W2, const __half* W3,
                       __half* C0, __half* C1, __half* C2, __half* C3, int nz,
                       int M, int N, int K, int lda, int ldb, int ldc){
    cudaFuncSetAttribute(hgemm_k<false,1>,
                         cudaFuncAttributeMaxDynamicSharedMemorySize, H_SMEM);
    dim3 g((N + 127) / 128, (M + 127) / 128, nz);
    hgemm_k<false,1><<<g, 256, H_SMEM>>>(A, W0, W1, W2, W3, nullptr, nullptr, nullptr,
                                         C0, C1, C2, C3, M, N, K, lda, ldb, ldc);
}
static void hgemm_wh(const __half* A, const __half* W, const float* bias, const float* res,
                     float* C, __half* Ch, int M, int N, int K, int lda, int ldb, int ldc){
    cudaFuncSetAttribute(hgemm_k<false,2>,
                         cudaFuncAttributeMaxDynamicSharedMemorySize, H_SMEM);
    dim3 g((N + 127) / 128, (M + 127) / 128, 1);
    hgemm_k<false,2><<<g, 256, H_SMEM>>>(A, W, W, W, W, bias, res, C,
                                         Ch, Ch, Ch, Ch, M, N, K, lda, ldb, ldc);
}
static void hgemm_final(const __half* A, const __half* W, const float* bias,
                        const float* x, float* out){
    cudaFuncSetAttribute(hgemm_k<false,3>,
                         cudaFuncAttributeMaxDynamicSharedMemorySize, H_SMEM);
    dim3 g(CC / 128, MM / 128, 1);
    hgemm_k<false,3><<<g, 256, H_SMEM>>>(A, W, W, W, W, bias, x, out,
                                         nullptr, nullptr, nullptr, nullptr,
                                         MM, CC, CC, CC, CC, CC);
}
static void hgemm_geglu(const __half* A, const __half* W1, const float* b1, __half* G){
    cudaFuncSetAttribute(hgemm_k<true,0>,
                         cudaFuncAttributeMaxDynamicSharedMemorySize, H_SMEM);
    dim3 g(2048 / 64, MM / 128, 1);
    hgemm_k<true,0><<<g, 256, H_SMEM>>>(A, W1, W1, W1, W1, b1, nullptr, nullptr,
                                        G, G, G, G, MM, 4096, CC, CC, 4096, 2048);
}

extern "C" void kernel_launch(void* const* d_in, const int* in_sizes, int n_in,
                              void* d_out, int out_size){
    (void)in_sizes; (void)n_in; (void)out_size;
    const float* x      = (const float*)d_in[0];
    const float* cond   = (const float*)d_in[1];
    const float* gn_s   = (const float*)d_in[2];
    const float* gn_b   = (const float*)d_in[3];
    const float* pin_w  = (const float*)d_in[4];
    const float* pin_b  = (const float*)d_in[5];
    const float* pout_w = (const float*)d_in[6];
    const float* pout_b = (const float*)d_in[7];
    const float* ln1_s  = (const float*)d_in[8];
    const float* ln1_b  = (const float*)d_in[9];
    const float* sa_wq  = (const float*)d_in[10];
    const float* sa_wk  = (const float*)d_in[11];
    const float* sa_wv  = (const float*)d_in[12];
    const float* sa_wo  = (const float*)d_in[13];
    const float* sa_bo  = (const float*)d_in[14];
    const float* ln2_s  = (const float*)d_in[15];
    const float* ln2_b  = (const float*)d_in[16];
    const float* ca_wq  = (const float*)d_in[17];
    const float* ca_wk  = (const float*)d_in[18];
    const float* ca_wv  = (const float*)d_in[19];
    const float* ca_wo  = (const float*)d_in[20];
    const float* ca_bo  = (const float*)d_in[21];
    const float* ln3_s  = (const float*)d_in[22];
    const float* ln3_b  = (const float*)d_in[23];
    const float* ff_w1  = (const float*)d_in[24];
    const float* ff_b1  = (const float*)d_in[25];
    const float* ff_w2  = (const float*)d_in[26];
    const float* ff_b2  = (const float*)d_in[27];
    float* out = (float*)d_out;

    float  *p_t, *p_qf, *p_kf, *p_vf;
    __half *p_tn, *p_ao, *p_gg, *p_w16;
    cudaGetSymbolAddress((void**)&p_t,    g_t);
    cudaGetSymbolAddress((void**)&p_qf,   g_q);
    cudaGetSymbolAddress((void**)&p_kf,   g_k);
    cudaGetSymbolAddress((void**)&p_vf,   g_v);
    cudaGetSymbolAddress((void**)&p_tn,   g_tn_h);
    cudaGetSymbolAddress((void**)&p_ao,   g_ao_h);
    cudaGetSymbolAddress((void**)&p_gg,   g_gg_h);
    cudaGetSymbolAddress((void**)&p_w16,  g_w16);
    __half* p_q16 = (__half*)p_qf;
    __half* p_k16 = (__half*)p_kf;
    __half* p_v16 = (__half*)p_vf;

    // ---- fp16 arena layout ----
    const size_t S512 = 512 * 512, S768 = 768 * 512;
    const size_t SW1 = 512 * 4096, SW2 = 2048 * 512;
    __half* pin16  = p_w16;
    __half* pout16 = pin16 + S512;
    const size_t LSZ = 6 * S512 + 2 * S768 + SW1 + SW2;
    __half* lbase0 = pout16 + S512;
    auto LW = [&](int l){ return lbase0 + (size_t)l * LSZ; };
    __half* cond16 = lbase0 + 2 * LSZ;
    __half* p_t16  = cond16 + (size_t)BB * NCC * DCC;
    const size_t SKV = (size_t)MKV * CC;
    __half* ckv_k0 = p_t16 + (size_t)MM * CC;
    __half* ckv_v0 = ckv_k0 + SKV;
    __half* ckv_k1 = ckv_v0 + SKV;
    __half* ckv_v1 = ckv_k1 + SKV;

    // ---- single batched fp32->fp16 conversion ----
    {
        CvtBatch cb{};
        int zi = 0;
        auto add = [&](const float* s, __half* d, size_t n){
            cb.s[zi] = s; cb.d[zi] = d; cb.n4[zi] = (int)(n / 4); zi++;
        };
        add(pin_w,  pin16,  S512);
        add(pout_w, pout16, S512);
        for (int l = 0; l < 2; l++){
            __half* b = LW(l);
            add(sa_wq + (long)l * S512, b,             S512);
            add(sa_wk + (long)l * S512, b + S512,      S512);
            add(sa_wv + (long)l * S512, b + 2 * S512,  S512);
            add(sa_wo + (long)l * S512, b + 3 * S512,  S512);
            add(ca_wq + (long)l * S512, b + 4 * S512,  S512);
            add(ca_wo + (long)l * S512, b + 5 * S512,  S512);
            add(ca_wk + (long)l * S768, b + 6 * S512,         S768);
            add(ca_wv + (long)l * S768, b + 6 * S512 + S768,  S768);
            add(ff_w1 + (long)l * SW1,  b + 6 * S512 + 2 * S768,       SW1);
            add(ff_w2 + (long)l * SW2,  b + 6 * S512 + 2 * S768 + SW1, SW2);
        }
        add(cond, cond16, (size_t)BB * NCC * DCC);
        int maxb = (int)((SW1 / 4 + 255) / 256);
        cvt_k<<<dim3(maxb, 1, zi), 256>>>(cb);
    }

    // ---- precompute ALL cross-attn K/V ----
    hgemm_h16z(cond16,
               LW(0) + 6 * S512, LW(0) + 6 * S512 + S768,
               LW(1) + 6 * S512, LW(1) + 6 * S512 + S768,
               ckv_k0, ckv_v0, ckv_k1, ckv_v1, 4,
               MKV, CC, DCC, DCC, CC, CC);

    // flash smem
    constexpr int SM_SELF16  = (128 * 72 + 2 * 64 * 72 + 2 * 64 * 72) * 2;
    constexpr int SM_CROSS16 = (128 * 72 + 80 * 72 + 80 * 72) * 2;
    cudaFuncSetAttribute(flash16_k<64, 1024, 16, 2>,
                         cudaFuncAttributeMaxDynamicSharedMemorySize, SM_SELF16);
    cudaFuncSetAttribute(flash16_k<80, 77, 1, 1>,
                         cudaFuncAttributeMaxDynamicSharedMemorySize, SM_CROSS16);

    gn_fused_k<<<BB * 32, 256>>>(x, gn_s, gn_b, p_tn);
    hgemm(p_tn, pin16, pin_b, nullptr, p_t, MM, CC, CC, CC, CC, CC);

    for (int l = 0; l < 2; l++){
        __half* b   = LW(l);
        __half* wq16  = b;
        __half* wk16  = b + S512;
        __half* wv16  = b + 2 * S512;
        __half* wo16  = b + 3 * S512;
        __half* cwq16 = b + 4 * S512;
        __half* cwo16 = b + 5 * S512;
        __half* w116  = b + 6 * S512 + 2 * S768;
        __half* w216  = w116 + SW1;
        const float* bo  = sa_bo + (long)l * CC;
        const float* cbo = ca_bo + (long)l * CC;
        const float* b1  = ff_b1 + (long)l * 4096;
        const float* b2  = ff_b2 + (long)l * CC;
        __half* ck = (l == 0) ? ckv_k0 : ckv_k1;
        __half* cv = (l == 0) ? ckv_v0 : ckv_v1;

        // ---- self-attention ----
        layernorm_k<<<MM / 8, 256>>>(p_t, ln1_s + l * CC, ln1_b + l * CC, p_tn);
        hgemm_h16z(p_tn, wq16, wk16, wv16, wq16,
                   p_q16, p_k16, p_v16, p_q16, 3,
                   MM, CC, CC, CC, CC, CC);
        flash16_k<64, 1024, 16, 2><<<dim3(SS / 128, BB * NHH), 256, SM_SELF16>>>(
            p_q16, p_k16, p_v16, p_ao, (long)SS * CC);
        hgemm(p_ao, wo16, bo, p_t, p_t, MM, CC, CC, CC, CC, CC);

        // ---- cross-attention ----
        layernorm_k<<<MM / 8, 256>>>(p_t, ln2_s + l * CC, ln2_b + l * CC, p_tn);
        hgemm_h16z(p_tn, cwq16, cwq16, cwq16, cwq16,
                   p_q16, p_q16, p_q16, p_q16, 1,
                   MM, CC, CC, CC, CC, CC);
        flash16_k<80, 77, 1, 1><<<dim3(SS / 128, BB * NHH), 256, SM_CROSS16>>>(
            p_q16, ck, cv, p_ao, (long)NCC * CC);
        hgemm(p_ao, cwo16, cbo, p_t, p_t, MM, CC, CC, CC, CC, CC);

        // ---- FFN (GEGLU fused) ----
        layernorm_k<<<MM / 8, 256>>>(p_t, ln3_s + l * CC, ln3_b + l * CC, p_tn);
        hgemm_geglu(p_tn, w116, b1, p_gg);
        if (l == 1)
            hgemm_wh(p_gg, w216, b2, p_t, p_t, p_t16, MM, CC, 2048, 2048, CC, CC);
        else
            hgemm(p_gg, w216, b2, p_t, p_t, MM, CC, 2048, 2048, CC, CC);
    }

    hgemm_final(p_t16, pout16, pout_b, x, out);
}